// round 1
// baseline (speedup 1.0000x reference)
#include <cuda_runtime.h>
#include <math.h>

#define BB 2
#define LL 2048
#define KK 32
#define HH 128
#define PP 8
#define MSG 456
#define LDT 33
#define NB (BB*LL)   /* 4096 nodes */

// -------- scratch (static device allocations are allowed) --------
__device__ float g_R [NB*9];
__device__ float g_t [NB*3];
__device__ float g_pl[NB*PP*3];
__device__ float g_pg[NB*PP*3];
__device__ float g_hV[NB*HH];

__device__ __forceinline__ float gelu_f(float x){
    return 0.5f*x*(1.0f+erff(x*0.70710678118654752440f));
}

// ============================================================
// Kernel 1: frames + p_local/p_global projection (1 warp / node)
// ============================================================
__global__ void k_prep(const float* __restrict__ hV_in,
                       const float* __restrict__ X,
                       const float* __restrict__ Wp,
                       const float* __restrict__ bp,
                       int use_updated)
{
    int bl = blockIdx.x;
    int lane = threadIdx.x;
    __shared__ float s_hv[HH];
    __shared__ float s_R[9], s_t[3], s_pl[24];
    const float* hv = use_updated ? g_hV : hV_in;
    #pragma unroll
    for (int i=0;i<4;i++) s_hv[lane+32*i] = hv[bl*HH + lane + 32*i];
    if (lane==0) {
        const float* Xp = X + bl*12;
        float Nx=Xp[0],Ny=Xp[1],Nz=Xp[2];
        float Ax=Xp[3],Ay=Xp[4],Az=Xp[5];
        float Cx=Xp[6],Cy=Xp[7],Cz=Xp[8];
        float e0x=Ax-Nx, e0y=Ay-Ny, e0z=Az-Nz;
        float inv = 1.0f/sqrtf(e0x*e0x+e0y*e0y+e0z*e0z + 1e-8f);
        e0x*=inv; e0y*=inv; e0z*=inv;
        float e1x=Cx-Ax, e1y=Cy-Ay, e1z=Cz-Az;
        float d = e0x*e1x+e0y*e1y+e0z*e1z;
        e1x-=e0x*d; e1y-=e0y*d; e1z-=e0z*d;
        inv = 1.0f/sqrtf(e1x*e1x+e1y*e1y+e1z*e1z + 1e-8f);
        e1x*=inv; e1y*=inv; e1z*=inv;
        float e2x=e0y*e1z-e0z*e1y;
        float e2y=e0z*e1x-e0x*e1z;
        float e2z=e0x*e1y-e0y*e1x;
        // R columns = (e0,e1,e2):  R[i*3+j] = e_j[i]
        s_R[0]=e0x; s_R[1]=e1x; s_R[2]=e2x;
        s_R[3]=e0y; s_R[4]=e1y; s_R[5]=e2y;
        s_R[6]=e0z; s_R[7]=e1z; s_R[8]=e2z;
        s_t[0]=Ax; s_t[1]=Ay; s_t[2]=Az;
        #pragma unroll
        for (int i=0;i<9;i++) g_R[bl*9+i]=s_R[i];
        g_t[bl*3+0]=Ax; g_t[bl*3+1]=Ay; g_t[bl*3+2]=Az;
    }
    __syncwarp();
    if (lane < 24) {
        float acc = bp[lane];
        #pragma unroll 4
        for (int f=0; f<HH; f++) acc += s_hv[f]*Wp[f*24+lane];
        s_pl[lane]=acc;
        g_pl[bl*24+lane]=acc;
    }
    __syncwarp();
    if (lane < 24) {
        int p = lane/3, i = lane%3;
        float v = s_t[i] + s_R[i*3+0]*s_pl[p*3+0]
                         + s_R[i*3+1]*s_pl[p*3+1]
                         + s_R[i*3+2]*s_pl[p*3+2];
        g_pg[bl*24+lane]=v;
    }
}

// ============================================================
// Shared-memory tile GEMM: out_T[c][r] = act( in_T[:,r] . W[:,c] + b[c] )
// 128 threads: thread -> 4 cols x 8 rows. in_T is [Kdim][LDT].
// ============================================================
__device__ __forceinline__ void gemm_tile(const float* __restrict__ W,
                                          const float* __restrict__ bias,
                                          const float* s_in, float* s_out,
                                          int Kdim, bool act, int t)
{
    int lane = t & 31, warp = t >> 5;
    int c0 = lane*4, r0 = warp*8;
    float acc[8][4];
    #pragma unroll
    for (int i=0;i<8;i++)
        #pragma unroll
        for(int j=0;j<4;j++) acc[i][j]=0.f;
    const float* Wc = W + c0;
    #pragma unroll 4
    for (int k=0;k<Kdim;k++) {
        float4 w = *reinterpret_cast<const float4*>(Wc + k*HH);
        float a[8];
        #pragma unroll
        for (int i=0;i<8;i++) a[i] = s_in[k*LDT + r0 + i];
        #pragma unroll
        for (int i=0;i<8;i++) {
            acc[i][0] += a[i]*w.x;
            acc[i][1] += a[i]*w.y;
            acc[i][2] += a[i]*w.z;
            acc[i][3] += a[i]*w.w;
        }
    }
    float b0=bias[c0], b1=bias[c0+1], b2=bias[c0+2], b3=bias[c0+3];
    #pragma unroll
    for (int i=0;i<8;i++) {
        float v0=acc[i][0]+b0, v1=acc[i][1]+b1, v2=acc[i][2]+b2, v3=acc[i][3]+b3;
        if (act) { v0=gelu_f(v0); v1=gelu_f(v1); v2=gelu_f(v2); v3=gelu_f(v3); }
        s_out[(c0+0)*LDT + r0 + i] = v0;
        s_out[(c0+1)*LDT + r0 + i] = v1;
        s_out[(c0+2)*LDT + r0 + i] = v2;
        s_out[(c0+3)*LDT + r0 + i] = v3;
    }
}

struct MsgSmem {
    float mi[MSG*LDT];
    float h1[HH*LDT];
    float h2[HH*LDT];
    float hv[HH];
    float x[HH];
    float ff[4*HH];
    float R[9]; float tv[3]; float pl[24]; float pg[24]; float mask[KK];
    int   nbidx[KK];
    float red[8];
    float mu[KK]; float rstd[KK];
};

__device__ __forceinline__ float2 block_stats128(float x, float* s_red, int t)
{
    int lane=t&31, warp=t>>5;
    float s=x, q=x*x;
    #pragma unroll
    for (int o=16;o>0;o>>=1){
        s+=__shfl_down_sync(0xffffffffu,s,o);
        q+=__shfl_down_sync(0xffffffffu,q,o);
    }
    if (lane==0){ s_red[warp]=s; s_red[4+warp]=q; }
    __syncthreads();
    float ts=s_red[0]+s_red[1]+s_red[2]+s_red[3];
    float tq=s_red[4]+s_red[5]+s_red[6]+s_red[7];
    __syncthreads();
    float mu = ts*(1.f/HH);
    float var = tq*(1.f/HH) - mu*mu;
    return make_float2(mu, rsqrtf(var+1e-5f));
}

// Build mi^T[456][32] in shared memory for node bl.
__device__ __forceinline__ void build_mi(MsgSmem& S, int bl, int b, int t,
                                         const float* __restrict__ hVsrc,
                                         const float* __restrict__ hE)
{
    float hvt = S.hv[t];
    #pragma unroll
    for (int r=0;r<KK;r++) S.mi[t*LDT + r] = hvt;
    for (int r=0;r<KK;r++) S.mi[(HH+t)*LDT + r]   = hE[(bl*KK+r)*HH + t];
    for (int r=0;r<KK;r++) S.mi[(2*HH+t)*LDT + r] = hVsrc[(b*LL + S.nbidx[r])*HH + t];

    if (t < KK) {
        int nb = S.nbidx[t];
        const float* npg = g_pg + (b*LL+nb)*24;
        #pragma unroll
        for (int p=0;p<PP;p++){
            float plx=S.pl[p*3], ply=S.pl[p*3+1], plz=S.pl[p*3+2];
            S.mi[(3*HH+p*3+0)*LDT+t]=plx;
            S.mi[(3*HH+p*3+1)*LDT+t]=ply;
            S.mi[(3*HH+p*3+2)*LDT+t]=plz;
            S.mi[(3*HH+24+p)*LDT+t]=sqrtf(plx*plx+ply*ply+plz*plz+1e-8f);
            float dx=npg[p*3+0]-S.tv[0], dy=npg[p*3+1]-S.tv[1], dz=npg[p*3+2]-S.tv[2];
            // nb_p_local = R^T d : nl[i] = sum_j R[j*3+i] * d[j]
            float nlx = S.R[0]*dx + S.R[3]*dy + S.R[6]*dz;
            float nly = S.R[1]*dx + S.R[4]*dy + S.R[7]*dz;
            float nlz = S.R[2]*dx + S.R[5]*dy + S.R[8]*dz;
            S.mi[(3*HH+32+p*3+0)*LDT+t]=nlx;
            S.mi[(3*HH+32+p*3+1)*LDT+t]=nly;
            S.mi[(3*HH+32+p*3+2)*LDT+t]=nlz;
            S.mi[(3*HH+56+p)*LDT+t]=sqrtf(nlx*nlx+nly*nly+nlz*nlz+1e-8f);
            float gx=S.pg[p*3+0]-npg[p*3+0];
            float gy=S.pg[p*3+1]-npg[p*3+1];
            float gz=S.pg[p*3+2]-npg[p*3+2];
            S.mi[(3*HH+64+p)*LDT+t]=sqrtf(gx*gx+gy*gy+gz*gz+1e-8f);
        }
    }
}

// ============================================================
// Kernel 2: node message + mean + LN1 + FFN + LN2 + mask
// ============================================================
__global__ void k_node(const float* __restrict__ hV,
                       const float* __restrict__ hE,
                       const int*   __restrict__ Eidx,
                       const float* __restrict__ maskV,
                       const float* __restrict__ maskA,
                       const float* __restrict__ W1, const float* __restrict__ b1,
                       const float* __restrict__ W2, const float* __restrict__ b2,
                       const float* __restrict__ W3, const float* __restrict__ b3,
                       const float* __restrict__ Wdin, const float* __restrict__ bdin,
                       const float* __restrict__ Wdout, const float* __restrict__ bdout,
                       const float* __restrict__ g1, const float* __restrict__ be1,
                       const float* __restrict__ g2, const float* __restrict__ be2,
                       float* __restrict__ out_hV)
{
    extern __shared__ char smem_raw[];
    MsgSmem& S = *reinterpret_cast<MsgSmem*>(smem_raw);
    int bl = blockIdx.x;
    int b  = bl / LL;
    int t  = threadIdx.x;

    S.hv[t] = hV[bl*HH + t];
    if (t < 9)  S.R[t]  = g_R[bl*9+t];
    if (t < 3)  S.tv[t] = g_t[bl*3+t];
    if (t < 24) { S.pl[t] = g_pl[bl*24+t]; S.pg[t] = g_pg[bl*24+t]; }
    if (t < KK) { S.nbidx[t] = Eidx[bl*KK+t]; S.mask[t] = maskA[bl*KK+t]; }
    __syncthreads();

    build_mi(S, bl, b, t, hV, hE);
    __syncthreads();

    gemm_tile(W1,b1,S.mi,S.h1,MSG,true,t);
    __syncthreads();
    gemm_tile(W2,b2,S.h1,S.h2,HH,true,t);
    __syncthreads();
    gemm_tile(W3,b3,S.h2,S.mi,HH,false,t);   // reuse mi as out3^T
    __syncthreads();

    // masked mean over K
    float m=0.f;
    #pragma unroll
    for (int r=0;r<KK;r++) m += S.mask[r]*S.mi[t*LDT+r];
    m *= (1.0f/KK);

    float x = S.hv[t] + m;
    float2 st = block_stats128(x, S.red, t);
    float xn = (x - st.x)*st.y*g1[t] + be1[t];
    S.x[t] = xn;
    __syncthreads();

    // FFN: 128 -> 512 (gelu) -> 128
    float f0=bdin[t*4+0], f1=bdin[t*4+1], f2=bdin[t*4+2], f3=bdin[t*4+3];
    #pragma unroll 4
    for (int k=0;k<HH;k++){
        float v = S.x[k];
        float4 w = *reinterpret_cast<const float4*>(Wdin + k*4*HH + t*4);
        f0 += v*w.x; f1 += v*w.y; f2 += v*w.z; f3 += v*w.w;
    }
    S.ff[t*4+0]=gelu_f(f0); S.ff[t*4+1]=gelu_f(f1);
    S.ff[t*4+2]=gelu_f(f2); S.ff[t*4+3]=gelu_f(f3);
    __syncthreads();

    float o = bdout[t];
    #pragma unroll 4
    for (int k=0;k<4*HH;k++) o += S.ff[k]*Wdout[k*HH+t];

    float x2 = xn + o;
    float2 st2 = block_stats128(x2, S.red, t);
    float y = (x2 - st2.x)*st2.y*g2[t] + be2[t];
    y *= maskV[bl];
    g_hV[bl*HH+t]  = y;
    out_hV[bl*HH+t]= y;
}

// ============================================================
// Kernel 3: edge message + residual + per-edge LN
// ============================================================
__global__ void k_edge(const float* __restrict__ hE,
                       const int*   __restrict__ Eidx,
                       const float* __restrict__ W1, const float* __restrict__ b1,
                       const float* __restrict__ W2, const float* __restrict__ b2,
                       const float* __restrict__ W3, const float* __restrict__ b3,
                       const float* __restrict__ g3, const float* __restrict__ be3,
                       float* __restrict__ out_hE)
{
    extern __shared__ char smem_raw[];
    MsgSmem& S = *reinterpret_cast<MsgSmem*>(smem_raw);
    int bl = blockIdx.x;
    int b  = bl / LL;
    int t  = threadIdx.x;

    S.hv[t] = g_hV[bl*HH + t];
    if (t < 9)  S.R[t]  = g_R[bl*9+t];
    if (t < 3)  S.tv[t] = g_t[bl*3+t];
    if (t < 24) { S.pl[t] = g_pl[bl*24+t]; S.pg[t] = g_pg[bl*24+t]; }
    if (t < KK) S.nbidx[t] = Eidx[bl*KK+t];
    __syncthreads();

    build_mi(S, bl, b, t, g_hV, hE);
    __syncthreads();

    gemm_tile(W1,b1,S.mi,S.h1,MSG,true,t);
    __syncthreads();
    gemm_tile(W2,b2,S.h1,S.h2,HH,true,t);
    __syncthreads();
    gemm_tile(W3,b3,S.h2,S.mi,HH,false,t);
    __syncthreads();

    // residual add
    for (int r=0;r<KK;r++) S.mi[t*LDT+r] += hE[(bl*KK+r)*HH + t];
    __syncthreads();

    // per-edge LN stats
    if (t < KK){
        float s=0.f, q=0.f;
        #pragma unroll 4
        for (int c=0;c<HH;c++){ float v=S.mi[c*LDT+t]; s+=v; q+=v*v; }
        float mu = s*(1.f/HH);
        S.mu[t]   = mu;
        S.rstd[t] = rsqrtf(q*(1.f/HH)-mu*mu+1e-5f);
    }
    __syncthreads();

    float gt=g3[t], bt=be3[t];
    for (int r=0;r<KK;r++){
        float v=(S.mi[t*LDT+r]-S.mu[r])*S.rstd[r]*gt+bt;
        out_hE[(bl*KK+r)*HH+t]=v;
    }
}

// ============================================================
extern "C" void kernel_launch(void* const* d_in, const int* in_sizes, int n_in,
                              void* d_out, int out_size)
{
    const float* hV    =(const float*)d_in[0];
    const float* hE    =(const float*)d_in[1];
    const int*   Eidx  =(const int*)  d_in[2];
    const float* X     =(const float*)d_in[3];
    const float* maskV =(const float*)d_in[4];
    const float* maskA =(const float*)d_in[5];
    const float* Wp_node=(const float*)d_in[6];  const float* bp_node=(const float*)d_in[7];
    const float* Wp_edge=(const float*)d_in[8];  const float* bp_edge=(const float*)d_in[9];
    const float* W1 =(const float*)d_in[10]; const float* b1 =(const float*)d_in[11];
    const float* W2 =(const float*)d_in[12]; const float* b2 =(const float*)d_in[13];
    const float* W3 =(const float*)d_in[14]; const float* b3 =(const float*)d_in[15];
    const float* W11=(const float*)d_in[16]; const float* b11=(const float*)d_in[17];
    const float* W12=(const float*)d_in[18]; const float* b12=(const float*)d_in[19];
    const float* W13=(const float*)d_in[20]; const float* b13=(const float*)d_in[21];
    const float* Wdin =(const float*)d_in[22]; const float* bdin =(const float*)d_in[23];
    const float* Wdout=(const float*)d_in[24]; const float* bdout=(const float*)d_in[25];
    const float* g1=(const float*)d_in[26]; const float* be1=(const float*)d_in[27];
    const float* g2=(const float*)d_in[28]; const float* be2=(const float*)d_in[29];
    const float* g3=(const float*)d_in[30]; const float* be3=(const float*)d_in[31];

    float* out_hV = (float*)d_out;
    float* out_hE = out_hV + (size_t)NB*HH;

    int smem = (int)sizeof(MsgSmem);
    cudaFuncSetAttribute(k_node, cudaFuncAttributeMaxDynamicSharedMemorySize, smem);
    cudaFuncSetAttribute(k_edge, cudaFuncAttributeMaxDynamicSharedMemorySize, smem);

    k_prep<<<NB,32>>>(hV, X, Wp_node, bp_node, 0);
    k_node<<<NB,128,smem>>>(hV,hE,Eidx,maskV,maskA,
                            W1,b1,W2,b2,W3,b3,
                            Wdin,bdin,Wdout,bdout,
                            g1,be1,g2,be2,out_hV);
    k_prep<<<NB,32>>>(hV, X, Wp_edge, bp_edge, 1);
    k_edge<<<NB,128,smem>>>(hE,Eidx,W11,b11,W12,b12,W13,b13,g3,be3,out_hE);
}

// round 3
// speedup vs baseline: 2.7427x; 2.7427x over previous
#include <cuda_runtime.h>
#include <math.h>
#include <stdint.h>

#define BB 2
#define LL 2048
#define KK 32
#define HH 128
#define PP 8
#define MSG 456
#define LDT 40
#define NB (BB*LL)   /* 4096 nodes */

// -------- scratch (static device allocations) --------
__device__ float g_R [NB*9];
__device__ float g_t [NB*3];
__device__ float g_pl[NB*24];
__device__ float g_pg[NB*24];
__device__ float g_hV[NB*HH];
__device__ float g_xn[NB*HH];
__device__ float g_ff[(size_t)NB*4*HH];

// packed tf32 weights: [(kc*ntiles + j)*32 + lane]*2
__device__ float g_W1p [57*16*64];
__device__ float g_W2p [16*16*64];
__device__ float g_W3p [16*16*64];
__device__ float g_W11p[57*16*64];
__device__ float g_W12p[16*16*64];
__device__ float g_W13p[16*16*64];
__device__ float g_Wdinp [16*64*64];
__device__ float g_Wdoutp[64*16*64];

__device__ __forceinline__ float gelu_f(float x){
    return 0.5f*x*(1.0f+erff(x*0.70710678118654752440f));
}
__device__ __forceinline__ float tf32r(float x){
    uint32_t u; asm("cvt.rna.tf32.f32 %0, %1;" : "=r"(u) : "f"(x));
    return __uint_as_float(u);
}
__device__ __forceinline__ void mma8(float* c, const uint32_t* a, uint32_t b0, uint32_t b1){
    asm volatile("mma.sync.aligned.m16n8k8.row.col.f32.tf32.tf32.f32 "
        "{%0,%1,%2,%3},{%4,%5,%6,%7},{%8,%9},{%0,%1,%2,%3};"
        : "+f"(c[0]),"+f"(c[1]),"+f"(c[2]),"+f"(c[3])
        : "r"(a[0]),"r"(a[1]),"r"(a[2]),"r"(a[3]),"r"(b0),"r"(b1));
}

// ============================================================
// Weight pack: W[K][N] row-major -> fragment order, tf32-rounded
// block (32,16); grid (K/8, N/128)
// ============================================================
__global__ void k_pack(const float* __restrict__ W, float* __restrict__ out, int N)
{
    int ntiles = N >> 3;
    int kc   = blockIdx.x;
    int j    = blockIdx.y*16 + threadIdx.y;
    int lane = threadIdx.x;
    int row  = kc*8 + (lane&3);
    int col  = j*8 + (lane>>2);
    float b0 = W[row*N + col];
    float b1 = W[(row+4)*N + col];
    float* o = out + (((size_t)kc*ntiles + j)*32 + lane)*2;
    o[0] = tf32r(b0); o[1] = tf32r(b1);
}

// ============================================================
// Kernel: frames + p_local/p_global projection (1 warp / node)
// ============================================================
__global__ void k_prep(const float* __restrict__ hV_in,
                       const float* __restrict__ X,
                       const float* __restrict__ Wp,
                       const float* __restrict__ bp,
                       int use_updated)
{
    int bl = blockIdx.x;
    int lane = threadIdx.x;
    __shared__ float s_hv[HH];
    __shared__ float s_R[9], s_t[3], s_pl[24];
    const float* hv = use_updated ? g_hV : hV_in;
    #pragma unroll
    for (int i=0;i<4;i++) s_hv[lane+32*i] = hv[bl*HH + lane + 32*i];
    if (lane==0) {
        const float* Xp = X + bl*12;
        float Nx=Xp[0],Ny=Xp[1],Nz=Xp[2];
        float Ax=Xp[3],Ay=Xp[4],Az=Xp[5];
        float Cx=Xp[6],Cy=Xp[7],Cz=Xp[8];
        float e0x=Ax-Nx, e0y=Ay-Ny, e0z=Az-Nz;
        float inv = 1.0f/sqrtf(e0x*e0x+e0y*e0y+e0z*e0z + 1e-8f);
        e0x*=inv; e0y*=inv; e0z*=inv;
        float e1x=Cx-Ax, e1y=Cy-Ay, e1z=Cz-Az;
        float d = e0x*e1x+e0y*e1y+e0z*e1z;
        e1x-=e0x*d; e1y-=e0y*d; e1z-=e0z*d;
        inv = 1.0f/sqrtf(e1x*e1x+e1y*e1y+e1z*e1z + 1e-8f);
        e1x*=inv; e1y*=inv; e1z*=inv;
        float e2x=e0y*e1z-e0z*e1y;
        float e2y=e0z*e1x-e0x*e1z;
        float e2z=e0x*e1y-e0y*e1x;
        s_R[0]=e0x; s_R[1]=e1x; s_R[2]=e2x;
        s_R[3]=e0y; s_R[4]=e1y; s_R[5]=e2y;
        s_R[6]=e0z; s_R[7]=e1z; s_R[8]=e2z;
        s_t[0]=Ax; s_t[1]=Ay; s_t[2]=Az;
        #pragma unroll
        for (int i=0;i<9;i++) g_R[bl*9+i]=s_R[i];
        g_t[bl*3+0]=Ax; g_t[bl*3+1]=Ay; g_t[bl*3+2]=Az;
    }
    __syncwarp();
    if (lane < 24) {
        float acc = bp[lane];
        #pragma unroll 4
        for (int f=0; f<HH; f++) acc += s_hv[f]*Wp[f*24+lane];
        s_pl[lane]=acc;
        g_pl[bl*24+lane]=acc;
    }
    __syncwarp();
    if (lane < 24) {
        int p = lane/3, i = lane%3;
        float v = s_t[i] + s_R[i*3+0]*s_pl[p*3+0]
                         + s_R[i*3+1]*s_pl[p*3+1]
                         + s_R[i*3+2]*s_pl[p*3+2];
        g_pg[bl*24+lane]=v;
    }
}

// ============================================================
// tf32 MMA core: warp computes C[32 x 32-slice] for its jbase.
// A in smem k-major: sA[k*LDT + m] (tf32-rounded). B packed.
// ============================================================
template<int NKC>
__device__ __forceinline__ void mma_core(const float* __restrict__ Bpack, int ntiles, int jbase,
                                         const float* sA, float c[2][4][4], int lane)
{
    int qid = lane>>2, tig = lane&3;
    #pragma unroll
    for (int mt=0;mt<2;mt++)
        #pragma unroll
        for (int j=0;j<4;j++)
            #pragma unroll
            for (int i=0;i<4;i++) c[mt][j][i]=0.f;
    const float* bbase = Bpack + (size_t)jbase*64 + lane*2;
    #pragma unroll 4
    for (int kc=0; kc<NKC; kc++){
        const float* a0p = sA + (kc*8+tig)*LDT;
        const float* a1p = a0p + 4*LDT;
        uint32_t a[2][4];
        a[0][0]=__float_as_uint(a0p[qid]);
        a[0][1]=__float_as_uint(a0p[qid+8]);
        a[0][2]=__float_as_uint(a1p[qid]);
        a[0][3]=__float_as_uint(a1p[qid+8]);
        a[1][0]=__float_as_uint(a0p[qid+16]);
        a[1][1]=__float_as_uint(a0p[qid+24]);
        a[1][2]=__float_as_uint(a1p[qid+16]);
        a[1][3]=__float_as_uint(a1p[qid+24]);
        const float* bp = bbase + (size_t)kc*ntiles*64;
        #pragma unroll
        for (int j=0;j<4;j++){
            float2 bv = *reinterpret_cast<const float2*>(bp + (size_t)j*64);
            uint32_t b0=__float_as_uint(bv.x), b1=__float_as_uint(bv.y);
            mma8(c[0][j], a[0], b0, b1);
            mma8(c[1][j], a[1], b0, b1);
        }
    }
}

template<bool ACT, bool ROUND>
__device__ __forceinline__ void epi_smem(float c[2][4][4], const float* __restrict__ bias,
                                         float* sOut, int lane, int warp)
{
    int qid=lane>>2, tig=lane&3;
    #pragma unroll
    for (int j=0;j<4;j++){
        int n = (warp*4+j)*8 + tig*2;
        float b0=bias[n], b1=bias[n+1];
        #pragma unroll
        for (int mt=0;mt<2;mt++){
            int r = mt*16 + qid;
            float v0=c[mt][j][0]+b0, v1=c[mt][j][1]+b1;
            float v2=c[mt][j][2]+b0, v3=c[mt][j][3]+b1;
            if (ACT){ v0=gelu_f(v0); v1=gelu_f(v1); v2=gelu_f(v2); v3=gelu_f(v3); }
            if (ROUND){ v0=tf32r(v0); v1=tf32r(v1); v2=tf32r(v2); v3=tf32r(v3); }
            sOut[n*LDT + r]       = v0;
            sOut[(n+1)*LDT + r]   = v1;
            sOut[n*LDT + r+8]     = v2;
            sOut[(n+1)*LDT + r+8] = v3;
        }
    }
}

struct MsgSmem {
    float A0[MSG*LDT];   // mi^T, later gemm2 out
    float A1[HH*LDT];    // gemm1 out, later message^T
    float hv[HH];
    float R[9]; float tv[3]; float pl[24]; float pg[24]; float mask[KK];
    int   nbidx[KK];
    float red[8];
    float mu[KK]; float rstd[KK];
};

__device__ __forceinline__ float2 block_stats128(float x, float* s_red, int t)
{
    int lane=t&31, warp=t>>5;
    float s=x, q=x*x;
    #pragma unroll
    for (int o=16;o>0;o>>=1){
        s+=__shfl_down_sync(0xffffffffu,s,o);
        q+=__shfl_down_sync(0xffffffffu,q,o);
    }
    if (lane==0){ s_red[warp]=s; s_red[4+warp]=q; }
    __syncthreads();
    float ts=s_red[0]+s_red[1]+s_red[2]+s_red[3];
    float tq=s_red[4]+s_red[5]+s_red[6]+s_red[7];
    __syncthreads();
    float mu = ts*(1.f/HH);
    float var = tq*(1.f/HH) - mu*mu;
    return make_float2(mu, rsqrtf(var+1e-5f));
}

// Build mi^T[456][32] (tf32-rounded) in shared memory for node bl.
__device__ __forceinline__ void build_mi(MsgSmem& S, int bl, int b, int t,
                                         const float* __restrict__ hVsrc,
                                         const float* __restrict__ hE)
{
    float hvt = tf32r(S.hv[t]);
    #pragma unroll
    for (int r=0;r<KK;r++) S.A0[t*LDT + r] = hvt;
    for (int r=0;r<KK;r++) S.A0[(HH+t)*LDT + r]   = tf32r(hE[((size_t)bl*KK+r)*HH + t]);
    for (int r=0;r<KK;r++) S.A0[(2*HH+t)*LDT + r] = tf32r(hVsrc[((size_t)b*LL + S.nbidx[r])*HH + t]);

    if (t < KK) {
        int nb = S.nbidx[t];
        const float* npg = g_pg + ((size_t)b*LL+nb)*24;
        #pragma unroll
        for (int p=0;p<PP;p++){
            float plx=S.pl[p*3], ply=S.pl[p*3+1], plz=S.pl[p*3+2];
            S.A0[(3*HH+p*3+0)*LDT+t]=tf32r(plx);
            S.A0[(3*HH+p*3+1)*LDT+t]=tf32r(ply);
            S.A0[(3*HH+p*3+2)*LDT+t]=tf32r(plz);
            S.A0[(3*HH+24+p)*LDT+t]=tf32r(sqrtf(plx*plx+ply*ply+plz*plz+1e-8f));
            float dx=npg[p*3+0]-S.tv[0], dy=npg[p*3+1]-S.tv[1], dz=npg[p*3+2]-S.tv[2];
            float nlx = S.R[0]*dx + S.R[3]*dy + S.R[6]*dz;
            float nly = S.R[1]*dx + S.R[4]*dy + S.R[7]*dz;
            float nlz = S.R[2]*dx + S.R[5]*dy + S.R[8]*dz;
            S.A0[(3*HH+32+p*3+0)*LDT+t]=tf32r(nlx);
            S.A0[(3*HH+32+p*3+1)*LDT+t]=tf32r(nly);
            S.A0[(3*HH+32+p*3+2)*LDT+t]=tf32r(nlz);
            S.A0[(3*HH+56+p)*LDT+t]=tf32r(sqrtf(nlx*nlx+nly*nly+nlz*nlz+1e-8f));
            float gx=S.pg[p*3+0]-npg[p*3+0];
            float gy=S.pg[p*3+1]-npg[p*3+1];
            float gz=S.pg[p*3+2]-npg[p*3+2];
            S.A0[(3*HH+64+p)*LDT+t]=tf32r(sqrtf(gx*gx+gy*gy+gz*gz+1e-8f));
        }
    }
}

// ============================================================
// Node message: build mi -> 3 MMA GEMMs -> mean -> LN1 -> g_xn
// ============================================================
__global__ void k_node(const float* __restrict__ hV,
                       const float* __restrict__ hE,
                       const int*   __restrict__ Eidx,
                       const float* __restrict__ maskA,
                       const float* __restrict__ b1,
                       const float* __restrict__ b2,
                       const float* __restrict__ b3,
                       const float* __restrict__ g1, const float* __restrict__ be1)
{
    extern __shared__ char smem_raw[];
    MsgSmem& S = *reinterpret_cast<MsgSmem*>(smem_raw);
    int bl = blockIdx.x;
    int b  = bl / LL;
    int t  = threadIdx.x;
    int lane=t&31, warp=t>>5;

    S.hv[t] = hV[(size_t)bl*HH + t];
    if (t < 9)  S.R[t]  = g_R[bl*9+t];
    if (t < 3)  S.tv[t] = g_t[bl*3+t];
    if (t < 24) { S.pl[t] = g_pl[bl*24+t]; S.pg[t] = g_pg[bl*24+t]; }
    if (t < KK) { S.nbidx[t] = Eidx[bl*KK+t]; S.mask[t] = maskA[bl*KK+t]; }
    __syncthreads();

    build_mi(S, bl, b, t, hV, hE);
    __syncthreads();

    float c[2][4][4];
    mma_core<57>(g_W1p, 16, warp*4, S.A0, c, lane);
    epi_smem<true,true>(c, b1, S.A1, lane, warp);
    __syncthreads();
    mma_core<16>(g_W2p, 16, warp*4, S.A1, c, lane);
    epi_smem<true,true>(c, b2, S.A0, lane, warp);
    __syncthreads();
    mma_core<16>(g_W3p, 16, warp*4, S.A0, c, lane);
    epi_smem<false,false>(c, b3, S.A1, lane, warp);
    __syncthreads();

    float m=0.f;
    #pragma unroll
    for (int r=0;r<KK;r++) m += S.mask[r]*S.A1[t*LDT+r];
    m *= (1.0f/KK);

    float x = S.hv[t] + m;
    float2 st = block_stats128(x, S.red, t);
    float xn = (x - st.x)*st.y*g1[t] + be1[t];
    g_xn[(size_t)bl*HH+t] = xn;
}

// ============================================================
// FFN part 1: g_ff = gelu(xn @ Wdin + bdin)   grid (128, 4)
// ============================================================
__global__ void k_ffn1(const float* __restrict__ bdin)
{
    __shared__ float sA[HH*LDT];
    int rb = blockIdx.x, cb = blockIdx.y;
    int t = threadIdx.x;
    int lane=t&31, warp=t>>5;

    int m = t>>2; int k0 = (t&3)*32;
    const float* src = g_xn + ((size_t)(rb*32+m))*HH + k0;
    #pragma unroll
    for (int i=0;i<8;i++){
        float4 v = *reinterpret_cast<const float4*>(src + i*4);
        sA[(k0+i*4+0)*LDT+m]=tf32r(v.x);
        sA[(k0+i*4+1)*LDT+m]=tf32r(v.y);
        sA[(k0+i*4+2)*LDT+m]=tf32r(v.z);
        sA[(k0+i*4+3)*LDT+m]=tf32r(v.w);
    }
    __syncthreads();

    float c[2][4][4];
    mma_core<16>(g_Wdinp, 64, cb*16 + warp*4, sA, c, lane);

    int qid=lane>>2, tig=lane&3;
    #pragma unroll
    for (int j=0;j<4;j++){
        int n = (cb*16+warp*4+j)*8 + tig*2;
        float b0=bdin[n], b1=bdin[n+1];
        #pragma unroll
        for (int mt=0;mt<2;mt++){
            int r = rb*32 + mt*16 + qid;
            g_ff[(size_t)r*512 + n]       = gelu_f(c[mt][j][0]+b0);
            g_ff[(size_t)r*512 + n+1]     = gelu_f(c[mt][j][1]+b1);
            g_ff[(size_t)(r+8)*512 + n]   = gelu_f(c[mt][j][2]+b0);
            g_ff[(size_t)(r+8)*512 + n+1] = gelu_f(c[mt][j][3]+b1);
        }
    }
}

// ============================================================
// FFN part 2: x2 = xn + ff @ Wdout + bdout; LN2; mask -> h_V
// ============================================================
struct FfnSmem {
    float sA[4*HH*LDT];
    float mu[32], rstd[32];
};

__global__ void k_ffn2(const float* __restrict__ bdout,
                       const float* __restrict__ g2, const float* __restrict__ be2,
                       const float* __restrict__ maskV,
                       float* __restrict__ out_hV)
{
    extern __shared__ char smem_raw[];
    FfnSmem& S = *reinterpret_cast<FfnSmem*>(smem_raw);
    int rb = blockIdx.x;
    int t = threadIdx.x;
    int lane=t&31, warp=t>>5;

    int m = t>>2; int k0 = (t&3)*128;
    const float* src = g_ff + ((size_t)(rb*32+m))*512 + k0;
    #pragma unroll
    for (int i=0;i<32;i++){
        float4 v = *reinterpret_cast<const float4*>(src + i*4);
        S.sA[(k0+i*4+0)*LDT+m]=tf32r(v.x);
        S.sA[(k0+i*4+1)*LDT+m]=tf32r(v.y);
        S.sA[(k0+i*4+2)*LDT+m]=tf32r(v.z);
        S.sA[(k0+i*4+3)*LDT+m]=tf32r(v.w);
    }
    __syncthreads();

    float c[2][4][4];
    mma_core<64>(g_Wdoutp, 16, warp*4, S.sA, c, lane);
    __syncthreads();   // all warps done reading sA; reuse as sOut

    int qid=lane>>2, tig=lane&3;
    #pragma unroll
    for (int j=0;j<4;j++){
        int n = (warp*4+j)*8 + tig*2;
        float b0=bdout[n], b1=bdout[n+1];
        #pragma unroll
        for (int mt=0;mt<2;mt++){
            int r = mt*16 + qid;
            size_t node0 = (size_t)(rb*32 + r);
            size_t node1 = node0 + 8;
            S.sA[n*LDT + r]       = c[mt][j][0]+b0 + g_xn[node0*HH + n];
            S.sA[(n+1)*LDT + r]   = c[mt][j][1]+b1 + g_xn[node0*HH + n+1];
            S.sA[n*LDT + r+8]     = c[mt][j][2]+b0 + g_xn[node1*HH + n];
            S.sA[(n+1)*LDT + r+8] = c[mt][j][3]+b1 + g_xn[node1*HH + n+1];
        }
    }
    __syncthreads();

    if (t < 32){
        float s=0.f, q=0.f;
        #pragma unroll 4
        for (int cf=0;cf<HH;cf++){ float v=S.sA[cf*LDT+t]; s+=v; q+=v*v; }
        float mu = s*(1.f/HH);
        S.mu[t]=mu;
        S.rstd[t]=rsqrtf(q*(1.f/HH)-mu*mu+1e-5f);
    }
    __syncthreads();

    float gg=g2[t], bb=be2[t];
    for (int r=0;r<32;r++){
        size_t node = (size_t)(rb*32+r);
        float y = (S.sA[t*LDT+r]-S.mu[r])*S.rstd[r]*gg+bb;
        y *= maskV[node];
        g_hV[node*HH+t]=y;
        out_hV[node*HH+t]=y;
    }
}

// ============================================================
// Edge message: 3 MMA GEMMs -> residual -> per-edge LN -> h_E
// ============================================================
__global__ void k_edge(const float* __restrict__ hE,
                       const int*   __restrict__ Eidx,
                       const float* __restrict__ b1,
                       const float* __restrict__ b2,
                       const float* __restrict__ b3,
                       const float* __restrict__ g3, const float* __restrict__ be3,
                       float* __restrict__ out_hE)
{
    extern __shared__ char smem_raw[];
    MsgSmem& S = *reinterpret_cast<MsgSmem*>(smem_raw);
    int bl = blockIdx.x;
    int b  = bl / LL;
    int t  = threadIdx.x;
    int lane=t&31, warp=t>>5;

    S.hv[t] = g_hV[(size_t)bl*HH + t];
    if (t < 9)  S.R[t]  = g_R[bl*9+t];
    if (t < 3)  S.tv[t] = g_t[bl*3+t];
    if (t < 24) { S.pl[t] = g_pl[bl*24+t]; S.pg[t] = g_pg[bl*24+t]; }
    if (t < KK) S.nbidx[t] = Eidx[bl*KK+t];
    __syncthreads();

    build_mi(S, bl, b, t, g_hV, hE);
    __syncthreads();

    float c[2][4][4];
    mma_core<57>(g_W11p, 16, warp*4, S.A0, c, lane);
    epi_smem<true,true>(c, b1, S.A1, lane, warp);
    __syncthreads();
    mma_core<16>(g_W12p, 16, warp*4, S.A1, c, lane);
    epi_smem<true,true>(c, b2, S.A0, lane, warp);
    __syncthreads();
    mma_core<16>(g_W13p, 16, warp*4, S.A0, c, lane);
    epi_smem<false,false>(c, b3, S.A1, lane, warp);
    __syncthreads();

    for (int r=0;r<KK;r++) S.A1[t*LDT+r] += hE[((size_t)bl*KK+r)*HH + t];
    __syncthreads();

    if (t < KK){
        float s=0.f, q=0.f;
        #pragma unroll 4
        for (int cf=0;cf<HH;cf++){ float v=S.A1[cf*LDT+t]; s+=v; q+=v*v; }
        float mu = s*(1.f/HH);
        S.mu[t]   = mu;
        S.rstd[t] = rsqrtf(q*(1.f/HH)-mu*mu+1e-5f);
    }
    __syncthreads();

    float gt=g3[t], bt=be3[t];
    for (int r=0;r<KK;r++){
        float v=(S.A1[t*LDT+r]-S.mu[r])*S.rstd[r]*gt+bt;
        out_hE[((size_t)bl*KK+r)*HH+t]=v;
    }
}

// ============================================================
extern "C" void kernel_launch(void* const* d_in, const int* in_sizes, int n_in,
                              void* d_out, int out_size)
{
    const float* hV    =(const float*)d_in[0];
    const float* hE    =(const float*)d_in[1];
    const int*   Eidx  =(const int*)  d_in[2];
    const float* X     =(const float*)d_in[3];
    const float* maskV =(const float*)d_in[4];
    const float* maskA =(const float*)d_in[5];
    const float* Wp_node=(const float*)d_in[6];  const float* bp_node=(const float*)d_in[7];
    const float* Wp_edge=(const float*)d_in[8];  const float* bp_edge=(const float*)d_in[9];
    const float* W1 =(const float*)d_in[10]; const float* b1 =(const float*)d_in[11];
    const float* W2 =(const float*)d_in[12]; const float* b2 =(const float*)d_in[13];
    const float* W3 =(const float*)d_in[14]; const float* b3 =(const float*)d_in[15];
    const float* W11=(const float*)d_in[16]; const float* b11=(const float*)d_in[17];
    const float* W12=(const float*)d_in[18]; const float* b12=(const float*)d_in[19];
    const float* W13=(const float*)d_in[20]; const float* b13=(const float*)d_in[21];
    const float* Wdin =(const float*)d_in[22]; const float* bdin =(const float*)d_in[23];
    const float* Wdout=(const float*)d_in[24]; const float* bdout=(const float*)d_in[25];
    const float* g1=(const float*)d_in[26]; const float* be1=(const float*)d_in[27];
    const float* g2=(const float*)d_in[28]; const float* be2=(const float*)d_in[29];
    const float* g3=(const float*)d_in[30]; const float* be3=(const float*)d_in[31];

    float* out_hV = (float*)d_out;
    float* out_hE = out_hV + (size_t)NB*HH;

    int smem_msg = (int)sizeof(MsgSmem);
    int smem_ffn = (int)sizeof(FfnSmem);
    cudaFuncSetAttribute(k_node, cudaFuncAttributeMaxDynamicSharedMemorySize, smem_msg);
    cudaFuncSetAttribute(k_edge, cudaFuncAttributeMaxDynamicSharedMemorySize, smem_msg);
    cudaFuncSetAttribute(k_ffn2, cudaFuncAttributeMaxDynamicSharedMemorySize, smem_ffn);

    float *p1,*p2,*p3,*p11,*p12,*p13,*pdin,*pdout;
    cudaGetSymbolAddress((void**)&p1,   g_W1p);
    cudaGetSymbolAddress((void**)&p2,   g_W2p);
    cudaGetSymbolAddress((void**)&p3,   g_W3p);
    cudaGetSymbolAddress((void**)&p11,  g_W11p);
    cudaGetSymbolAddress((void**)&p12,  g_W12p);
    cudaGetSymbolAddress((void**)&p13,  g_W13p);
    cudaGetSymbolAddress((void**)&pdin, g_Wdinp);
    cudaGetSymbolAddress((void**)&pdout,g_Wdoutp);

    dim3 pb(32,16);
    k_pack<<<dim3(57,1),pb>>>(W1,  p1, 128);
    k_pack<<<dim3(16,1),pb>>>(W2,  p2, 128);
    k_pack<<<dim3(16,1),pb>>>(W3,  p3, 128);
    k_pack<<<dim3(57,1),pb>>>(W11, p11,128);
    k_pack<<<dim3(16,1),pb>>>(W12, p12,128);
    k_pack<<<dim3(16,1),pb>>>(W13, p13,128);
    k_pack<<<dim3(16,4),pb>>>(Wdin, pdin, 512);
    k_pack<<<dim3(64,1),pb>>>(Wdout,pdout,128);

    k_prep<<<NB,32>>>(hV, X, Wp_node, bp_node, 0);
    k_node<<<NB,128,smem_msg>>>(hV,hE,Eidx,maskA,b1,b2,b3,g1,be1);
    k_ffn1<<<dim3(128,4),128>>>(bdin);
    k_ffn2<<<128,128,smem_ffn>>>(bdout,g2,be2,maskV,out_hV);
    k_prep<<<NB,32>>>(hV, X, Wp_edge, bp_edge, 1);
    k_edge<<<NB,128,smem_msg>>>(hE,Eidx,b11,b12,b13,g3,be3,out_hE);
}

// round 4
// speedup vs baseline: 5.8823x; 2.1448x over previous
#include <cuda_runtime.h>
#include <cuda_bf16.h>
#include <math.h>
#include <stdint.h>

#define BB 2
#define LL 2048
#define KK 32
#define HH 128
#define PP 8
#define MSG 456
#define LDT 40        /* tf32 FFN tiles */
#define NB (BB*LL)    /* 4096 nodes */

#define NODES 4       /* nodes per message CTA */
#define LDK 472       /* bf16 elems per mi row (456 used, pad->conflict-free, 944B stride) */
#define LDH 136       /* bf16 elems per h row (272B stride) */
#define LDF 132       /* fp32 msg row */

// -------- scratch --------
__device__ float g_R [NB*9];
__device__ float g_t [NB*3];
__device__ float g_pl[NB*24];
__device__ float g_pg[NB*24];
__device__ float g_hV[NB*HH];
__device__ float g_xn[NB*HH];
__device__ float g_ff[(size_t)NB*4*HH];

// tf32 packed FFN weights
__device__ float g_Wdinp [16*64*64];
__device__ float g_Wdoutp[64*16*64];

// bf16 packed message weights: [((kc*16 + j)*32 + lane)*2 + reg] (uint32 = bf16x2)
__device__ uint32_t g_W1pb [29*16*64];
__device__ uint32_t g_W2pb [ 8*16*64];
__device__ uint32_t g_W3pb [ 8*16*64];
__device__ uint32_t g_W11pb[29*16*64];
__device__ uint32_t g_W12pb[ 8*16*64];
__device__ uint32_t g_W13pb[ 8*16*64];

__device__ __forceinline__ float gelu_f(float x){
    return 0.5f*x*(1.0f+erff(x*0.70710678118654752440f));
}
__device__ __forceinline__ float tf32r(float x){
    uint32_t u; asm("cvt.rna.tf32.f32 %0, %1;" : "=r"(u) : "f"(x));
    return __uint_as_float(u);
}
__device__ __forceinline__ uint32_t bf16x2(float lo, float hi){
    __nv_bfloat162 h = __floats2bfloat162_rn(lo, hi);
    return *reinterpret_cast<uint32_t*>(&h);
}
__device__ __forceinline__ void mma8(float* c, const uint32_t* a, uint32_t b0, uint32_t b1){
    asm volatile("mma.sync.aligned.m16n8k8.row.col.f32.tf32.tf32.f32 "
        "{%0,%1,%2,%3},{%4,%5,%6,%7},{%8,%9},{%0,%1,%2,%3};"
        : "+f"(c[0]),"+f"(c[1]),"+f"(c[2]),"+f"(c[3])
        : "r"(a[0]),"r"(a[1]),"r"(a[2]),"r"(a[3]),"r"(b0),"r"(b1));
}
__device__ __forceinline__ void mma16816(float* c, const uint32_t* a, const uint32_t* b){
    asm volatile("mma.sync.aligned.m16n8k16.row.col.f32.bf16.bf16.f32 "
        "{%0,%1,%2,%3},{%4,%5,%6,%7},{%8,%9},{%0,%1,%2,%3};"
        : "+f"(c[0]),"+f"(c[1]),"+f"(c[2]),"+f"(c[3])
        : "r"(a[0]),"r"(a[1]),"r"(a[2]),"r"(a[3]),"r"(b[0]),"r"(b[1]));
}
__device__ __forceinline__ void ldsm4(uint32_t* r, uint32_t addr){
    asm volatile("ldmatrix.sync.aligned.m8n8.x4.shared.b16 {%0,%1,%2,%3}, [%4];"
        : "=r"(r[0]),"=r"(r[1]),"=r"(r[2]),"=r"(r[3]) : "r"(addr));
}

// ============================================================
// tf32 weight pack for FFN (unchanged from R3)
// ============================================================
__global__ void k_pack(const float* __restrict__ W, float* __restrict__ out, int N)
{
    int ntiles = N >> 3;
    int kc   = blockIdx.x;
    int j    = blockIdx.y*16 + threadIdx.y;
    int lane = threadIdx.x;
    int row  = kc*8 + (lane&3);
    int col  = j*8 + (lane>>2);
    float b0 = W[row*N + col];
    float b1 = W[(row+4)*N + col];
    float* o = out + (((size_t)kc*ntiles + j)*32 + lane)*2;
    o[0] = tf32r(b0); o[1] = tf32r(b1);
}

// ============================================================
// bf16 weight pack for the 6 message weights. grid(29,16,6) block 32.
// ============================================================
__global__ void k_packb(const float* __restrict__ W1,const float* __restrict__ W2,
                        const float* __restrict__ W3,const float* __restrict__ W11,
                        const float* __restrict__ W12,const float* __restrict__ W13,
                        uint32_t* o1,uint32_t* o2,uint32_t* o3,
                        uint32_t* o11,uint32_t* o12,uint32_t* o13)
{
    int z = blockIdx.z;
    const float* src; uint32_t* dst; int Ktot;
    switch(z){
        case 0: src=W1;  dst=o1;  Ktot=MSG; break;
        case 1: src=W2;  dst=o2;  Ktot=HH;  break;
        case 2: src=W3;  dst=o3;  Ktot=HH;  break;
        case 3: src=W11; dst=o11; Ktot=MSG; break;
        case 4: src=W12; dst=o12; Ktot=HH;  break;
        default:src=W13; dst=o13; Ktot=HH;  break;
    }
    int kc = blockIdx.x;
    if (kc >= (Ktot+15)/16) return;
    int j = blockIdx.y, lane = threadIdx.x;
    int n = j*8 + (lane>>2);
    #pragma unroll
    for (int r=0;r<2;r++){
        int k = kc*16 + (lane&3)*2 + 8*r;
        float v0 = (k   < Ktot)? src[(size_t)k*HH + n]     : 0.f;
        float v1 = (k+1 < Ktot)? src[(size_t)(k+1)*HH + n] : 0.f;
        dst[(((size_t)kc*16 + j)*32 + lane)*2 + r] = bf16x2(v0, v1);
    }
}

// ============================================================
// Kernel: frames + p_local/p_global projection (1 warp / node)
// ============================================================
__global__ void k_prep(const float* __restrict__ hV_in,
                       const float* __restrict__ X,
                       const float* __restrict__ Wp,
                       const float* __restrict__ bp,
                       int use_updated)
{
    int bl = blockIdx.x;
    int lane = threadIdx.x;
    __shared__ float s_hv[HH];
    __shared__ float s_R[9], s_t[3], s_pl[24];
    const float* hv = use_updated ? g_hV : hV_in;
    #pragma unroll
    for (int i=0;i<4;i++) s_hv[lane+32*i] = hv[(size_t)bl*HH + lane + 32*i];
    if (lane==0) {
        const float* Xp = X + (size_t)bl*12;
        float Nx=Xp[0],Ny=Xp[1],Nz=Xp[2];
        float Ax=Xp[3],Ay=Xp[4],Az=Xp[5];
        float Cx=Xp[6],Cy=Xp[7],Cz=Xp[8];
        float e0x=Ax-Nx, e0y=Ay-Ny, e0z=Az-Nz;
        float inv = 1.0f/sqrtf(e0x*e0x+e0y*e0y+e0z*e0z + 1e-8f);
        e0x*=inv; e0y*=inv; e0z*=inv;
        float e1x=Cx-Ax, e1y=Cy-Ay, e1z=Cz-Az;
        float d = e0x*e1x+e0y*e1y+e0z*e1z;
        e1x-=e0x*d; e1y-=e0y*d; e1z-=e0z*d;
        inv = 1.0f/sqrtf(e1x*e1x+e1y*e1y+e1z*e1z + 1e-8f);
        e1x*=inv; e1y*=inv; e1z*=inv;
        float e2x=e0y*e1z-e0z*e1y;
        float e2y=e0z*e1x-e0x*e1z;
        float e2z=e0x*e1y-e0y*e1x;
        s_R[0]=e0x; s_R[1]=e1x; s_R[2]=e2x;
        s_R[3]=e0y; s_R[4]=e1y; s_R[5]=e2y;
        s_R[6]=e0z; s_R[7]=e1z; s_R[8]=e2z;
        s_t[0]=Ax; s_t[1]=Ay; s_t[2]=Az;
        #pragma unroll
        for (int i=0;i<9;i++) g_R[bl*9+i]=s_R[i];
        g_t[bl*3+0]=Ax; g_t[bl*3+1]=Ay; g_t[bl*3+2]=Az;
    }
    __syncwarp();
    if (lane < 24) {
        float acc = bp[lane];
        #pragma unroll 4
        for (int f=0; f<HH; f++) acc += s_hv[f]*Wp[f*24+lane];
        s_pl[lane]=acc;
        g_pl[bl*24+lane]=acc;
    }
    __syncwarp();
    if (lane < 24) {
        int p = lane/3, i = lane%3;
        float v = s_t[i] + s_R[i*3+0]*s_pl[p*3+0]
                         + s_R[i*3+1]*s_pl[p*3+1]
                         + s_R[i*3+2]*s_pl[p*3+2];
        g_pg[bl*24+lane]=v;
    }
}

// ============================================================
// Message-kernel shared memory (4 nodes, M=128)
// ============================================================
struct __align__(16) MsgSmem2 {
    __nv_bfloat16 A0[128*LDK];  // mi (bf16) -> h2 (bf16 LDH) -> msgF (fp32 LDF)
    __nv_bfloat16 A1[128*LDH];  // h1
    float hv[NODES*HH];
    float Rr[36], tvv[12], pll[96], pgg[96];
    float mask[128];
    int   nbidx[128];
    float red[32];
};

// ============================================================
// bf16 MMA core: warp (mq,nq) computes C[64 x 32] slice of [128x128].
// A row-major bf16 in smem, stride ldkB bytes. B fragment-packed in gmem.
// ============================================================
template<int NKC>
__device__ __forceinline__ void mma_bf16(const uint32_t* __restrict__ Bp, int nq,
                                         uint32_t aAddr, int ldkB, int mq, int lane,
                                         float c[4][4][4])
{
    #pragma unroll
    for (int mt=0;mt<4;mt++)
        #pragma unroll
        for (int j=0;j<4;j++)
            #pragma unroll
            for (int i=0;i<4;i++) c[mt][j][i]=0.f;

    uint32_t arow = aAddr + (uint32_t)((mq*64 + (lane&15))*ldkB) + ((lane>>4)&1)*16;
    for (int kc=0; kc<NKC; kc++){
        uint32_t a[4][4];
        #pragma unroll
        for (int mt=0;mt<4;mt++) ldsm4(a[mt], arow + mt*16*ldkB + kc*32);
        const uint32_t* bp = Bp + ((size_t)(kc*16 + nq*4)*32 + lane)*2;
        uint32_t b[4][2];
        #pragma unroll
        for (int j=0;j<4;j++){
            uint2 u = *reinterpret_cast<const uint2*>(bp + j*64);
            b[j][0]=u.x; b[j][1]=u.y;
        }
        #pragma unroll
        for (int mt=0;mt<4;mt++)
            #pragma unroll
            for (int j=0;j<4;j++) mma16816(c[mt][j], a[mt], b[j]);
    }
}

__device__ __forceinline__ void epi_gelu_bf16(float c[4][4][4], const float* __restrict__ bias,
                                              __nv_bfloat16* dst, int lane, int mq, int nq)
{
    int qid=lane>>2, tig=lane&3;
    #pragma unroll
    for (int mt=0;mt<4;mt++){
        int r0 = mq*64 + mt*16 + qid;
        #pragma unroll
        for (int j=0;j<4;j++){
            int n0 = nq*32 + j*8 + tig*2;
            float b0=bias[n0], b1=bias[n0+1];
            *reinterpret_cast<uint32_t*>(dst + (size_t)r0*LDH + n0) =
                bf16x2(gelu_f(c[mt][j][0]+b0), gelu_f(c[mt][j][1]+b1));
            *reinterpret_cast<uint32_t*>(dst + (size_t)(r0+8)*LDH + n0) =
                bf16x2(gelu_f(c[mt][j][2]+b0), gelu_f(c[mt][j][3]+b1));
        }
    }
}

__device__ __forceinline__ void epi_float(float c[4][4][4], const float* __restrict__ bias,
                                          float* msgF, int lane, int mq, int nq)
{
    int qid=lane>>2, tig=lane&3;
    #pragma unroll
    for (int mt=0;mt<4;mt++){
        int r0 = mq*64 + mt*16 + qid;
        #pragma unroll
        for (int j=0;j<4;j++){
            int n0 = nq*32 + j*8 + tig*2;
            float b0=bias[n0], b1=bias[n0+1];
            msgF[(size_t)r0*LDF + n0]     = c[mt][j][0]+b0;
            msgF[(size_t)r0*LDF + n0+1]   = c[mt][j][1]+b1;
            msgF[(size_t)(r0+8)*LDF + n0]   = c[mt][j][2]+b0;
            msgF[(size_t)(r0+8)*LDF + n0+1] = c[mt][j][3]+b1;
        }
    }
}

// Build mi (row-major bf16 [128][LDK]) for 4 nodes.
__device__ __forceinline__ void build_mi2(MsgSmem2& S, int bl0, int b, int t,
                                          const float* __restrict__ hVsrc,
                                          const float* __restrict__ hE)
{
    int w=t>>5, lane=t&31;
    // stage A: features 0..383 (node_e | h_E | nb_hV), coalesced float4 loads
    for (int i=0;i<16;i++){
        int gr = w*16+i; int v = gr>>5;
        size_t e = (size_t)bl0*KK + gr;
        int nb = S.nbidx[gr];
        const float4* hv4 = reinterpret_cast<const float4*>(&S.hv[v*HH]);
        const float4* he4 = reinterpret_cast<const float4*>(hE + e*HH);
        const float4* nb4 = reinterpret_cast<const float4*>(hVsrc + ((size_t)b*LL + nb)*HH);
        __nv_bfloat16* row = S.A0 + (size_t)gr*LDK;
        float4 x;
        x = hv4[lane];
        *reinterpret_cast<uint2*>(row + lane*4)        = make_uint2(bf16x2(x.x,x.y), bf16x2(x.z,x.w));
        x = he4[lane];
        *reinterpret_cast<uint2*>(row + HH + lane*4)   = make_uint2(bf16x2(x.x,x.y), bf16x2(x.z,x.w));
        x = nb4[lane];
        *reinterpret_cast<uint2*>(row + 2*HH + lane*4) = make_uint2(bf16x2(x.x,x.y), bf16x2(x.z,x.w));
        if (lane < 8) reinterpret_cast<uint32_t*>(row + MSG)[lane] = 0u;  // zero pad 456..471
    }
    // stage B: geometry features 384..455, one thread per edge-row
    if (t < 128){
        int gr=t, v=gr>>5;
        const float* R  = S.Rr  + v*9;
        const float* tv = S.tvv + v*3;
        const float* pl = S.pll + v*24;
        const float* pg = S.pgg + v*24;
        int nb = S.nbidx[gr];
        const float* npg = g_pg + ((size_t)b*LL + nb)*24;
        __nv_bfloat16* q = S.A0 + (size_t)gr*LDK + 3*HH;
        #pragma unroll
        for (int p=0;p<PP;p++){
            float plx=pl[p*3], ply=pl[p*3+1], plz=pl[p*3+2];
            q[p*3+0]=__float2bfloat16_rn(plx);
            q[p*3+1]=__float2bfloat16_rn(ply);
            q[p*3+2]=__float2bfloat16_rn(plz);
            q[24+p] =__float2bfloat16_rn(sqrtf(plx*plx+ply*ply+plz*plz+1e-8f));
            float dx=npg[p*3+0]-tv[0], dy=npg[p*3+1]-tv[1], dz=npg[p*3+2]-tv[2];
            float nlx = R[0]*dx + R[3]*dy + R[6]*dz;
            float nly = R[1]*dx + R[4]*dy + R[7]*dz;
            float nlz = R[2]*dx + R[5]*dy + R[8]*dz;
            q[32+p*3+0]=__float2bfloat16_rn(nlx);
            q[32+p*3+1]=__float2bfloat16_rn(nly);
            q[32+p*3+2]=__float2bfloat16_rn(nlz);
            q[56+p]=__float2bfloat16_rn(sqrtf(nlx*nlx+nly*nly+nlz*nlz+1e-8f));
            float gx=pg[p*3+0]-npg[p*3+0];
            float gy=pg[p*3+1]-npg[p*3+1];
            float gz=pg[p*3+2]-npg[p*3+2];
            q[64+p]=__float2bfloat16_rn(sqrtf(gx*gx+gy*gy+gz*gz+1e-8f));
        }
    }
}

// Three chained GEMMs. Leaves fp32 message in (float*)S.A0 [128][LDF].
__device__ __forceinline__ void run_msg_gemms(MsgSmem2& S,
    const uint32_t* __restrict__ B1, const float* __restrict__ b1,
    const uint32_t* __restrict__ B2, const float* __restrict__ b2,
    const uint32_t* __restrict__ B3, const float* __restrict__ b3, int t)
{
    int lane=t&31, w=t>>5, mq=w&1, nq=w>>1;
    uint32_t a0 = (uint32_t)__cvta_generic_to_shared(S.A0);
    uint32_t a1 = (uint32_t)__cvta_generic_to_shared(S.A1);
    float c[4][4][4];

    mma_bf16<29>(B1, nq, a0, LDK*2, mq, lane, c);
    epi_gelu_bf16(c, b1, S.A1, lane, mq, nq);
    __syncthreads();

    mma_bf16<8>(B2, nq, a1, LDH*2, mq, lane, c);
    epi_gelu_bf16(c, b2, S.A0, lane, mq, nq);     // h2 reuses A0 space (LDH layout)
    __syncthreads();

    mma_bf16<8>(B3, nq, a0, LDH*2, mq, lane, c);
    __syncthreads();                              // all h2 reads done before fp32 overwrite
    epi_float(c, b3, reinterpret_cast<float*>(S.A0), lane, mq, nq);
    __syncthreads();
}

__device__ __forceinline__ void load_node_params(MsgSmem2& S, int bl0, int t,
                                                 const float* __restrict__ hVsrc,
                                                 const int* __restrict__ Eidx,
                                                 const float* __restrict__ maskA)
{
    for (int i=t;i<NODES*HH;i+=256) S.hv[i] = hVsrc[(size_t)bl0*HH + i];
    if (t < 128){
        S.nbidx[t] = Eidx[(size_t)bl0*KK + t];
        S.mask[t]  = maskA ? maskA[(size_t)bl0*KK + t] : 1.0f;
    }
    if (t < 36) S.Rr[t]  = g_R[bl0*9 + t];
    if (t < 12) S.tvv[t] = g_t[bl0*3 + t];
    if (t < 96){ S.pll[t] = g_pl[bl0*24 + t]; S.pgg[t] = g_pg[bl0*24 + t]; }
}

// ============================================================
// Node message kernel: 4 nodes/CTA -> msg -> masked mean -> LN1 -> g_xn
// ============================================================
__global__ __launch_bounds__(256) void k_node(
    const float* __restrict__ hV, const float* __restrict__ hE,
    const int* __restrict__ Eidx, const float* __restrict__ maskA,
    const float* __restrict__ b1, const float* __restrict__ b2, const float* __restrict__ b3,
    const float* __restrict__ g1, const float* __restrict__ be1)
{
    extern __shared__ char smem_raw[];
    MsgSmem2& S = *reinterpret_cast<MsgSmem2*>(smem_raw);
    int bl0 = blockIdx.x * NODES;
    int b   = bl0 / LL;
    int t   = threadIdx.x;

    load_node_params(S, bl0, t, hV, Eidx, maskA);
    __syncthreads();
    build_mi2(S, bl0, b, t, hV, hE);
    __syncthreads();
    run_msg_gemms(S, g_W1pb, b1, g_W2pb, b2, g_W3pb, b3, t);

    const float* msgF = reinterpret_cast<const float*>(S.A0);
    int f = t&127, half = t>>7, w = t>>5, lane = t&31, widx = w&3;
    for (int vv=0; vv<2; vv++){
        int v = half*2 + vv;
        float acc = 0.f;
        #pragma unroll
        for (int r=0;r<32;r++) acc += S.mask[v*32+r] * msgF[(size_t)(v*32+r)*LDF + f];
        float x = S.hv[v*HH + f] + acc*(1.0f/KK);
        float s=x, q=x*x;
        #pragma unroll
        for (int o=16;o>0;o>>=1){
            s += __shfl_down_sync(0xffffffffu, s, o);
            q += __shfl_down_sync(0xffffffffu, q, o);
        }
        if (lane==0){ S.red[v*4+widx]=s; S.red[16+v*4+widx]=q; }
        __syncthreads();
        float ts = S.red[v*4]+S.red[v*4+1]+S.red[v*4+2]+S.red[v*4+3];
        float tq = S.red[16+v*4]+S.red[16+v*4+1]+S.red[16+v*4+2]+S.red[16+v*4+3];
        float mu = ts*(1.0f/HH);
        float rstd = rsqrtf(tq*(1.0f/HH)-mu*mu+1e-5f);
        g_xn[(size_t)(bl0+v)*HH + f] = (x-mu)*rstd*g1[f] + be1[f];
        __syncthreads();
    }
}

// ============================================================
// Edge message kernel: 4 nodes/CTA -> msg -> residual(fp32) -> per-edge LN -> h_E
// ============================================================
__global__ __launch_bounds__(256) void k_edge(
    const float* __restrict__ hE, const int* __restrict__ Eidx,
    const float* __restrict__ b1, const float* __restrict__ b2, const float* __restrict__ b3,
    const float* __restrict__ g3, const float* __restrict__ be3,
    float* __restrict__ out_hE)
{
    extern __shared__ char smem_raw[];
    MsgSmem2& S = *reinterpret_cast<MsgSmem2*>(smem_raw);
    int bl0 = blockIdx.x * NODES;
    int b   = bl0 / LL;
    int t   = threadIdx.x;

    load_node_params(S, bl0, t, g_hV, Eidx, (const float*)0);
    __syncthreads();
    build_mi2(S, bl0, b, t, g_hV, hE);
    __syncthreads();
    run_msg_gemms(S, g_W11pb, b1, g_W12pb, b2, g_W13pb, b3, t);

    const float* msgF = reinterpret_cast<const float*>(S.A0);
    int w = t>>5, lane = t&31;
    for (int i=0;i<16;i++){
        int gr = w*16+i;
        size_t e = (size_t)bl0*KK + gr;
        float4 hv_ = reinterpret_cast<const float4*>(hE + e*HH)[lane];
        float4 mv  = reinterpret_cast<const float4*>(msgF + (size_t)gr*LDF)[lane];
        float x0 = mv.x+hv_.x, x1 = mv.y+hv_.y, x2 = mv.z+hv_.z, x3 = mv.w+hv_.w;
        float s = x0+x1+x2+x3;
        float q = x0*x0+x1*x1+x2*x2+x3*x3;
        #pragma unroll
        for (int o=16;o>0;o>>=1){
            s += __shfl_xor_sync(0xffffffffu, s, o);
            q += __shfl_xor_sync(0xffffffffu, q, o);
        }
        float mu = s*(1.0f/HH);
        float rstd = rsqrtf(q*(1.0f/HH)-mu*mu+1e-5f);
        int f0 = lane*4;
        float4 gg = *reinterpret_cast<const float4*>(g3 + f0);
        float4 bb = *reinterpret_cast<const float4*>(be3 + f0);
        float4 o4;
        o4.x = (x0-mu)*rstd*gg.x + bb.x;
        o4.y = (x1-mu)*rstd*gg.y + bb.y;
        o4.z = (x2-mu)*rstd*gg.z + bb.z;
        o4.w = (x3-mu)*rstd*gg.w + bb.w;
        *reinterpret_cast<float4*>(out_hE + e*HH + f0) = o4;
    }
}

// ============================================================
// tf32 FFN (unchanged from R3)
// ============================================================
template<int NKC>
__device__ __forceinline__ void mma_core(const float* __restrict__ Bpack, int ntiles, int jbase,
                                         const float* sA, float c[2][4][4], int lane)
{
    int qid = lane>>2, tig = lane&3;
    #pragma unroll
    for (int mt=0;mt<2;mt++)
        #pragma unroll
        for (int j=0;j<4;j++)
            #pragma unroll
            for (int i=0;i<4;i++) c[mt][j][i]=0.f;
    const float* bbase = Bpack + (size_t)jbase*64 + lane*2;
    #pragma unroll 4
    for (int kc=0; kc<NKC; kc++){
        const float* a0p = sA + (kc*8+tig)*LDT;
        const float* a1p = a0p + 4*LDT;
        uint32_t a[2][4];
        a[0][0]=__float_as_uint(a0p[qid]);
        a[0][1]=__float_as_uint(a0p[qid+8]);
        a[0][2]=__float_as_uint(a1p[qid]);
        a[0][3]=__float_as_uint(a1p[qid+8]);
        a[1][0]=__float_as_uint(a0p[qid+16]);
        a[1][1]=__float_as_uint(a0p[qid+24]);
        a[1][2]=__float_as_uint(a1p[qid+16]);
        a[1][3]=__float_as_uint(a1p[qid+24]);
        const float* bp = bbase + (size_t)kc*ntiles*64;
        #pragma unroll
        for (int j=0;j<4;j++){
            float2 bv = *reinterpret_cast<const float2*>(bp + (size_t)j*64);
            uint32_t b0=__float_as_uint(bv.x), b1=__float_as_uint(bv.y);
            mma8(c[0][j], a[0], b0, b1);
            mma8(c[1][j], a[1], b0, b1);
        }
    }
}

__global__ void k_ffn1(const float* __restrict__ bdin)
{
    __shared__ float sA[HH*LDT];
    int rb = blockIdx.x, cb = blockIdx.y;
    int t = threadIdx.x;
    int lane=t&31, warp=t>>5;

    int m = t>>2; int k0 = (t&3)*32;
    const float* src = g_xn + ((size_t)(rb*32+m))*HH + k0;
    #pragma unroll
    for (int i=0;i<8;i++){
        float4 v = *reinterpret_cast<const float4*>(src + i*4);
        sA[(k0+i*4+0)*LDT+m]=tf32r(v.x);
        sA[(k0+i*4+1)*LDT+m]=tf32r(v.y);
        sA[(k0+i*4+2)*LDT+m]=tf32r(v.z);
        sA[(k0+i*4+3)*LDT+m]=tf32r(v.w);
    }
    __syncthreads();

    float c[2][4][4];
    mma_core<16>(g_Wdinp, 64, cb*16 + warp*4, sA, c, lane);

    int qid=lane>>2, tig=lane&3;
    #pragma unroll
    for (int j=0;j<4;j++){
        int n = (cb*16+warp*4+j)*8 + tig*2;
        float b0=bdin[n], b1=bdin[n+1];
        #pragma unroll
        for (int mt=0;mt<2;mt++){
            int r = rb*32 + mt*16 + qid;
            g_ff[(size_t)r*512 + n]       = gelu_f(c[mt][j][0]+b0);
            g_ff[(size_t)r*512 + n+1]     = gelu_f(c[mt][j][1]+b1);
            g_ff[(size_t)(r+8)*512 + n]   = gelu_f(c[mt][j][2]+b0);
            g_ff[(size_t)(r+8)*512 + n+1] = gelu_f(c[mt][j][3]+b1);
        }
    }
}

struct FfnSmem {
    float sA[4*HH*LDT];
    float mu[32], rstd[32];
};

__global__ void k_ffn2(const float* __restrict__ bdout,
                       const float* __restrict__ g2, const float* __restrict__ be2,
                       const float* __restrict__ maskV,
                       float* __restrict__ out_hV)
{
    extern __shared__ char smem_raw[];
    FfnSmem& S = *reinterpret_cast<FfnSmem*>(smem_raw);
    int rb = blockIdx.x;
    int t = threadIdx.x;
    int lane=t&31, warp=t>>5;

    int m = t>>2; int k0 = (t&3)*128;
    const float* src = g_ff + ((size_t)(rb*32+m))*512 + k0;
    #pragma unroll
    for (int i=0;i<32;i++){
        float4 v = *reinterpret_cast<const float4*>(src + i*4);
        S.sA[(k0+i*4+0)*LDT+m]=tf32r(v.x);
        S.sA[(k0+i*4+1)*LDT+m]=tf32r(v.y);
        S.sA[(k0+i*4+2)*LDT+m]=tf32r(v.z);
        S.sA[(k0+i*4+3)*LDT+m]=tf32r(v.w);
    }
    __syncthreads();

    float c[2][4][4];
    mma_core<64>(g_Wdoutp, 16, warp*4, S.sA, c, lane);
    __syncthreads();

    int qid=lane>>2, tig=lane&3;
    #pragma unroll
    for (int j=0;j<4;j++){
        int n = (warp*4+j)*8 + tig*2;
        float b0=bdout[n], b1=bdout[n+1];
        #pragma unroll
        for (int mt=0;mt<2;mt++){
            int r = mt*16 + qid;
            size_t node0 = (size_t)(rb*32 + r);
            size_t node1 = node0 + 8;
            S.sA[n*LDT + r]       = c[mt][j][0]+b0 + g_xn[node0*HH + n];
            S.sA[(n+1)*LDT + r]   = c[mt][j][1]+b1 + g_xn[node0*HH + n+1];
            S.sA[n*LDT + r+8]     = c[mt][j][2]+b0 + g_xn[node1*HH + n];
            S.sA[(n+1)*LDT + r+8] = c[mt][j][3]+b1 + g_xn[node1*HH + n+1];
        }
    }
    __syncthreads();

    if (t < 32){
        float s=0.f, q=0.f;
        #pragma unroll 4
        for (int cf=0;cf<HH;cf++){ float v=S.sA[cf*LDT+t]; s+=v; q+=v*v; }
        float mu = s*(1.f/HH);
        S.mu[t]=mu;
        S.rstd[t]=rsqrtf(q*(1.f/HH)-mu*mu+1e-5f);
    }
    __syncthreads();

    float gg=g2[t], bb=be2[t];
    for (int r=0;r<32;r++){
        size_t node = (size_t)(rb*32+r);
        float y = (S.sA[t*LDT+r]-S.mu[r])*S.rstd[r]*gg+bb;
        y *= maskV[node];
        g_hV[node*HH+t]=y;
        out_hV[node*HH+t]=y;
    }
}

// ============================================================
extern "C" void kernel_launch(void* const* d_in, const int* in_sizes, int n_in,
                              void* d_out, int out_size)
{
    const float* hV    =(const float*)d_in[0];
    const float* hE    =(const float*)d_in[1];
    const int*   Eidx  =(const int*)  d_in[2];
    const float* X     =(const float*)d_in[3];
    const float* maskV =(const float*)d_in[4];
    const float* maskA =(const float*)d_in[5];
    const float* Wp_node=(const float*)d_in[6];  const float* bp_node=(const float*)d_in[7];
    const float* Wp_edge=(const float*)d_in[8];  const float* bp_edge=(const float*)d_in[9];
    const float* W1 =(const float*)d_in[10]; const float* b1 =(const float*)d_in[11];
    const float* W2 =(const float*)d_in[12]; const float* b2 =(const float*)d_in[13];
    const float* W3 =(const float*)d_in[14]; const float* b3 =(const float*)d_in[15];
    const float* W11=(const float*)d_in[16]; const float* b11=(const float*)d_in[17];
    const float* W12=(const float*)d_in[18]; const float* b12=(const float*)d_in[19];
    const float* W13=(const float*)d_in[20]; const float* b13=(const float*)d_in[21];
    const float* Wdin =(const float*)d_in[22]; const float* bdin =(const float*)d_in[23];
    const float* Wdout=(const float*)d_in[24]; const float* bdout=(const float*)d_in[25];
    const float* g1=(const float*)d_in[26]; const float* be1=(const float*)d_in[27];
    const float* g2=(const float*)d_in[28]; const float* be2=(const float*)d_in[29];
    const float* g3=(const float*)d_in[30]; const float* be3=(const float*)d_in[31];

    float* out_hV = (float*)d_out;
    float* out_hE = out_hV + (size_t)NB*HH;

    int smem_msg = (int)sizeof(MsgSmem2);
    int smem_ffn = (int)sizeof(FfnSmem);
    cudaFuncSetAttribute(k_node, cudaFuncAttributeMaxDynamicSharedMemorySize, smem_msg);
    cudaFuncSetAttribute(k_edge, cudaFuncAttributeMaxDynamicSharedMemorySize, smem_msg);
    cudaFuncSetAttribute(k_ffn2, cudaFuncAttributeMaxDynamicSharedMemorySize, smem_ffn);

    uint32_t *p1,*p2,*p3,*p11,*p12,*p13;
    float *pdin,*pdout;
    cudaGetSymbolAddress((void**)&p1,   g_W1pb);
    cudaGetSymbolAddress((void**)&p2,   g_W2pb);
    cudaGetSymbolAddress((void**)&p3,   g_W3pb);
    cudaGetSymbolAddress((void**)&p11,  g_W11pb);
    cudaGetSymbolAddress((void**)&p12,  g_W12pb);
    cudaGetSymbolAddress((void**)&p13,  g_W13pb);
    cudaGetSymbolAddress((void**)&pdin, g_Wdinp);
    cudaGetSymbolAddress((void**)&pdout,g_Wdoutp);

    k_packb<<<dim3(29,16,6),32>>>(W1,W2,W3,W11,W12,W13,p1,p2,p3,p11,p12,p13);
    dim3 pb(32,16);
    k_pack<<<dim3(16,4),pb>>>(Wdin,  pdin, 512);
    k_pack<<<dim3(64,1),pb>>>(Wdout, pdout,128);

    k_prep<<<NB,32>>>(hV, X, Wp_node, bp_node, 0);
    k_node<<<NB/NODES,256,smem_msg>>>(hV,hE,Eidx,maskA,b1,b2,b3,g1,be1);
    k_ffn1<<<dim3(128,4),128>>>(bdin);
    k_ffn2<<<128,128,smem_ffn>>>(bdout,g2,be2,maskV,out_hV);
    k_prep<<<NB,32>>>(hV, X, Wp_edge, bp_edge, 1);
    k_edge<<<NB/NODES,256,smem_msg>>>(hE,Eidx,b11,b12,b13,g3,be3,out_hE);
}

// round 5
// speedup vs baseline: 7.1540x; 1.2162x over previous
#include <cuda_runtime.h>
#include <cuda_bf16.h>
#include <math.h>
#include <stdint.h>

#define BB 2
#define LL 2048
#define KK 32
#define HH 128
#define PP 8
#define MSG 456
#define LDT 40        /* tf32 FFN tiles */
#define NB (BB*LL)    /* 4096 nodes */

#define NODES 2       /* nodes per message CTA */
#define MROWS (NODES*KK)   /* 64 */
#define LDK 472       /* bf16 elems per mi row (944B stride, conflict-free) */
#define LDH 136       /* bf16 elems per h row (272B stride) */
#define LDF 132       /* fp32 msg row */

// -------- scratch --------
__device__ float g_R [NB*9];
__device__ float g_t [NB*3];
__device__ float g_pl[NB*24];
__device__ float g_pg[NB*24];
__device__ float g_hV[NB*HH];
__device__ float g_xn[NB*HH];
__device__ float g_ff[(size_t)NB*4*HH];

// tf32 packed FFN weights
__device__ float g_Wdinp [16*64*64];
__device__ float g_Wdoutp[64*16*64];

// bf16 packed message weights: [((kc*16 + j)*32 + lane)*2 + reg] (uint32 = bf16x2)
__device__ uint32_t g_W1pb [29*16*64];
__device__ uint32_t g_W2pb [ 8*16*64];
__device__ uint32_t g_W3pb [ 8*16*64];
__device__ uint32_t g_W11pb[29*16*64];
__device__ uint32_t g_W12pb[ 8*16*64];
__device__ uint32_t g_W13pb[ 8*16*64];

__device__ __forceinline__ float gelu_f(float x){
    return 0.5f*x*(1.0f+erff(x*0.70710678118654752440f));
}
__device__ __forceinline__ float tf32r(float x){
    uint32_t u; asm("cvt.rna.tf32.f32 %0, %1;" : "=r"(u) : "f"(x));
    return __uint_as_float(u);
}
__device__ __forceinline__ uint32_t bf16x2(float lo, float hi){
    __nv_bfloat162 h = __floats2bfloat162_rn(lo, hi);
    return *reinterpret_cast<uint32_t*>(&h);
}
__device__ __forceinline__ void mma8(float* c, const uint32_t* a, uint32_t b0, uint32_t b1){
    asm volatile("mma.sync.aligned.m16n8k8.row.col.f32.tf32.tf32.f32 "
        "{%0,%1,%2,%3},{%4,%5,%6,%7},{%8,%9},{%0,%1,%2,%3};"
        : "+f"(c[0]),"+f"(c[1]),"+f"(c[2]),"+f"(c[3])
        : "r"(a[0]),"r"(a[1]),"r"(a[2]),"r"(a[3]),"r"(b0),"r"(b1));
}
__device__ __forceinline__ void mma16816(float* c, const uint32_t* a, const uint32_t* b){
    asm volatile("mma.sync.aligned.m16n8k16.row.col.f32.bf16.bf16.f32 "
        "{%0,%1,%2,%3},{%4,%5,%6,%7},{%8,%9},{%0,%1,%2,%3};"
        : "+f"(c[0]),"+f"(c[1]),"+f"(c[2]),"+f"(c[3])
        : "r"(a[0]),"r"(a[1]),"r"(a[2]),"r"(a[3]),"r"(b[0]),"r"(b[1]));
}
__device__ __forceinline__ void ldsm4(uint32_t* r, uint32_t addr){
    asm volatile("ldmatrix.sync.aligned.m8n8.x4.shared.b16 {%0,%1,%2,%3}, [%4];"
        : "=r"(r[0]),"=r"(r[1]),"=r"(r[2]),"=r"(r[3]) : "r"(addr));
}

// ============================================================
// tf32 weight pack for FFN
// ============================================================
__global__ void k_pack(const float* __restrict__ W, float* __restrict__ out, int N)
{
    int ntiles = N >> 3;
    int kc   = blockIdx.x;
    int j    = blockIdx.y*16 + threadIdx.y;
    int lane = threadIdx.x;
    int row  = kc*8 + (lane&3);
    int col  = j*8 + (lane>>2);
    float b0 = W[row*N + col];
    float b1 = W[(row+4)*N + col];
    float* o = out + (((size_t)kc*ntiles + j)*32 + lane)*2;
    o[0] = tf32r(b0); o[1] = tf32r(b1);
}

// ============================================================
// bf16 weight pack for the 6 message weights. grid(29,16,6) block 32.
// ============================================================
__global__ void k_packb(const float* __restrict__ W1,const float* __restrict__ W2,
                        const float* __restrict__ W3,const float* __restrict__ W11,
                        const float* __restrict__ W12,const float* __restrict__ W13,
                        uint32_t* o1,uint32_t* o2,uint32_t* o3,
                        uint32_t* o11,uint32_t* o12,uint32_t* o13)
{
    int z = blockIdx.z;
    const float* src; uint32_t* dst; int Ktot;
    switch(z){
        case 0: src=W1;  dst=o1;  Ktot=MSG; break;
        case 1: src=W2;  dst=o2;  Ktot=HH;  break;
        case 2: src=W3;  dst=o3;  Ktot=HH;  break;
        case 3: src=W11; dst=o11; Ktot=MSG; break;
        case 4: src=W12; dst=o12; Ktot=HH;  break;
        default:src=W13; dst=o13; Ktot=HH;  break;
    }
    int kc = blockIdx.x;
    if (kc >= (Ktot+15)/16) return;
    int j = blockIdx.y, lane = threadIdx.x;
    int n = j*8 + (lane>>2);
    #pragma unroll
    for (int r=0;r<2;r++){
        int k = kc*16 + (lane&3)*2 + 8*r;
        float v0 = (k   < Ktot)? src[(size_t)k*HH + n]     : 0.f;
        float v1 = (k+1 < Ktot)? src[(size_t)(k+1)*HH + n] : 0.f;
        dst[(((size_t)kc*16 + j)*32 + lane)*2 + r] = bf16x2(v0, v1);
    }
}

// ============================================================
// Frames: 1 thread per node
// ============================================================
__global__ void k_frames(const float* __restrict__ X)
{
    int node = blockIdx.x*128 + threadIdx.x;
    if (node >= NB) return;
    const float* Xp = X + (size_t)node*12;
    float Nx=Xp[0],Ny=Xp[1],Nz=Xp[2];
    float Ax=Xp[3],Ay=Xp[4],Az=Xp[5];
    float Cx=Xp[6],Cy=Xp[7],Cz=Xp[8];
    float e0x=Ax-Nx, e0y=Ay-Ny, e0z=Az-Nz;
    float inv = 1.0f/sqrtf(e0x*e0x+e0y*e0y+e0z*e0z + 1e-8f);
    e0x*=inv; e0y*=inv; e0z*=inv;
    float e1x=Cx-Ax, e1y=Cy-Ay, e1z=Cz-Az;
    float d = e0x*e1x+e0y*e1y+e0z*e1z;
    e1x-=e0x*d; e1y-=e0y*d; e1z-=e0z*d;
    inv = 1.0f/sqrtf(e1x*e1x+e1y*e1y+e1z*e1z + 1e-8f);
    e1x*=inv; e1y*=inv; e1z*=inv;
    float e2x=e0y*e1z-e0z*e1y;
    float e2y=e0z*e1x-e0x*e1z;
    float e2z=e0x*e1y-e0y*e1x;
    float* R = g_R + node*9;
    R[0]=e0x; R[1]=e1x; R[2]=e2x;
    R[3]=e0y; R[4]=e1y; R[5]=e2y;
    R[6]=e0z; R[7]=e1z; R[8]=e2z;
    g_t[node*3+0]=Ax; g_t[node*3+1]=Ay; g_t[node*3+2]=Az;
}

// ============================================================
// p_local projection: 1 thread per (node, out24)
// ============================================================
__global__ void k_proj(const float* __restrict__ hv,
                       const float* __restrict__ Wp,
                       const float* __restrict__ bp)
{
    int idx = blockIdx.x*256 + threadIdx.x;   // < 4096*24
    int node = idx/24, j = idx%24;
    const float* h = hv + (size_t)node*HH;
    float acc = bp[j];
    #pragma unroll 8
    for (int f=0; f<HH; f++) acc += h[f]*Wp[f*24+j];
    g_pl[(size_t)node*24 + j] = acc;
}

// p_global: 1 thread per (node, 24)
__global__ void k_pg()
{
    int idx = blockIdx.x*256 + threadIdx.x;
    int node = idx/24, l = idx%24;
    int p = l/3, i = l%3;
    const float* R  = g_R + node*9;
    const float* pl = g_pl + (size_t)node*24 + p*3;
    g_pg[(size_t)node*24 + l] =
        g_t[node*3+i] + R[i*3+0]*pl[0] + R[i*3+1]*pl[1] + R[i*3+2]*pl[2];
}

// ============================================================
// Message-kernel shared memory (2 nodes, M=64)
// ============================================================
struct __align__(16) MsgSmem2 {
    __nv_bfloat16 A0[MROWS*LDK];  // mi (bf16) -> h2 (bf16 LDH) -> msgF (fp32 LDF)
    __nv_bfloat16 A1[MROWS*LDH];  // h1
    float hv[NODES*HH];
    float Rr[NODES*9], tvv[NODES*3], pll[NODES*24], pgg[NODES*24];
    float mask[MROWS];
    int   nbidx[MROWS];
    float red[16];
};

// ============================================================
// bf16 MMA core: warp nq computes C[64 x 16] slice of [64x128].
// ============================================================
template<int NKC>
__device__ __forceinline__ void mma_bf16(const uint32_t* __restrict__ Bp, int nq,
                                         uint32_t aAddr, int ldkB, int lane,
                                         float c[4][2][4])
{
    #pragma unroll
    for (int mt=0;mt<4;mt++)
        #pragma unroll
        for (int j=0;j<2;j++)
            #pragma unroll
            for (int i=0;i<4;i++) c[mt][j][i]=0.f;

    uint32_t arow = aAddr + (uint32_t)((lane&15)*ldkB) + ((lane>>4)&1)*16;
    for (int kc=0; kc<NKC; kc++){
        uint32_t a[4][4];
        #pragma unroll
        for (int mt=0;mt<4;mt++) ldsm4(a[mt], arow + mt*16*ldkB + kc*32);
        const uint32_t* bp = Bp + ((size_t)(kc*16 + nq*2)*32 + lane)*2;
        uint32_t b[2][2];
        #pragma unroll
        for (int j=0;j<2;j++){
            uint2 u = *reinterpret_cast<const uint2*>(bp + j*64);
            b[j][0]=u.x; b[j][1]=u.y;
        }
        #pragma unroll
        for (int mt=0;mt<4;mt++)
            #pragma unroll
            for (int j=0;j<2;j++) mma16816(c[mt][j], a[mt], b[j]);
    }
}

__device__ __forceinline__ void epi_gelu_bf16(float c[4][2][4], const float* __restrict__ bias,
                                              __nv_bfloat16* dst, int lane, int nq)
{
    int qid=lane>>2, tig=lane&3;
    #pragma unroll
    for (int mt=0;mt<4;mt++){
        int r0 = mt*16 + qid;
        #pragma unroll
        for (int j=0;j<2;j++){
            int n0 = nq*16 + j*8 + tig*2;
            float b0=bias[n0], b1=bias[n0+1];
            *reinterpret_cast<uint32_t*>(dst + (size_t)r0*LDH + n0) =
                bf16x2(gelu_f(c[mt][j][0]+b0), gelu_f(c[mt][j][1]+b1));
            *reinterpret_cast<uint32_t*>(dst + (size_t)(r0+8)*LDH + n0) =
                bf16x2(gelu_f(c[mt][j][2]+b0), gelu_f(c[mt][j][3]+b1));
        }
    }
}

__device__ __forceinline__ void epi_float(float c[4][2][4], const float* __restrict__ bias,
                                          float* msgF, int lane, int nq)
{
    int qid=lane>>2, tig=lane&3;
    #pragma unroll
    for (int mt=0;mt<4;mt++){
        int r0 = mt*16 + qid;
        #pragma unroll
        for (int j=0;j<2;j++){
            int n0 = nq*16 + j*8 + tig*2;
            float b0=bias[n0], b1=bias[n0+1];
            msgF[(size_t)r0*LDF + n0]       = c[mt][j][0]+b0;
            msgF[(size_t)r0*LDF + n0+1]     = c[mt][j][1]+b1;
            msgF[(size_t)(r0+8)*LDF + n0]   = c[mt][j][2]+b0;
            msgF[(size_t)(r0+8)*LDF + n0+1] = c[mt][j][3]+b1;
        }
    }
}

// Build mi (row-major bf16 [64][LDK]) for 2 nodes.
__device__ __forceinline__ void build_mi2(MsgSmem2& S, int bl0, int b, int t,
                                          const float* __restrict__ hVsrc,
                                          const float* __restrict__ hE)
{
    int w=t>>5, lane=t&31;
    // stage A: features 0..383 (node_e | h_E | nb_hV)
    #pragma unroll
    for (int i=0;i<8;i++){
        int gr = w*8+i; int v = gr>>5;
        size_t e = (size_t)bl0*KK + gr;
        int nb = S.nbidx[gr];
        const float4* hv4 = reinterpret_cast<const float4*>(&S.hv[v*HH]);
        const float4* he4 = reinterpret_cast<const float4*>(hE + e*HH);
        const float4* nb4 = reinterpret_cast<const float4*>(hVsrc + ((size_t)b*LL + nb)*HH);
        __nv_bfloat16* row = S.A0 + (size_t)gr*LDK;
        float4 x;
        x = hv4[lane];
        *reinterpret_cast<uint2*>(row + lane*4)        = make_uint2(bf16x2(x.x,x.y), bf16x2(x.z,x.w));
        x = he4[lane];
        *reinterpret_cast<uint2*>(row + HH + lane*4)   = make_uint2(bf16x2(x.x,x.y), bf16x2(x.z,x.w));
        x = nb4[lane];
        *reinterpret_cast<uint2*>(row + 2*HH + lane*4) = make_uint2(bf16x2(x.x,x.y), bf16x2(x.z,x.w));
        if (lane < 8) reinterpret_cast<uint32_t*>(row + MSG)[lane] = 0u;  // zero pad 456..471
    }
    // stage B: geometry features 384..455, one thread per edge-row
    if (t < MROWS){
        int gr=t, v=gr>>5;
        const float* R  = S.Rr  + v*9;
        const float* tv = S.tvv + v*3;
        const float* pl = S.pll + v*24;
        const float* pg = S.pgg + v*24;
        int nb = S.nbidx[gr];
        const float* npg = g_pg + ((size_t)b*LL + nb)*24;
        __nv_bfloat16* q = S.A0 + (size_t)gr*LDK + 3*HH;
        #pragma unroll
        for (int p=0;p<PP;p++){
            float plx=pl[p*3], ply=pl[p*3+1], plz=pl[p*3+2];
            q[p*3+0]=__float2bfloat16_rn(plx);
            q[p*3+1]=__float2bfloat16_rn(ply);
            q[p*3+2]=__float2bfloat16_rn(plz);
            q[24+p] =__float2bfloat16_rn(sqrtf(plx*plx+ply*ply+plz*plz+1e-8f));
            float dx=npg[p*3+0]-tv[0], dy=npg[p*3+1]-tv[1], dz=npg[p*3+2]-tv[2];
            float nlx = R[0]*dx + R[3]*dy + R[6]*dz;
            float nly = R[1]*dx + R[4]*dy + R[7]*dz;
            float nlz = R[2]*dx + R[5]*dy + R[8]*dz;
            q[32+p*3+0]=__float2bfloat16_rn(nlx);
            q[32+p*3+1]=__float2bfloat16_rn(nly);
            q[32+p*3+2]=__float2bfloat16_rn(nlz);
            q[56+p]=__float2bfloat16_rn(sqrtf(nlx*nlx+nly*nly+nlz*nlz+1e-8f));
            float gx=pg[p*3+0]-npg[p*3+0];
            float gy=pg[p*3+1]-npg[p*3+1];
            float gz=pg[p*3+2]-npg[p*3+2];
            q[64+p]=__float2bfloat16_rn(sqrtf(gx*gx+gy*gy+gz*gz+1e-8f));
        }
    }
}

// Three chained GEMMs. Leaves fp32 message in (float*)S.A0 [64][LDF].
__device__ __forceinline__ void run_msg_gemms(MsgSmem2& S,
    const uint32_t* __restrict__ B1, const float* __restrict__ b1,
    const uint32_t* __restrict__ B2, const float* __restrict__ b2,
    const uint32_t* __restrict__ B3, const float* __restrict__ b3, int t)
{
    int lane=t&31, nq=t>>5;
    uint32_t a0 = (uint32_t)__cvta_generic_to_shared(S.A0);
    uint32_t a1 = (uint32_t)__cvta_generic_to_shared(S.A1);
    float c[4][2][4];

    mma_bf16<29>(B1, nq, a0, LDK*2, lane, c);
    epi_gelu_bf16(c, b1, S.A1, lane, nq);
    __syncthreads();

    mma_bf16<8>(B2, nq, a1, LDH*2, lane, c);
    epi_gelu_bf16(c, b2, S.A0, lane, nq);     // h2 reuses A0 (LDH layout)
    __syncthreads();

    mma_bf16<8>(B3, nq, a0, LDH*2, lane, c);
    __syncthreads();                          // all h2 reads done before fp32 overwrite
    epi_float(c, b3, reinterpret_cast<float*>(S.A0), lane, nq);
    __syncthreads();
}

__device__ __forceinline__ void load_node_params(MsgSmem2& S, int bl0, int t,
                                                 const float* __restrict__ hVsrc,
                                                 const int* __restrict__ Eidx,
                                                 const float* __restrict__ maskA)
{
    if (t < NODES*HH) S.hv[t] = hVsrc[(size_t)bl0*HH + t];
    if (t < MROWS){
        S.nbidx[t] = Eidx[(size_t)bl0*KK + t];
        S.mask[t]  = maskA ? maskA[(size_t)bl0*KK + t] : 1.0f;
    }
    if (t < NODES*9)  S.Rr[t]  = g_R[bl0*9 + t];
    if (t < NODES*3)  S.tvv[t] = g_t[bl0*3 + t];
    if (t < NODES*24){ S.pll[t] = g_pl[bl0*24 + t]; S.pgg[t] = g_pg[bl0*24 + t]; }
}

// ============================================================
// Node message kernel: 2 nodes/CTA -> msg -> masked mean -> LN1 -> g_xn
// ============================================================
__global__ __launch_bounds__(256,2) void k_node(
    const float* __restrict__ hV, const float* __restrict__ hE,
    const int* __restrict__ Eidx, const float* __restrict__ maskA,
    const float* __restrict__ b1, const float* __restrict__ b2, const float* __restrict__ b3,
    const float* __restrict__ g1, const float* __restrict__ be1)
{
    extern __shared__ char smem_raw[];
    MsgSmem2& S = *reinterpret_cast<MsgSmem2*>(smem_raw);
    int bl0 = blockIdx.x * NODES;
    int b   = bl0 / LL;
    int t   = threadIdx.x;

    load_node_params(S, bl0, t, hV, Eidx, maskA);
    __syncthreads();
    build_mi2(S, bl0, b, t, hV, hE);
    __syncthreads();
    run_msg_gemms(S, g_W1pb, b1, g_W2pb, b2, g_W3pb, b3, t);

    const float* msgF = reinterpret_cast<const float*>(S.A0);
    int f = t&127, v = t>>7, lane = t&31, widx = (t>>5)&3;
    float acc = 0.f;
    #pragma unroll
    for (int r=0;r<32;r++) acc += S.mask[v*32+r] * msgF[(size_t)(v*32+r)*LDF + f];
    float x = S.hv[v*HH + f] + acc*(1.0f/KK);
    float s=x, q=x*x;
    #pragma unroll
    for (int o=16;o>0;o>>=1){
        s += __shfl_down_sync(0xffffffffu, s, o);
        q += __shfl_down_sync(0xffffffffu, q, o);
    }
    if (lane==0){ S.red[v*4+widx]=s; S.red[8+v*4+widx]=q; }
    __syncthreads();
    float ts = S.red[v*4]+S.red[v*4+1]+S.red[v*4+2]+S.red[v*4+3];
    float tq = S.red[8+v*4]+S.red[8+v*4+1]+S.red[8+v*4+2]+S.red[8+v*4+3];
    float mu = ts*(1.0f/HH);
    float rstd = rsqrtf(tq*(1.0f/HH)-mu*mu+1e-5f);
    g_xn[(size_t)(bl0+v)*HH + f] = (x-mu)*rstd*g1[f] + be1[f];
}

// ============================================================
// Edge message kernel: 2 nodes/CTA -> msg -> residual(fp32) -> per-edge LN -> h_E
// ============================================================
__global__ __launch_bounds__(256,2) void k_edge(
    const float* __restrict__ hE, const int* __restrict__ Eidx,
    const float* __restrict__ b1, const float* __restrict__ b2, const float* __restrict__ b3,
    const float* __restrict__ g3, const float* __restrict__ be3,
    float* __restrict__ out_hE)
{
    extern __shared__ char smem_raw[];
    MsgSmem2& S = *reinterpret_cast<MsgSmem2*>(smem_raw);
    int bl0 = blockIdx.x * NODES;
    int b   = bl0 / LL;
    int t   = threadIdx.x;

    load_node_params(S, bl0, t, g_hV, Eidx, (const float*)0);
    __syncthreads();
    build_mi2(S, bl0, b, t, g_hV, hE);
    __syncthreads();
    run_msg_gemms(S, g_W11pb, b1, g_W12pb, b2, g_W13pb, b3, t);

    const float* msgF = reinterpret_cast<const float*>(S.A0);
    int w = t>>5, lane = t&31;
    #pragma unroll
    for (int i=0;i<8;i++){
        int gr = w*8+i;
        size_t e = (size_t)bl0*KK + gr;
        float4 hv_ = reinterpret_cast<const float4*>(hE + e*HH)[lane];
        float4 mv  = reinterpret_cast<const float4*>(msgF + (size_t)gr*LDF)[lane];
        float x0 = mv.x+hv_.x, x1 = mv.y+hv_.y, x2 = mv.z+hv_.z, x3 = mv.w+hv_.w;
        float s = x0+x1+x2+x3;
        float q = x0*x0+x1*x1+x2*x2+x3*x3;
        #pragma unroll
        for (int o=16;o>0;o>>=1){
            s += __shfl_xor_sync(0xffffffffu, s, o);
            q += __shfl_xor_sync(0xffffffffu, q, o);
        }
        float mu = s*(1.0f/HH);
        float rstd = rsqrtf(q*(1.0f/HH)-mu*mu+1e-5f);
        int f0 = lane*4;
        float4 gg = *reinterpret_cast<const float4*>(g3 + f0);
        float4 bb = *reinterpret_cast<const float4*>(be3 + f0);
        float4 o4;
        o4.x = (x0-mu)*rstd*gg.x + bb.x;
        o4.y = (x1-mu)*rstd*gg.y + bb.y;
        o4.z = (x2-mu)*rstd*gg.z + bb.z;
        o4.w = (x3-mu)*rstd*gg.w + bb.w;
        *reinterpret_cast<float4*>(out_hE + e*HH + f0) = o4;
    }
}

// ============================================================
// tf32 FFN (unchanged)
// ============================================================
template<int NKC>
__device__ __forceinline__ void mma_core(const float* __restrict__ Bpack, int ntiles, int jbase,
                                         const float* sA, float c[2][4][4], int lane)
{
    int qid = lane>>2, tig = lane&3;
    #pragma unroll
    for (int mt=0;mt<2;mt++)
        #pragma unroll
        for (int j=0;j<4;j++)
            #pragma unroll
            for (int i=0;i<4;i++) c[mt][j][i]=0.f;
    const float* bbase = Bpack + (size_t)jbase*64 + lane*2;
    #pragma unroll 4
    for (int kc=0; kc<NKC; kc++){
        const float* a0p = sA + (kc*8+tig)*LDT;
        const float* a1p = a0p + 4*LDT;
        uint32_t a[2][4];
        a[0][0]=__float_as_uint(a0p[qid]);
        a[0][1]=__float_as_uint(a0p[qid+8]);
        a[0][2]=__float_as_uint(a1p[qid]);
        a[0][3]=__float_as_uint(a1p[qid+8]);
        a[1][0]=__float_as_uint(a0p[qid+16]);
        a[1][1]=__float_as_uint(a0p[qid+24]);
        a[1][2]=__float_as_uint(a1p[qid+16]);
        a[1][3]=__float_as_uint(a1p[qid+24]);
        const float* bp = bbase + (size_t)kc*ntiles*64;
        #pragma unroll
        for (int j=0;j<4;j++){
            float2 bv = *reinterpret_cast<const float2*>(bp + (size_t)j*64);
            uint32_t b0=__float_as_uint(bv.x), b1=__float_as_uint(bv.y);
            mma8(c[0][j], a[0], b0, b1);
            mma8(c[1][j], a[1], b0, b1);
        }
    }
}

__global__ void k_ffn1(const float* __restrict__ bdin)
{
    __shared__ float sA[HH*LDT];
    int rb = blockIdx.x, cb = blockIdx.y;
    int t = threadIdx.x;
    int lane=t&31, warp=t>>5;

    int m = t>>2; int k0 = (t&3)*32;
    const float* src = g_xn + ((size_t)(rb*32+m))*HH + k0;
    #pragma unroll
    for (int i=0;i<8;i++){
        float4 v = *reinterpret_cast<const float4*>(src + i*4);
        sA[(k0+i*4+0)*LDT+m]=tf32r(v.x);
        sA[(k0+i*4+1)*LDT+m]=tf32r(v.y);
        sA[(k0+i*4+2)*LDT+m]=tf32r(v.z);
        sA[(k0+i*4+3)*LDT+m]=tf32r(v.w);
    }
    __syncthreads();

    float c[2][4][4];
    mma_core<16>(g_Wdinp, 64, cb*16 + warp*4, sA, c, lane);

    int qid=lane>>2, tig=lane&3;
    #pragma unroll
    for (int j=0;j<4;j++){
        int n = (cb*16+warp*4+j)*8 + tig*2;
        float b0=bdin[n], b1=bdin[n+1];
        #pragma unroll
        for (int mt=0;mt<2;mt++){
            int r = rb*32 + mt*16 + qid;
            g_ff[(size_t)r*512 + n]       = gelu_f(c[mt][j][0]+b0);
            g_ff[(size_t)r*512 + n+1]     = gelu_f(c[mt][j][1]+b1);
            g_ff[(size_t)(r+8)*512 + n]   = gelu_f(c[mt][j][2]+b0);
            g_ff[(size_t)(r+8)*512 + n+1] = gelu_f(c[mt][j][3]+b1);
        }
    }
}

struct FfnSmem {
    float sA[4*HH*LDT];
    float mu[32], rstd[32];
};

__global__ void k_ffn2(const float* __restrict__ bdout,
                       const float* __restrict__ g2, const float* __restrict__ be2,
                       const float* __restrict__ maskV,
                       float* __restrict__ out_hV)
{
    extern __shared__ char smem_raw[];
    FfnSmem& S = *reinterpret_cast<FfnSmem*>(smem_raw);
    int rb = blockIdx.x;
    int t = threadIdx.x;
    int lane=t&31, warp=t>>5;

    int m = t>>2; int k0 = (t&3)*128;
    const float* src = g_ff + ((size_t)(rb*32+m))*512 + k0;
    #pragma unroll
    for (int i=0;i<32;i++){
        float4 v = *reinterpret_cast<const float4*>(src + i*4);
        S.sA[(k0+i*4+0)*LDT+m]=tf32r(v.x);
        S.sA[(k0+i*4+1)*LDT+m]=tf32r(v.y);
        S.sA[(k0+i*4+2)*LDT+m]=tf32r(v.z);
        S.sA[(k0+i*4+3)*LDT+m]=tf32r(v.w);
    }
    __syncthreads();

    float c[2][4][4];
    mma_core<64>(g_Wdoutp, 16, warp*4, S.sA, c, lane);
    __syncthreads();

    int qid=lane>>2, tig=lane&3;
    #pragma unroll
    for (int j=0;j<4;j++){
        int n = (warp*4+j)*8 + tig*2;
        float b0=bdout[n], b1=bdout[n+1];
        #pragma unroll
        for (int mt=0;mt<2;mt++){
            int r = mt*16 + qid;
            size_t node0 = (size_t)(rb*32 + r);
            size_t node1 = node0 + 8;
            S.sA[n*LDT + r]       = c[mt][j][0]+b0 + g_xn[node0*HH + n];
            S.sA[(n+1)*LDT + r]   = c[mt][j][1]+b1 + g_xn[node0*HH + n+1];
            S.sA[n*LDT + r+8]     = c[mt][j][2]+b0 + g_xn[node1*HH + n];
            S.sA[(n+1)*LDT + r+8] = c[mt][j][3]+b1 + g_xn[node1*HH + n+1];
        }
    }
    __syncthreads();

    if (t < 32){
        float s=0.f, q=0.f;
        #pragma unroll 4
        for (int cf=0;cf<HH;cf++){ float v=S.sA[cf*LDT+t]; s+=v; q+=v*v; }
        float mu = s*(1.f/HH);
        S.mu[t]=mu;
        S.rstd[t]=rsqrtf(q*(1.f/HH)-mu*mu+1e-5f);
    }
    __syncthreads();

    float gg=g2[t], bb=be2[t];
    for (int r=0;r<32;r++){
        size_t node = (size_t)(rb*32+r);
        float y = (S.sA[t*LDT+r]-S.mu[r])*S.rstd[r]*gg+bb;
        y *= maskV[node];
        g_hV[node*HH+t]=y;
        out_hV[node*HH+t]=y;
    }
}

// ============================================================
extern "C" void kernel_launch(void* const* d_in, const int* in_sizes, int n_in,
                              void* d_out, int out_size)
{
    const float* hV    =(const float*)d_in[0];
    const float* hE    =(const float*)d_in[1];
    const int*   Eidx  =(const int*)  d_in[2];
    const float* X     =(const float*)d_in[3];
    const float* maskV =(const float*)d_in[4];
    const float* maskA =(const float*)d_in[5];
    const float* Wp_node=(const float*)d_in[6];  const float* bp_node=(const float*)d_in[7];
    const float* Wp_edge=(const float*)d_in[8];  const float* bp_edge=(const float*)d_in[9];
    const float* W1 =(const float*)d_in[10]; const float* b1 =(const float*)d_in[11];
    const float* W2 =(const float*)d_in[12]; const float* b2 =(const float*)d_in[13];
    const float* W3 =(const float*)d_in[14]; const float* b3 =(const float*)d_in[15];
    const float* W11=(const float*)d_in[16]; const float* b11=(const float*)d_in[17];
    const float* W12=(const float*)d_in[18]; const float* b12=(const float*)d_in[19];
    const float* W13=(const float*)d_in[20]; const float* b13=(const float*)d_in[21];
    const float* Wdin =(const float*)d_in[22]; const float* bdin =(const float*)d_in[23];
    const float* Wdout=(const float*)d_in[24]; const float* bdout=(const float*)d_in[25];
    const float* g1=(const float*)d_in[26]; const float* be1=(const float*)d_in[27];
    const float* g2=(const float*)d_in[28]; const float* be2=(const float*)d_in[29];
    const float* g3=(const float*)d_in[30]; const float* be3=(const float*)d_in[31];

    float* out_hV = (float*)d_out;
    float* out_hE = out_hV + (size_t)NB*HH;

    int smem_msg = (int)sizeof(MsgSmem2);
    int smem_ffn = (int)sizeof(FfnSmem);
    cudaFuncSetAttribute(k_node, cudaFuncAttributeMaxDynamicSharedMemorySize, smem_msg);
    cudaFuncSetAttribute(k_edge, cudaFuncAttributeMaxDynamicSharedMemorySize, smem_msg);
    cudaFuncSetAttribute(k_ffn2, cudaFuncAttributeMaxDynamicSharedMemorySize, smem_ffn);

    uint32_t *p1,*p2,*p3,*p11,*p12,*p13;
    float *pdin,*pdout,*phv;
    cudaGetSymbolAddress((void**)&p1,   g_W1pb);
    cudaGetSymbolAddress((void**)&p2,   g_W2pb);
    cudaGetSymbolAddress((void**)&p3,   g_W3pb);
    cudaGetSymbolAddress((void**)&p11,  g_W11pb);
    cudaGetSymbolAddress((void**)&p12,  g_W12pb);
    cudaGetSymbolAddress((void**)&p13,  g_W13pb);
    cudaGetSymbolAddress((void**)&pdin, g_Wdinp);
    cudaGetSymbolAddress((void**)&pdout,g_Wdoutp);
    cudaGetSymbolAddress((void**)&phv,  g_hV);

    k_packb<<<dim3(29,16,6),32>>>(W1,W2,W3,W11,W12,W13,p1,p2,p3,p11,p12,p13);
    dim3 pb(32,16);
    k_pack<<<dim3(16,4),pb>>>(Wdin,  pdin, 512);
    k_pack<<<dim3(64,1),pb>>>(Wdout, pdout,128);

    k_frames<<<NB/128,128>>>(X);
    k_proj<<<NB*24/256,256>>>(hV, Wp_node, bp_node);
    k_pg<<<NB*24/256,256>>>();
    k_node<<<NB/NODES,256,smem_msg>>>(hV,hE,Eidx,maskA,b1,b2,b3,g1,be1);
    k_ffn1<<<dim3(128,4),128>>>(bdin);
    k_ffn2<<<128,128,smem_ffn>>>(bdout,g2,be2,maskV,out_hV);
    k_proj<<<NB*24/256,256>>>(phv, Wp_edge, bp_edge);
    k_pg<<<NB*24/256,256>>>();
    k_edge<<<NB/NODES,256,smem_msg>>>(hE,Eidx,b11,b12,b13,g3,be3,out_hE);
}

// round 6
// speedup vs baseline: 7.1709x; 1.0024x over previous
#include <cuda_runtime.h>
#include <cuda_bf16.h>
#include <math.h>
#include <stdint.h>

#define BB 2
#define LL 2048
#define KK 32
#define HH 128
#define PP 8
#define MSG 456
#define LDT 40        /* tf32 FFN tiles */
#define NB (BB*LL)    /* 4096 nodes */

#define NODES 2       /* nodes per message CTA */
#define MROWS (NODES*KK)   /* 64 */
#define LDK 472       /* bf16 elems per mi row (944B stride, conflict-free) */
#define LDH 136       /* bf16 elems per h row (272B stride) */
#define LDF 132       /* fp32 msg row */

// -------- scratch --------
__device__ float g_R [NB*9];
__device__ float g_t [NB*3];
__device__ float g_pl[NB*24];
__device__ float g_pg[NB*24];
__device__ float g_hV[NB*HH];
__device__ float g_xn[NB*HH];
__device__ float g_u [NB*HH];          /* per-node head contribution */
__device__ float g_ff[(size_t)NB*4*HH];

// tf32 packed weights
__device__ float g_Wdinp [16*64*64];
__device__ float g_Wdoutp[64*16*64];
__device__ float g_W1hp  [16*16*64];   /* W1[0:128]  head */
__device__ float g_W11hp [16*16*64];   /* W11[0:128] head */

// bf16 packed message weights: [((kc*16 + j)*32 + lane)*2 + reg]
__device__ uint32_t g_W1pb [29*16*64];
__device__ uint32_t g_W2pb [ 8*16*64];
__device__ uint32_t g_W3pb [ 8*16*64];
__device__ uint32_t g_W11pb[29*16*64];
__device__ uint32_t g_W12pb[ 8*16*64];
__device__ uint32_t g_W13pb[ 8*16*64];

__device__ __forceinline__ float gelu_f(float x){
    return 0.5f*x*(1.0f+erff(x*0.70710678118654752440f));
}
__device__ __forceinline__ float tf32r(float x){
    uint32_t u; asm("cvt.rna.tf32.f32 %0, %1;" : "=r"(u) : "f"(x));
    return __uint_as_float(u);
}
__device__ __forceinline__ uint32_t bf16x2(float lo, float hi){
    __nv_bfloat162 h = __floats2bfloat162_rn(lo, hi);
    return *reinterpret_cast<uint32_t*>(&h);
}
__device__ __forceinline__ void mma8(float* c, const uint32_t* a, uint32_t b0, uint32_t b1){
    asm volatile("mma.sync.aligned.m16n8k8.row.col.f32.tf32.tf32.f32 "
        "{%0,%1,%2,%3},{%4,%5,%6,%7},{%8,%9},{%0,%1,%2,%3};"
        : "+f"(c[0]),"+f"(c[1]),"+f"(c[2]),"+f"(c[3])
        : "r"(a[0]),"r"(a[1]),"r"(a[2]),"r"(a[3]),"r"(b0),"r"(b1));
}
__device__ __forceinline__ void mma16816(float* c, const uint32_t* a, const uint32_t* b){
    asm volatile("mma.sync.aligned.m16n8k16.row.col.f32.bf16.bf16.f32 "
        "{%0,%1,%2,%3},{%4,%5,%6,%7},{%8,%9},{%0,%1,%2,%3};"
        : "+f"(c[0]),"+f"(c[1]),"+f"(c[2]),"+f"(c[3])
        : "r"(a[0]),"r"(a[1]),"r"(a[2]),"r"(a[3]),"r"(b[0]),"r"(b[1]));
}
__device__ __forceinline__ void ldsm4(uint32_t* r, uint32_t addr){
    asm volatile("ldmatrix.sync.aligned.m8n8.x4.shared.b16 {%0,%1,%2,%3}, [%4];"
        : "=r"(r[0]),"=r"(r[1]),"=r"(r[2]),"=r"(r[3]) : "r"(addr));
}

// ============================================================
// tf32 weight pack: W[K][N] row-major -> fragment order
// ============================================================
__global__ void k_pack(const float* __restrict__ W, float* __restrict__ out, int N)
{
    int ntiles = N >> 3;
    int kc   = blockIdx.x;
    int j    = blockIdx.y*16 + threadIdx.y;
    int lane = threadIdx.x;
    int row  = kc*8 + (lane&3);
    int col  = j*8 + (lane>>2);
    float b0 = W[row*N + col];
    float b1 = W[(row+4)*N + col];
    float* o = out + (((size_t)kc*ntiles + j)*32 + lane)*2;
    o[0] = tf32r(b0); o[1] = tf32r(b1);
}

// ============================================================
// bf16 weight pack for the 6 message weights. grid(29,16,6) block 32.
// ============================================================
__global__ void k_packb(const float* __restrict__ W1,const float* __restrict__ W2,
                        const float* __restrict__ W3,const float* __restrict__ W11,
                        const float* __restrict__ W12,const float* __restrict__ W13,
                        uint32_t* o1,uint32_t* o2,uint32_t* o3,
                        uint32_t* o11,uint32_t* o12,uint32_t* o13)
{
    int z = blockIdx.z;
    const float* src; uint32_t* dst; int Ktot;
    switch(z){
        case 0: src=W1;  dst=o1;  Ktot=MSG; break;
        case 1: src=W2;  dst=o2;  Ktot=HH;  break;
        case 2: src=W3;  dst=o3;  Ktot=HH;  break;
        case 3: src=W11; dst=o11; Ktot=MSG; break;
        case 4: src=W12; dst=o12; Ktot=HH;  break;
        default:src=W13; dst=o13; Ktot=HH;  break;
    }
    int kc = blockIdx.x;
    if (kc >= (Ktot+15)/16) return;
    int j = blockIdx.y, lane = threadIdx.x;
    int n = j*8 + (lane>>2);
    #pragma unroll
    for (int r=0;r<2;r++){
        int k = kc*16 + (lane&3)*2 + 8*r;
        float v0 = (k   < Ktot)? src[(size_t)k*HH + n]     : 0.f;
        float v1 = (k+1 < Ktot)? src[(size_t)(k+1)*HH + n] : 0.f;
        dst[(((size_t)kc*16 + j)*32 + lane)*2 + r] = bf16x2(v0, v1);
    }
}

// ============================================================
// Frames: 1 thread per node
// ============================================================
__global__ void k_frames(const float* __restrict__ X)
{
    int node = blockIdx.x*128 + threadIdx.x;
    if (node >= NB) return;
    const float* Xp = X + (size_t)node*12;
    float Nx=Xp[0],Ny=Xp[1],Nz=Xp[2];
    float Ax=Xp[3],Ay=Xp[4],Az=Xp[5];
    float Cx=Xp[6],Cy=Xp[7],Cz=Xp[8];
    float e0x=Ax-Nx, e0y=Ay-Ny, e0z=Az-Nz;
    float inv = 1.0f/sqrtf(e0x*e0x+e0y*e0y+e0z*e0z + 1e-8f);
    e0x*=inv; e0y*=inv; e0z*=inv;
    float e1x=Cx-Ax, e1y=Cy-Ay, e1z=Cz-Az;
    float d = e0x*e1x+e0y*e1y+e0z*e1z;
    e1x-=e0x*d; e1y-=e0y*d; e1z-=e0z*d;
    inv = 1.0f/sqrtf(e1x*e1x+e1y*e1y+e1z*e1z + 1e-8f);
    e1x*=inv; e1y*=inv; e1z*=inv;
    float e2x=e0y*e1z-e0z*e1y;
    float e2y=e0z*e1x-e0x*e1z;
    float e2z=e0x*e1y-e0y*e1x;
    float* R = g_R + node*9;
    R[0]=e0x; R[1]=e1x; R[2]=e2x;
    R[3]=e0y; R[4]=e1y; R[5]=e2y;
    R[6]=e0z; R[7]=e1z; R[8]=e2z;
    g_t[node*3+0]=Ax; g_t[node*3+1]=Ay; g_t[node*3+2]=Az;
}

// ============================================================
// p_local projection / p_global
// ============================================================
__global__ void k_proj(const float* __restrict__ hv,
                       const float* __restrict__ Wp,
                       const float* __restrict__ bp)
{
    int idx = blockIdx.x*256 + threadIdx.x;
    int node = idx/24, j = idx%24;
    const float* h = hv + (size_t)node*HH;
    float acc = bp[j];
    #pragma unroll 8
    for (int f=0; f<HH; f++) acc += h[f]*Wp[f*24+j];
    g_pl[(size_t)node*24 + j] = acc;
}

__global__ void k_pg()
{
    int idx = blockIdx.x*256 + threadIdx.x;
    int node = idx/24, l = idx%24;
    int p = l/3, i = l%3;
    const float* R  = g_R + node*9;
    const float* pl = g_pl + (size_t)node*24 + p*3;
    g_pg[(size_t)node*24 + l] =
        g_t[node*3+i] + R[i*3+0]*pl[0] + R[i*3+1]*pl[1] + R[i*3+2]*pl[2];
}

// ============================================================
// tf32 MMA core (FFN + head precompute)
// ============================================================
template<int NKC>
__device__ __forceinline__ void mma_core(const float* __restrict__ Bpack, int ntiles, int jbase,
                                         const float* sA, float c[2][4][4], int lane)
{
    int qid = lane>>2, tig = lane&3;
    #pragma unroll
    for (int mt=0;mt<2;mt++)
        #pragma unroll
        for (int j=0;j<4;j++)
            #pragma unroll
            for (int i=0;i<4;i++) c[mt][j][i]=0.f;
    const float* bbase = Bpack + (size_t)jbase*64 + lane*2;
    #pragma unroll 4
    for (int kc=0; kc<NKC; kc++){
        const float* a0p = sA + (kc*8+tig)*LDT;
        const float* a1p = a0p + 4*LDT;
        uint32_t a[2][4];
        a[0][0]=__float_as_uint(a0p[qid]);
        a[0][1]=__float_as_uint(a0p[qid+8]);
        a[0][2]=__float_as_uint(a1p[qid]);
        a[0][3]=__float_as_uint(a1p[qid+8]);
        a[1][0]=__float_as_uint(a0p[qid+16]);
        a[1][1]=__float_as_uint(a0p[qid+24]);
        a[1][2]=__float_as_uint(a1p[qid+16]);
        a[1][3]=__float_as_uint(a1p[qid+24]);
        const float* bp = bbase + (size_t)kc*ntiles*64;
        #pragma unroll
        for (int j=0;j<4;j++){
            float2 bv = *reinterpret_cast<const float2*>(bp + (size_t)j*64);
            uint32_t b0=__float_as_uint(bv.x), b1=__float_as_uint(bv.y);
            mma8(c[0][j], a[0], b0, b1);
            mma8(c[1][j], a[1], b0, b1);
        }
    }
}

// ============================================================
// Head precompute: out[node][128] = src[node] @ Whead + bias (no act)
// grid 128, block 128 (32 nodes per CTA)
// ============================================================
__global__ void k_head(const float* __restrict__ src,
                       const float* __restrict__ Bpack,
                       const float* __restrict__ bias,
                       float* __restrict__ out)
{
    __shared__ float sA[HH*LDT];
    int rb = blockIdx.x;
    int t = threadIdx.x;
    int lane=t&31, warp=t>>5;

    int m = t>>2; int k0 = (t&3)*32;
    const float* s = src + ((size_t)(rb*32+m))*HH + k0;
    #pragma unroll
    for (int i=0;i<8;i++){
        float4 v = *reinterpret_cast<const float4*>(s + i*4);
        sA[(k0+i*4+0)*LDT+m]=tf32r(v.x);
        sA[(k0+i*4+1)*LDT+m]=tf32r(v.y);
        sA[(k0+i*4+2)*LDT+m]=tf32r(v.z);
        sA[(k0+i*4+3)*LDT+m]=tf32r(v.w);
    }
    __syncthreads();

    float c[2][4][4];
    mma_core<16>(Bpack, 16, warp*4, sA, c, lane);

    int qid=lane>>2, tig=lane&3;
    #pragma unroll
    for (int j=0;j<4;j++){
        int n = (warp*4+j)*8 + tig*2;
        float b0=bias[n], b1=bias[n+1];
        #pragma unroll
        for (int mt=0;mt<2;mt++){
            int r = rb*32 + mt*16 + qid;
            out[(size_t)r*HH + n]       = c[mt][j][0]+b0;
            out[(size_t)r*HH + n+1]     = c[mt][j][1]+b1;
            out[(size_t)(r+8)*HH + n]   = c[mt][j][2]+b0;
            out[(size_t)(r+8)*HH + n+1] = c[mt][j][3]+b1;
        }
    }
}

// ============================================================
// Message-kernel shared memory (2 nodes, M=64)
// ============================================================
struct __align__(16) MsgSmem2 {
    __nv_bfloat16 A0[MROWS*LDK];  // mi (bf16) -> h2 (bf16 LDH) -> msgF (fp32 LDF)
    __nv_bfloat16 A1[MROWS*LDH];  // h1
    float hv[NODES*HH];
    float uu[NODES*HH];           // per-node head contribution (incl. bias)
    float Rr[NODES*9], tvv[NODES*3], pll[NODES*24], pgg[NODES*24];
    float mask[MROWS];
    int   nbidx[MROWS];
    float red[16];
};

// ============================================================
// bf16 MMA core: warp (mq,nq) computes C[32 x 32] slice of [64x128].
// ldsm:mma = 1:4.
// ============================================================
template<int NKC>
__device__ __forceinline__ void mma_bf16(const uint32_t* __restrict__ Bp, int nq,
                                         uint32_t aAddr, int ldkB, int mq, int lane,
                                         float c[2][4][4])
{
    #pragma unroll
    for (int mt=0;mt<2;mt++)
        #pragma unroll
        for (int j=0;j<4;j++)
            #pragma unroll
            for (int i=0;i<4;i++) c[mt][j][i]=0.f;

    uint32_t arow = aAddr + (uint32_t)((mq*32 + (lane&15))*ldkB) + ((lane>>4)&1)*16;
    for (int kc=0; kc<NKC; kc++){
        uint32_t a[2][4];
        #pragma unroll
        for (int mt=0;mt<2;mt++) ldsm4(a[mt], arow + mt*16*ldkB + kc*32);
        const uint32_t* bp = Bp + ((size_t)(kc*16 + nq*4)*32 + lane)*2;
        uint32_t b[4][2];
        #pragma unroll
        for (int j=0;j<4;j++){
            uint2 u = *reinterpret_cast<const uint2*>(bp + j*64);
            b[j][0]=u.x; b[j][1]=u.y;
        }
        #pragma unroll
        for (int mt=0;mt<2;mt++)
            #pragma unroll
            for (int j=0;j<4;j++) mma16816(c[mt][j], a[mt], b[j]);
    }
}

// GEMM1 epilogue: add per-node head vector u (bias included), gelu, bf16 store
__device__ __forceinline__ void epi_gelu_u(float c[2][4][4], const float* __restrict__ uu,
                                           __nv_bfloat16* dst, int lane, int mq, int nq)
{
    int qid=lane>>2, tig=lane&3;
    const float* uv = uu + mq*HH;   // warp's mq block == node index
    #pragma unroll
    for (int mt=0;mt<2;mt++){
        int r0 = mq*32 + mt*16 + qid;
        #pragma unroll
        for (int j=0;j<4;j++){
            int n0 = nq*32 + j*8 + tig*2;
            float b0=uv[n0], b1=uv[n0+1];
            *reinterpret_cast<uint32_t*>(dst + (size_t)r0*LDH + n0) =
                bf16x2(gelu_f(c[mt][j][0]+b0), gelu_f(c[mt][j][1]+b1));
            *reinterpret_cast<uint32_t*>(dst + (size_t)(r0+8)*LDH + n0) =
                bf16x2(gelu_f(c[mt][j][2]+b0), gelu_f(c[mt][j][3]+b1));
        }
    }
}

__device__ __forceinline__ void epi_gelu_bf16(float c[2][4][4], const float* __restrict__ bias,
                                              __nv_bfloat16* dst, int lane, int mq, int nq)
{
    int qid=lane>>2, tig=lane&3;
    #pragma unroll
    for (int mt=0;mt<2;mt++){
        int r0 = mq*32 + mt*16 + qid;
        #pragma unroll
        for (int j=0;j<4;j++){
            int n0 = nq*32 + j*8 + tig*2;
            float b0=bias[n0], b1=bias[n0+1];
            *reinterpret_cast<uint32_t*>(dst + (size_t)r0*LDH + n0) =
                bf16x2(gelu_f(c[mt][j][0]+b0), gelu_f(c[mt][j][1]+b1));
            *reinterpret_cast<uint32_t*>(dst + (size_t)(r0+8)*LDH + n0) =
                bf16x2(gelu_f(c[mt][j][2]+b0), gelu_f(c[mt][j][3]+b1));
        }
    }
}

__device__ __forceinline__ void epi_float(float c[2][4][4], const float* __restrict__ bias,
                                          float* msgF, int lane, int mq, int nq)
{
    int qid=lane>>2, tig=lane&3;
    #pragma unroll
    for (int mt=0;mt<2;mt++){
        int r0 = mq*32 + mt*16 + qid;
        #pragma unroll
        for (int j=0;j<4;j++){
            int n0 = nq*32 + j*8 + tig*2;
            float b0=bias[n0], b1=bias[n0+1];
            msgF[(size_t)r0*LDF + n0]       = c[mt][j][0]+b0;
            msgF[(size_t)r0*LDF + n0+1]     = c[mt][j][1]+b1;
            msgF[(size_t)(r0+8)*LDF + n0]   = c[mt][j][2]+b0;
            msgF[(size_t)(r0+8)*LDF + n0+1] = c[mt][j][3]+b1;
        }
    }
}

// Build mi rows 128..471 (head block 0..127 is skipped: handled via g_u).
__device__ __forceinline__ void build_mi2(MsgSmem2& S, int bl0, int b, int t,
                                          const float* __restrict__ hVsrc,
                                          const float* __restrict__ hE)
{
    int w=t>>5, lane=t&31;
    #pragma unroll
    for (int i=0;i<8;i++){
        int gr = w*8+i;
        size_t e = (size_t)bl0*KK + gr;
        int nb = S.nbidx[gr];
        const float4* he4 = reinterpret_cast<const float4*>(hE + e*HH);
        const float4* nb4 = reinterpret_cast<const float4*>(hVsrc + ((size_t)b*LL + nb)*HH);
        __nv_bfloat16* row = S.A0 + (size_t)gr*LDK;
        float4 x;
        x = he4[lane];
        *reinterpret_cast<uint2*>(row + HH + lane*4)   = make_uint2(bf16x2(x.x,x.y), bf16x2(x.z,x.w));
        x = nb4[lane];
        *reinterpret_cast<uint2*>(row + 2*HH + lane*4) = make_uint2(bf16x2(x.x,x.y), bf16x2(x.z,x.w));
        if (lane < 8) reinterpret_cast<uint32_t*>(row + MSG)[lane] = 0u;  // zero pad 456..471
    }
    if (t < MROWS){
        int gr=t, v=gr>>5;
        const float* R  = S.Rr  + v*9;
        const float* tv = S.tvv + v*3;
        const float* pl = S.pll + v*24;
        const float* pg = S.pgg + v*24;
        int nb = S.nbidx[gr];
        const float* npg = g_pg + ((size_t)b*LL + nb)*24;
        __nv_bfloat16* q = S.A0 + (size_t)gr*LDK + 3*HH;
        #pragma unroll
        for (int p=0;p<PP;p++){
            float plx=pl[p*3], ply=pl[p*3+1], plz=pl[p*3+2];
            q[p*3+0]=__float2bfloat16_rn(plx);
            q[p*3+1]=__float2bfloat16_rn(ply);
            q[p*3+2]=__float2bfloat16_rn(plz);
            q[24+p] =__float2bfloat16_rn(sqrtf(plx*plx+ply*ply+plz*plz+1e-8f));
            float dx=npg[p*3+0]-tv[0], dy=npg[p*3+1]-tv[1], dz=npg[p*3+2]-tv[2];
            float nlx = R[0]*dx + R[3]*dy + R[6]*dz;
            float nly = R[1]*dx + R[4]*dy + R[7]*dz;
            float nlz = R[2]*dx + R[5]*dy + R[8]*dz;
            q[32+p*3+0]=__float2bfloat16_rn(nlx);
            q[32+p*3+1]=__float2bfloat16_rn(nly);
            q[32+p*3+2]=__float2bfloat16_rn(nlz);
            q[56+p]=__float2bfloat16_rn(sqrtf(nlx*nlx+nly*nly+nlz*nlz+1e-8f));
            float gx=pg[p*3+0]-npg[p*3+0];
            float gy=pg[p*3+1]-npg[p*3+1];
            float gz=pg[p*3+2]-npg[p*3+2];
            q[64+p]=__float2bfloat16_rn(sqrtf(gx*gx+gy*gy+gz*gz+1e-8f));
        }
    }
}

// Three chained GEMMs. Leaves fp32 message in (float*)S.A0 [64][LDF].
__device__ __forceinline__ void run_msg_gemms(MsgSmem2& S,
    const uint32_t* __restrict__ B1,
    const uint32_t* __restrict__ B2, const float* __restrict__ b2,
    const uint32_t* __restrict__ B3, const float* __restrict__ b3, int t)
{
    int lane=t&31, w=t>>5, mq=w&1, nq=w>>1;
    uint32_t a0 = (uint32_t)__cvta_generic_to_shared(S.A0);
    uint32_t a1 = (uint32_t)__cvta_generic_to_shared(S.A1);
    float c[2][4][4];

    // GEMM1 over k=128..463 only (kc 8..28); head handled via u.
    mma_bf16<21>(B1 + (size_t)8*16*64, nq, a0 + 2*HH, LDK*2, mq, lane, c);
    epi_gelu_u(c, S.uu, S.A1, lane, mq, nq);
    __syncthreads();

    mma_bf16<8>(B2, nq, a1, LDH*2, mq, lane, c);
    epi_gelu_bf16(c, b2, S.A0, lane, mq, nq);     // h2 reuses A0 (LDH layout)
    __syncthreads();

    mma_bf16<8>(B3, nq, a0, LDH*2, mq, lane, c);
    __syncthreads();                              // all h2 reads done before fp32 overwrite
    epi_float(c, b3, reinterpret_cast<float*>(S.A0), lane, mq, nq);
    __syncthreads();
}

__device__ __forceinline__ void load_node_params(MsgSmem2& S, int bl0, int t,
                                                 const float* __restrict__ hVsrc,
                                                 const int* __restrict__ Eidx,
                                                 const float* __restrict__ maskA)
{
    if (t < NODES*HH){
        S.hv[t] = hVsrc[(size_t)bl0*HH + t];
        S.uu[t] = g_u[(size_t)bl0*HH + t];
    }
    if (t < MROWS){
        S.nbidx[t] = Eidx[(size_t)bl0*KK + t];
        S.mask[t]  = maskA ? maskA[(size_t)bl0*KK + t] : 1.0f;
    }
    if (t < NODES*9)  S.Rr[t]  = g_R[bl0*9 + t];
    if (t < NODES*3)  S.tvv[t] = g_t[bl0*3 + t];
    if (t < NODES*24){ S.pll[t] = g_pl[bl0*24 + t]; S.pgg[t] = g_pg[bl0*24 + t]; }
}

// ============================================================
// Node message kernel
// ============================================================
__global__ __launch_bounds__(256,2) void k_node(
    const float* __restrict__ hV, const float* __restrict__ hE,
    const int* __restrict__ Eidx, const float* __restrict__ maskA,
    const float* __restrict__ b2, const float* __restrict__ b3,
    const float* __restrict__ g1, const float* __restrict__ be1)
{
    extern __shared__ char smem_raw[];
    MsgSmem2& S = *reinterpret_cast<MsgSmem2*>(smem_raw);
    int bl0 = blockIdx.x * NODES;
    int b   = bl0 / LL;
    int t   = threadIdx.x;

    load_node_params(S, bl0, t, hV, Eidx, maskA);
    __syncthreads();
    build_mi2(S, bl0, b, t, hV, hE);
    __syncthreads();
    run_msg_gemms(S, g_W1pb, g_W2pb, b2, g_W3pb, b3, t);

    const float* msgF = reinterpret_cast<const float*>(S.A0);
    int f = t&127, v = t>>7, lane = t&31, widx = (t>>5)&3;
    float acc = 0.f;
    #pragma unroll
    for (int r=0;r<32;r++) acc += S.mask[v*32+r] * msgF[(size_t)(v*32+r)*LDF + f];
    float x = S.hv[v*HH + f] + acc*(1.0f/KK);
    float s=x, q=x*x;
    #pragma unroll
    for (int o=16;o>0;o>>=1){
        s += __shfl_down_sync(0xffffffffu, s, o);
        q += __shfl_down_sync(0xffffffffu, q, o);
    }
    if (lane==0){ S.red[v*4+widx]=s; S.red[8+v*4+widx]=q; }
    __syncthreads();
    float ts = S.red[v*4]+S.red[v*4+1]+S.red[v*4+2]+S.red[v*4+3];
    float tq = S.red[8+v*4]+S.red[8+v*4+1]+S.red[8+v*4+2]+S.red[8+v*4+3];
    float mu = ts*(1.0f/HH);
    float rstd = rsqrtf(tq*(1.0f/HH)-mu*mu+1e-5f);
    g_xn[(size_t)(bl0+v)*HH + f] = (x-mu)*rstd*g1[f] + be1[f];
}

// ============================================================
// Edge message kernel
// ============================================================
__global__ __launch_bounds__(256,2) void k_edge(
    const float* __restrict__ hE, const int* __restrict__ Eidx,
    const float* __restrict__ b2, const float* __restrict__ b3,
    const float* __restrict__ g3, const float* __restrict__ be3,
    float* __restrict__ out_hE)
{
    extern __shared__ char smem_raw[];
    MsgSmem2& S = *reinterpret_cast<MsgSmem2*>(smem_raw);
    int bl0 = blockIdx.x * NODES;
    int b   = bl0 / LL;
    int t   = threadIdx.x;

    load_node_params(S, bl0, t, g_hV, Eidx, (const float*)0);
    __syncthreads();
    build_mi2(S, bl0, b, t, g_hV, hE);
    __syncthreads();
    run_msg_gemms(S, g_W11pb, g_W12pb, b2, g_W13pb, b3, t);

    const float* msgF = reinterpret_cast<const float*>(S.A0);
    int w = t>>5, lane = t&31;
    #pragma unroll
    for (int i=0;i<8;i++){
        int gr = w*8+i;
        size_t e = (size_t)bl0*KK + gr;
        float4 hv_ = reinterpret_cast<const float4*>(hE + e*HH)[lane];
        float4 mv  = reinterpret_cast<const float4*>(msgF + (size_t)gr*LDF)[lane];
        float x0 = mv.x+hv_.x, x1 = mv.y+hv_.y, x2 = mv.z+hv_.z, x3 = mv.w+hv_.w;
        float s = x0+x1+x2+x3;
        float q = x0*x0+x1*x1+x2*x2+x3*x3;
        #pragma unroll
        for (int o=16;o>0;o>>=1){
            s += __shfl_xor_sync(0xffffffffu, s, o);
            q += __shfl_xor_sync(0xffffffffu, q, o);
        }
        float mu = s*(1.0f/HH);
        float rstd = rsqrtf(q*(1.0f/HH)-mu*mu+1e-5f);
        int f0 = lane*4;
        float4 gg = *reinterpret_cast<const float4*>(g3 + f0);
        float4 bb = *reinterpret_cast<const float4*>(be3 + f0);
        float4 o4;
        o4.x = (x0-mu)*rstd*gg.x + bb.x;
        o4.y = (x1-mu)*rstd*gg.y + bb.y;
        o4.z = (x2-mu)*rstd*gg.z + bb.z;
        o4.w = (x3-mu)*rstd*gg.w + bb.w;
        *reinterpret_cast<float4*>(out_hE + e*HH + f0) = o4;
    }
}

// ============================================================
// tf32 FFN
// ============================================================
__global__ void k_ffn1(const float* __restrict__ bdin)
{
    __shared__ float sA[HH*LDT];
    int rb = blockIdx.x, cb = blockIdx.y;
    int t = threadIdx.x;
    int lane=t&31, warp=t>>5;

    int m = t>>2; int k0 = (t&3)*32;
    const float* src = g_xn + ((size_t)(rb*32+m))*HH + k0;
    #pragma unroll
    for (int i=0;i<8;i++){
        float4 v = *reinterpret_cast<const float4*>(src + i*4);
        sA[(k0+i*4+0)*LDT+m]=tf32r(v.x);
        sA[(k0+i*4+1)*LDT+m]=tf32r(v.y);
        sA[(k0+i*4+2)*LDT+m]=tf32r(v.z);
        sA[(k0+i*4+3)*LDT+m]=tf32r(v.w);
    }
    __syncthreads();

    float c[2][4][4];
    mma_core<16>(g_Wdinp, 64, cb*16 + warp*4, sA, c, lane);

    int qid=lane>>2, tig=lane&3;
    #pragma unroll
    for (int j=0;j<4;j++){
        int n = (cb*16+warp*4+j)*8 + tig*2;
        float b0=bdin[n], b1=bdin[n+1];
        #pragma unroll
        for (int mt=0;mt<2;mt++){
            int r = rb*32 + mt*16 + qid;
            g_ff[(size_t)r*512 + n]       = gelu_f(c[mt][j][0]+b0);
            g_ff[(size_t)r*512 + n+1]     = gelu_f(c[mt][j][1]+b1);
            g_ff[(size_t)(r+8)*512 + n]   = gelu_f(c[mt][j][2]+b0);
            g_ff[(size_t)(r+8)*512 + n+1] = gelu_f(c[mt][j][3]+b1);
        }
    }
}

struct FfnSmem {
    float sA[4*HH*LDT];
    float mu[32], rstd[32];
};

__global__ void k_ffn2(const float* __restrict__ bdout,
                       const float* __restrict__ g2, const float* __restrict__ be2,
                       const float* __restrict__ maskV,
                       float* __restrict__ out_hV)
{
    extern __shared__ char smem_raw[];
    FfnSmem& S = *reinterpret_cast<FfnSmem*>(smem_raw);
    int rb = blockIdx.x;
    int t = threadIdx.x;
    int lane=t&31, warp=t>>5;

    int m = t>>2; int k0 = (t&3)*128;
    const float* src = g_ff + ((size_t)(rb*32+m))*512 + k0;
    #pragma unroll
    for (int i=0;i<32;i++){
        float4 v = *reinterpret_cast<const float4*>(src + i*4);
        S.sA[(k0+i*4+0)*LDT+m]=tf32r(v.x);
        S.sA[(k0+i*4+1)*LDT+m]=tf32r(v.y);
        S.sA[(k0+i*4+2)*LDT+m]=tf32r(v.z);
        S.sA[(k0+i*4+3)*LDT+m]=tf32r(v.w);
    }
    __syncthreads();

    float c[2][4][4];
    mma_core<64>(g_Wdoutp, 16, warp*4, S.sA, c, lane);
    __syncthreads();

    int qid=lane>>2, tig=lane&3;
    #pragma unroll
    for (int j=0;j<4;j++){
        int n = (warp*4+j)*8 + tig*2;
        float b0=bdout[n], b1=bdout[n+1];
        #pragma unroll
        for (int mt=0;mt<2;mt++){
            int r = mt*16 + qid;
            size_t node0 = (size_t)(rb*32 + r);
            size_t node1 = node0 + 8;
            S.sA[n*LDT + r]       = c[mt][j][0]+b0 + g_xn[node0*HH + n];
            S.sA[(n+1)*LDT + r]   = c[mt][j][1]+b1 + g_xn[node0*HH + n+1];
            S.sA[n*LDT + r+8]     = c[mt][j][2]+b0 + g_xn[node1*HH + n];
            S.sA[(n+1)*LDT + r+8] = c[mt][j][3]+b1 + g_xn[node1*HH + n+1];
        }
    }
    __syncthreads();

    if (t < 32){
        float s=0.f, q=0.f;
        #pragma unroll 4
        for (int cf=0;cf<HH;cf++){ float v=S.sA[cf*LDT+t]; s+=v; q+=v*v; }
        float mu = s*(1.f/HH);
        S.mu[t]=mu;
        S.rstd[t]=rsqrtf(q*(1.f/HH)-mu*mu+1e-5f);
    }
    __syncthreads();

    float gg=g2[t], bb=be2[t];
    for (int r=0;r<32;r++){
        size_t node = (size_t)(rb*32+r);
        float y = (S.sA[t*LDT+r]-S.mu[r])*S.rstd[r]*gg+bb;
        y *= maskV[node];
        g_hV[node*HH+t]=y;
        out_hV[node*HH+t]=y;
    }
}

// ============================================================
extern "C" void kernel_launch(void* const* d_in, const int* in_sizes, int n_in,
                              void* d_out, int out_size)
{
    const float* hV    =(const float*)d_in[0];
    const float* hE    =(const float*)d_in[1];
    const int*   Eidx  =(const int*)  d_in[2];
    const float* X     =(const float*)d_in[3];
    const float* maskV =(const float*)d_in[4];
    const float* maskA =(const float*)d_in[5];
    const float* Wp_node=(const float*)d_in[6];  const float* bp_node=(const float*)d_in[7];
    const float* Wp_edge=(const float*)d_in[8];  const float* bp_edge=(const float*)d_in[9];
    const float* W1 =(const float*)d_in[10]; const float* b1 =(const float*)d_in[11];
    const float* W2 =(const float*)d_in[12]; const float* b2 =(const float*)d_in[13];
    const float* W3 =(const float*)d_in[14]; const float* b3 =(const float*)d_in[15];
    const float* W11=(const float*)d_in[16]; const float* b11=(const float*)d_in[17];
    const float* W12=(const float*)d_in[18]; const float* b12=(const float*)d_in[19];
    const float* W13=(const float*)d_in[20]; const float* b13=(const float*)d_in[21];
    const float* Wdin =(const float*)d_in[22]; const float* bdin =(const float*)d_in[23];
    const float* Wdout=(const float*)d_in[24]; const float* bdout=(const float*)d_in[25];
    const float* g1=(const float*)d_in[26]; const float* be1=(const float*)d_in[27];
    const float* g2=(const float*)d_in[28]; const float* be2=(const float*)d_in[29];
    const float* g3=(const float*)d_in[30]; const float* be3=(const float*)d_in[31];

    float* out_hV = (float*)d_out;
    float* out_hE = out_hV + (size_t)NB*HH;

    int smem_msg = (int)sizeof(MsgSmem2);
    int smem_ffn = (int)sizeof(FfnSmem);
    cudaFuncSetAttribute(k_node, cudaFuncAttributeMaxDynamicSharedMemorySize, smem_msg);
    cudaFuncSetAttribute(k_edge, cudaFuncAttributeMaxDynamicSharedMemorySize, smem_msg);
    cudaFuncSetAttribute(k_ffn2, cudaFuncAttributeMaxDynamicSharedMemorySize, smem_ffn);

    uint32_t *p1,*p2,*p3,*p11,*p12,*p13;
    float *pdin,*pdout,*phv,*pw1h,*pw11h,*pu;
    cudaGetSymbolAddress((void**)&p1,   g_W1pb);
    cudaGetSymbolAddress((void**)&p2,   g_W2pb);
    cudaGetSymbolAddress((void**)&p3,   g_W3pb);
    cudaGetSymbolAddress((void**)&p11,  g_W11pb);
    cudaGetSymbolAddress((void**)&p12,  g_W12pb);
    cudaGetSymbolAddress((void**)&p13,  g_W13pb);
    cudaGetSymbolAddress((void**)&pdin, g_Wdinp);
    cudaGetSymbolAddress((void**)&pdout,g_Wdoutp);
    cudaGetSymbolAddress((void**)&phv,  g_hV);
    cudaGetSymbolAddress((void**)&pw1h, g_W1hp);
    cudaGetSymbolAddress((void**)&pw11h,g_W11hp);
    cudaGetSymbolAddress((void**)&pu,   g_u);

    k_packb<<<dim3(29,16,6),32>>>(W1,W2,W3,W11,W12,W13,p1,p2,p3,p11,p12,p13);
    dim3 pb(32,16);
    k_pack<<<dim3(16,4),pb>>>(Wdin,  pdin, 512);
    k_pack<<<dim3(64,1),pb>>>(Wdout, pdout,128);
    k_pack<<<dim3(16,1),pb>>>(W1,  pw1h, 128);
    k_pack<<<dim3(16,1),pb>>>(W11, pw11h,128);

    k_frames<<<NB/128,128>>>(X);
    k_proj<<<NB*24/256,256>>>(hV, Wp_node, bp_node);
    k_pg<<<NB*24/256,256>>>();
    k_head<<<NB/32,128>>>(hV, pw1h, b1, pu);
    k_node<<<NB/NODES,256,smem_msg>>>(hV,hE,Eidx,maskA,b2,b3,g1,be1);
    k_ffn1<<<dim3(128,4),128>>>(bdin);
    k_ffn2<<<128,128,smem_ffn>>>(bdout,g2,be2,maskV,out_hV);
    k_proj<<<NB*24/256,256>>>(phv, Wp_edge, bp_edge);
    k_pg<<<NB*24/256,256>>>();
    k_head<<<NB/32,128>>>(phv, pw11h, b11, pu);
    k_edge<<<NB/NODES,256,smem_msg>>>(hE,Eidx,b12,b13,g3,be3,out_hE);
}

// round 7
// speedup vs baseline: 8.5287x; 1.1893x over previous
#include <cuda_runtime.h>
#include <cuda_bf16.h>
#include <math.h>
#include <stdint.h>

#define BB 2
#define LL 2048
#define KK 32
#define HH 128
#define PP 8
#define MSG 456
#define LDT 40        /* tf32 FFN tiles */
#define NB (BB*LL)    /* 4096 nodes */

#define NODES 2       /* nodes per message CTA */
#define MROWS (NODES*KK)   /* 64 */
#define LDK 344       /* bf16 elems per mi row, k=128..471 of original (688B stride, conflict-free) */
#define LDH 136       /* bf16 elems per h row (272B stride) */
#define LDF 132       /* fp32 msg row */

// -------- scratch --------
__device__ float g_R [NB*9];
__device__ float g_t [NB*3];
__device__ float g_pl[NB*24];
__device__ float g_pg[NB*24];
__device__ float g_hV[NB*HH];
__device__ float g_xn[NB*HH];
__device__ float g_u [NB*HH];          /* per-node head contribution */
__device__ float g_ff[(size_t)NB*4*HH];

// tf32 packed weights
__device__ float g_Wdinp [16*64*64];
__device__ float g_Wdoutp[64*16*64];
__device__ float g_W1hp  [16*16*64];
__device__ float g_W11hp [16*16*64];

// bf16 packed message weights
__device__ uint32_t g_W1pb [29*16*64];
__device__ uint32_t g_W2pb [ 8*16*64];
__device__ uint32_t g_W3pb [ 8*16*64];
__device__ uint32_t g_W11pb[29*16*64];
__device__ uint32_t g_W12pb[ 8*16*64];
__device__ uint32_t g_W13pb[ 8*16*64];

__device__ __forceinline__ float gelu_f(float x){
    return 0.5f*x*(1.0f+erff(x*0.70710678118654752440f));
}
__device__ __forceinline__ float tf32r(float x){
    uint32_t u; asm("cvt.rna.tf32.f32 %0, %1;" : "=r"(u) : "f"(x));
    return __uint_as_float(u);
}
__device__ __forceinline__ uint32_t bf16x2(float lo, float hi){
    __nv_bfloat162 h = __floats2bfloat162_rn(lo, hi);
    return *reinterpret_cast<uint32_t*>(&h);
}
__device__ __forceinline__ void mma8(float* c, const uint32_t* a, uint32_t b0, uint32_t b1){
    asm volatile("mma.sync.aligned.m16n8k8.row.col.f32.tf32.tf32.f32 "
        "{%0,%1,%2,%3},{%4,%5,%6,%7},{%8,%9},{%0,%1,%2,%3};"
        : "+f"(c[0]),"+f"(c[1]),"+f"(c[2]),"+f"(c[3])
        : "r"(a[0]),"r"(a[1]),"r"(a[2]),"r"(a[3]),"r"(b0),"r"(b1));
}
__device__ __forceinline__ void mma16816(float* c, const uint32_t* a, const uint32_t* b){
    asm volatile("mma.sync.aligned.m16n8k16.row.col.f32.bf16.bf16.f32 "
        "{%0,%1,%2,%3},{%4,%5,%6,%7},{%8,%9},{%0,%1,%2,%3};"
        : "+f"(c[0]),"+f"(c[1]),"+f"(c[2]),"+f"(c[3])
        : "r"(a[0]),"r"(a[1]),"r"(a[2]),"r"(a[3]),"r"(b[0]),"r"(b[1]));
}
__device__ __forceinline__ void ldsm4(uint32_t* r, uint32_t addr){
    asm volatile("ldmatrix.sync.aligned.m8n8.x4.shared.b16 {%0,%1,%2,%3}, [%4];"
        : "=r"(r[0]),"=r"(r[1]),"=r"(r[2]),"=r"(r[3]) : "r"(addr));
}

// ============================================================
// tf32 weight pack
// ============================================================
__global__ void k_pack(const float* __restrict__ W, float* __restrict__ out, int N)
{
    int ntiles = N >> 3;
    int kc   = blockIdx.x;
    int j    = blockIdx.y*16 + threadIdx.y;
    int lane = threadIdx.x;
    int row  = kc*8 + (lane&3);
    int col  = j*8 + (lane>>2);
    float b0 = W[row*N + col];
    float b1 = W[(row+4)*N + col];
    float* o = out + (((size_t)kc*ntiles + j)*32 + lane)*2;
    o[0] = tf32r(b0); o[1] = tf32r(b1);
}

// ============================================================
// bf16 weight pack. grid(29,16,6) block 32.
// ============================================================
__global__ void k_packb(const float* __restrict__ W1,const float* __restrict__ W2,
                        const float* __restrict__ W3,const float* __restrict__ W11,
                        const float* __restrict__ W12,const float* __restrict__ W13,
                        uint32_t* o1,uint32_t* o2,uint32_t* o3,
                        uint32_t* o11,uint32_t* o12,uint32_t* o13)
{
    int z = blockIdx.z;
    const float* src; uint32_t* dst; int Ktot;
    switch(z){
        case 0: src=W1;  dst=o1;  Ktot=MSG; break;
        case 1: src=W2;  dst=o2;  Ktot=HH;  break;
        case 2: src=W3;  dst=o3;  Ktot=HH;  break;
        case 3: src=W11; dst=o11; Ktot=MSG; break;
        case 4: src=W12; dst=o12; Ktot=HH;  break;
        default:src=W13; dst=o13; Ktot=HH;  break;
    }
    int kc = blockIdx.x;
    if (kc >= (Ktot+15)/16) return;
    int j = blockIdx.y, lane = threadIdx.x;
    int n = j*8 + (lane>>2);
    #pragma unroll
    for (int r=0;r<2;r++){
        int k = kc*16 + (lane&3)*2 + 8*r;
        float v0 = (k   < Ktot)? src[(size_t)k*HH + n]     : 0.f;
        float v1 = (k+1 < Ktot)? src[(size_t)(k+1)*HH + n] : 0.f;
        dst[(((size_t)kc*16 + j)*32 + lane)*2 + r] = bf16x2(v0, v1);
    }
}

// ============================================================
// Frames: 1 thread per node
// ============================================================
__global__ void k_frames(const float* __restrict__ X)
{
    int node = blockIdx.x*128 + threadIdx.x;
    if (node >= NB) return;
    const float* Xp = X + (size_t)node*12;
    float Nx=Xp[0],Ny=Xp[1],Nz=Xp[2];
    float Ax=Xp[3],Ay=Xp[4],Az=Xp[5];
    float Cx=Xp[6],Cy=Xp[7],Cz=Xp[8];
    float e0x=Ax-Nx, e0y=Ay-Ny, e0z=Az-Nz;
    float inv = 1.0f/sqrtf(e0x*e0x+e0y*e0y+e0z*e0z + 1e-8f);
    e0x*=inv; e0y*=inv; e0z*=inv;
    float e1x=Cx-Ax, e1y=Cy-Ay, e1z=Cz-Az;
    float d = e0x*e1x+e0y*e1y+e0z*e1z;
    e1x-=e0x*d; e1y-=e0y*d; e1z-=e0z*d;
    inv = 1.0f/sqrtf(e1x*e1x+e1y*e1y+e1z*e1z + 1e-8f);
    e1x*=inv; e1y*=inv; e1z*=inv;
    float e2x=e0y*e1z-e0z*e1y;
    float e2y=e0z*e1x-e0x*e1z;
    float e2z=e0x*e1y-e0y*e1x;
    float* R = g_R + node*9;
    R[0]=e0x; R[1]=e1x; R[2]=e2x;
    R[3]=e0y; R[4]=e1y; R[5]=e2y;
    R[6]=e0z; R[7]=e1z; R[8]=e2z;
    g_t[node*3+0]=Ax; g_t[node*3+1]=Ay; g_t[node*3+2]=Az;
}

// ============================================================
// Fused p_local projection + p_global. block (24,8), grid NB/8.
// ============================================================
__global__ void k_projpg(const float* __restrict__ hv,
                         const float* __restrict__ Wp,
                         const float* __restrict__ bp)
{
    __shared__ float spl[8][24];
    int node = blockIdx.x*8 + threadIdx.y;
    int j = threadIdx.x;
    const float* h = hv + (size_t)node*HH;
    float acc = bp[j];
    #pragma unroll 8
    for (int f=0; f<HH; f++) acc += h[f]*Wp[f*24+j];
    g_pl[(size_t)node*24 + j] = acc;
    spl[threadIdx.y][j] = acc;
    __syncthreads();
    int p = j/3, i = j%3;
    const float* R = g_R + node*9;
    const float* pl = &spl[threadIdx.y][p*3];
    g_pg[(size_t)node*24 + j] =
        g_t[node*3+i] + R[i*3+0]*pl[0] + R[i*3+1]*pl[1] + R[i*3+2]*pl[2];
}

// ============================================================
// tf32 MMA core (FFN + head precompute)
// ============================================================
template<int NKC>
__device__ __forceinline__ void mma_core(const float* __restrict__ Bpack, int ntiles, int jbase,
                                         const float* sA, float c[2][4][4], int lane)
{
    int qid = lane>>2, tig = lane&3;
    #pragma unroll
    for (int mt=0;mt<2;mt++)
        #pragma unroll
        for (int j=0;j<4;j++)
            #pragma unroll
            for (int i=0;i<4;i++) c[mt][j][i]=0.f;
    const float* bbase = Bpack + (size_t)jbase*64 + lane*2;
    #pragma unroll 4
    for (int kc=0; kc<NKC; kc++){
        const float* a0p = sA + (kc*8+tig)*LDT;
        const float* a1p = a0p + 4*LDT;
        uint32_t a[2][4];
        a[0][0]=__float_as_uint(a0p[qid]);
        a[0][1]=__float_as_uint(a0p[qid+8]);
        a[0][2]=__float_as_uint(a1p[qid]);
        a[0][3]=__float_as_uint(a1p[qid+8]);
        a[1][0]=__float_as_uint(a0p[qid+16]);
        a[1][1]=__float_as_uint(a0p[qid+24]);
        a[1][2]=__float_as_uint(a1p[qid+16]);
        a[1][3]=__float_as_uint(a1p[qid+24]);
        const float* bp = bbase + (size_t)kc*ntiles*64;
        #pragma unroll
        for (int j=0;j<4;j++){
            float2 bv = *reinterpret_cast<const float2*>(bp + (size_t)j*64);
            uint32_t b0=__float_as_uint(bv.x), b1=__float_as_uint(bv.y);
            mma8(c[0][j], a[0], b0, b1);
            mma8(c[1][j], a[1], b0, b1);
        }
    }
}

// ============================================================
// Head precompute: out[node][128] = src[node] @ Whead + bias
// ============================================================
__global__ void k_head(const float* __restrict__ src,
                       const float* __restrict__ Bpack,
                       const float* __restrict__ bias,
                       float* __restrict__ out)
{
    __shared__ float sA[HH*LDT];
    int rb = blockIdx.x;
    int t = threadIdx.x;
    int lane=t&31, warp=t>>5;

    int m = t>>2; int k0 = (t&3)*32;
    const float* s = src + ((size_t)(rb*32+m))*HH + k0;
    #pragma unroll
    for (int i=0;i<8;i++){
        float4 v = *reinterpret_cast<const float4*>(s + i*4);
        sA[(k0+i*4+0)*LDT+m]=tf32r(v.x);
        sA[(k0+i*4+1)*LDT+m]=tf32r(v.y);
        sA[(k0+i*4+2)*LDT+m]=tf32r(v.z);
        sA[(k0+i*4+3)*LDT+m]=tf32r(v.w);
    }
    __syncthreads();

    float c[2][4][4];
    mma_core<16>(Bpack, 16, warp*4, sA, c, lane);

    int qid=lane>>2, tig=lane&3;
    #pragma unroll
    for (int j=0;j<4;j++){
        int n = (warp*4+j)*8 + tig*2;
        float b0=bias[n], b1=bias[n+1];
        #pragma unroll
        for (int mt=0;mt<2;mt++){
            int r = rb*32 + mt*16 + qid;
            out[(size_t)r*HH + n]       = c[mt][j][0]+b0;
            out[(size_t)r*HH + n+1]     = c[mt][j][1]+b1;
            out[(size_t)(r+8)*HH + n]   = c[mt][j][2]+b0;
            out[(size_t)(r+8)*HH + n+1] = c[mt][j][3]+b1;
        }
    }
}

// ============================================================
// Message-kernel shared memory (2 nodes, M=64), ~64.6KB
// A0 columns map to original mi k = 128 + col (head block removed).
// ============================================================
struct __align__(16) MsgSmem2 {
    __nv_bfloat16 A0[MROWS*LDK];  // mi[k>=128] (bf16) -> h2 (bf16 LDH) -> msgF (fp32 LDF)
    __nv_bfloat16 A1[MROWS*LDH];  // h1
    float hv[NODES*HH];
    float uu[NODES*HH];
    float Rr[NODES*9], tvv[NODES*3], pll[NODES*24], pgg[NODES*24];
    float mask[MROWS];
    int   nbidx[MROWS];
    float red[16];
};

// ============================================================
// bf16 MMA core: warp (mq,nq) computes C[32 x 32] slice of [64x128].
// ============================================================
template<int NKC>
__device__ __forceinline__ void mma_bf16(const uint32_t* __restrict__ Bp, int nq,
                                         uint32_t aAddr, int ldkB, int mq, int lane,
                                         float c[2][4][4])
{
    #pragma unroll
    for (int mt=0;mt<2;mt++)
        #pragma unroll
        for (int j=0;j<4;j++)
            #pragma unroll
            for (int i=0;i<4;i++) c[mt][j][i]=0.f;

    uint32_t arow = aAddr + (uint32_t)((mq*32 + (lane&15))*ldkB) + ((lane>>4)&1)*16;
    for (int kc=0; kc<NKC; kc++){
        uint32_t a[2][4];
        #pragma unroll
        for (int mt=0;mt<2;mt++) ldsm4(a[mt], arow + mt*16*ldkB + kc*32);
        const uint32_t* bp = Bp + ((size_t)(kc*16 + nq*4)*32 + lane)*2;
        uint32_t b[4][2];
        #pragma unroll
        for (int j=0;j<4;j++){
            uint2 u = *reinterpret_cast<const uint2*>(bp + j*64);
            b[j][0]=u.x; b[j][1]=u.y;
        }
        #pragma unroll
        for (int mt=0;mt<2;mt++)
            #pragma unroll
            for (int j=0;j<4;j++) mma16816(c[mt][j], a[mt], b[j]);
    }
}

__device__ __forceinline__ void epi_gelu_u(float c[2][4][4], const float* __restrict__ uu,
                                           __nv_bfloat16* dst, int lane, int mq, int nq)
{
    int qid=lane>>2, tig=lane&3;
    const float* uv = uu + mq*HH;
    #pragma unroll
    for (int mt=0;mt<2;mt++){
        int r0 = mq*32 + mt*16 + qid;
        #pragma unroll
        for (int j=0;j<4;j++){
            int n0 = nq*32 + j*8 + tig*2;
            float b0=uv[n0], b1=uv[n0+1];
            *reinterpret_cast<uint32_t*>(dst + (size_t)r0*LDH + n0) =
                bf16x2(gelu_f(c[mt][j][0]+b0), gelu_f(c[mt][j][1]+b1));
            *reinterpret_cast<uint32_t*>(dst + (size_t)(r0+8)*LDH + n0) =
                bf16x2(gelu_f(c[mt][j][2]+b0), gelu_f(c[mt][j][3]+b1));
        }
    }
}

__device__ __forceinline__ void epi_gelu_bf16(float c[2][4][4], const float* __restrict__ bias,
                                              __nv_bfloat16* dst, int lane, int mq, int nq)
{
    int qid=lane>>2, tig=lane&3;
    #pragma unroll
    for (int mt=0;mt<2;mt++){
        int r0 = mq*32 + mt*16 + qid;
        #pragma unroll
        for (int j=0;j<4;j++){
            int n0 = nq*32 + j*8 + tig*2;
            float b0=bias[n0], b1=bias[n0+1];
            *reinterpret_cast<uint32_t*>(dst + (size_t)r0*LDH + n0) =
                bf16x2(gelu_f(c[mt][j][0]+b0), gelu_f(c[mt][j][1]+b1));
            *reinterpret_cast<uint32_t*>(dst + (size_t)(r0+8)*LDH + n0) =
                bf16x2(gelu_f(c[mt][j][2]+b0), gelu_f(c[mt][j][3]+b1));
        }
    }
}

__device__ __forceinline__ void epi_float(float c[2][4][4], const float* __restrict__ bias,
                                          float* msgF, int lane, int mq, int nq)
{
    int qid=lane>>2, tig=lane&3;
    #pragma unroll
    for (int mt=0;mt<2;mt++){
        int r0 = mq*32 + mt*16 + qid;
        #pragma unroll
        for (int j=0;j<4;j++){
            int n0 = nq*32 + j*8 + tig*2;
            float b0=bias[n0], b1=bias[n0+1];
            msgF[(size_t)r0*LDF + n0]       = c[mt][j][0]+b0;
            msgF[(size_t)r0*LDF + n0+1]     = c[mt][j][1]+b1;
            msgF[(size_t)(r0+8)*LDF + n0]   = c[mt][j][2]+b0;
            msgF[(size_t)(r0+8)*LDF + n0+1] = c[mt][j][3]+b1;
        }
    }
}

// Build mi columns: hE at 0, nb_hV at 128, geometry at 256..327, pad 328..343.
__device__ __forceinline__ void build_mi2(MsgSmem2& S, int bl0, int b, int t,
                                          const float* __restrict__ hVsrc,
                                          const float* __restrict__ hE)
{
    int w=t>>5, lane=t&31;
    #pragma unroll
    for (int i=0;i<8;i++){
        int gr = w*8+i;
        size_t e = (size_t)bl0*KK + gr;
        int nb = S.nbidx[gr];
        const float4* he4 = reinterpret_cast<const float4*>(hE + e*HH);
        const float4* nb4 = reinterpret_cast<const float4*>(hVsrc + ((size_t)b*LL + nb)*HH);
        __nv_bfloat16* row = S.A0 + (size_t)gr*LDK;
        float4 x;
        x = he4[lane];
        *reinterpret_cast<uint2*>(row + lane*4)      = make_uint2(bf16x2(x.x,x.y), bf16x2(x.z,x.w));
        x = nb4[lane];
        *reinterpret_cast<uint2*>(row + HH + lane*4) = make_uint2(bf16x2(x.x,x.y), bf16x2(x.z,x.w));
        if (lane < 8) reinterpret_cast<uint32_t*>(row + 328)[lane] = 0u;  // pad 328..343
    }
    if (t < MROWS){
        int gr=t, v=gr>>5;
        const float* R  = S.Rr  + v*9;
        const float* tv = S.tvv + v*3;
        const float* pl = S.pll + v*24;
        const float* pg = S.pgg + v*24;
        int nb = S.nbidx[gr];
        const float* npg = g_pg + ((size_t)b*LL + nb)*24;
        __nv_bfloat16* q = S.A0 + (size_t)gr*LDK + 2*HH;
        #pragma unroll
        for (int p=0;p<PP;p++){
            float plx=pl[p*3], ply=pl[p*3+1], plz=pl[p*3+2];
            q[p*3+0]=__float2bfloat16_rn(plx);
            q[p*3+1]=__float2bfloat16_rn(ply);
            q[p*3+2]=__float2bfloat16_rn(plz);
            q[24+p] =__float2bfloat16_rn(sqrtf(plx*plx+ply*ply+plz*plz+1e-8f));
            float dx=npg[p*3+0]-tv[0], dy=npg[p*3+1]-tv[1], dz=npg[p*3+2]-tv[2];
            float nlx = R[0]*dx + R[3]*dy + R[6]*dz;
            float nly = R[1]*dx + R[4]*dy + R[7]*dz;
            float nlz = R[2]*dx + R[5]*dy + R[8]*dz;
            q[32+p*3+0]=__float2bfloat16_rn(nlx);
            q[32+p*3+1]=__float2bfloat16_rn(nly);
            q[32+p*3+2]=__float2bfloat16_rn(nlz);
            q[56+p]=__float2bfloat16_rn(sqrtf(nlx*nlx+nly*nly+nlz*nlz+1e-8f));
            float gx=pg[p*3+0]-npg[p*3+0];
            float gy=pg[p*3+1]-npg[p*3+1];
            float gz=pg[p*3+2]-npg[p*3+2];
            q[64+p]=__float2bfloat16_rn(sqrtf(gx*gx+gy*gy+gz*gz+1e-8f));
        }
    }
}

// Three chained GEMMs. Leaves fp32 message in (float*)S.A0 [64][LDF].
__device__ __forceinline__ void run_msg_gemms(MsgSmem2& S,
    const uint32_t* __restrict__ B1,
    const uint32_t* __restrict__ B2, const float* __restrict__ b2,
    const uint32_t* __restrict__ B3, const float* __restrict__ b3, int t)
{
    int lane=t&31, w=t>>5, mq=w&1, nq=w>>1;
    uint32_t a0 = (uint32_t)__cvta_generic_to_shared(S.A0);
    uint32_t a1 = (uint32_t)__cvta_generic_to_shared(S.A1);
    float c[2][4][4];

    // GEMM1 over k=128..463 of the original mi (kc 8..28 of packed W).
    mma_bf16<21>(B1 + (size_t)8*16*64, nq, a0, LDK*2, mq, lane, c);
    epi_gelu_u(c, S.uu, S.A1, lane, mq, nq);
    __syncthreads();

    mma_bf16<8>(B2, nq, a1, LDH*2, mq, lane, c);
    epi_gelu_bf16(c, b2, S.A0, lane, mq, nq);     // h2 reuses A0 (LDH layout)
    __syncthreads();

    mma_bf16<8>(B3, nq, a0, LDH*2, mq, lane, c);
    __syncthreads();                              // all h2 reads done before fp32 overwrite
    epi_float(c, b3, reinterpret_cast<float*>(S.A0), lane, mq, nq);
    __syncthreads();
}

__device__ __forceinline__ void load_node_params(MsgSmem2& S, int bl0, int t,
                                                 const float* __restrict__ hVsrc,
                                                 const int* __restrict__ Eidx,
                                                 const float* __restrict__ maskA)
{
    if (t < NODES*HH){
        S.hv[t] = hVsrc[(size_t)bl0*HH + t];
        S.uu[t] = g_u[(size_t)bl0*HH + t];
    }
    if (t < MROWS){
        S.nbidx[t] = Eidx[(size_t)bl0*KK + t];
        S.mask[t]  = maskA ? maskA[(size_t)bl0*KK + t] : 1.0f;
    }
    if (t < NODES*9)  S.Rr[t]  = g_R[bl0*9 + t];
    if (t < NODES*3)  S.tvv[t] = g_t[bl0*3 + t];
    if (t < NODES*24){ S.pll[t] = g_pl[bl0*24 + t]; S.pgg[t] = g_pg[bl0*24 + t]; }
}

// ============================================================
// Node message kernel
// ============================================================
__global__ __launch_bounds__(256,3) void k_node(
    const float* __restrict__ hV, const float* __restrict__ hE,
    const int* __restrict__ Eidx, const float* __restrict__ maskA,
    const float* __restrict__ b2, const float* __restrict__ b3,
    const float* __restrict__ g1, const float* __restrict__ be1)
{
    extern __shared__ char smem_raw[];
    MsgSmem2& S = *reinterpret_cast<MsgSmem2*>(smem_raw);
    int bl0 = blockIdx.x * NODES;
    int b   = bl0 / LL;
    int t   = threadIdx.x;

    load_node_params(S, bl0, t, hV, Eidx, maskA);
    __syncthreads();
    build_mi2(S, bl0, b, t, hV, hE);
    __syncthreads();
    run_msg_gemms(S, g_W1pb, g_W2pb, b2, g_W3pb, b3, t);

    const float* msgF = reinterpret_cast<const float*>(S.A0);
    int f = t&127, v = t>>7, lane = t&31, widx = (t>>5)&3;
    float acc = 0.f;
    #pragma unroll
    for (int r=0;r<32;r++) acc += S.mask[v*32+r] * msgF[(size_t)(v*32+r)*LDF + f];
    float x = S.hv[v*HH + f] + acc*(1.0f/KK);
    float s=x, q=x*x;
    #pragma unroll
    for (int o=16;o>0;o>>=1){
        s += __shfl_down_sync(0xffffffffu, s, o);
        q += __shfl_down_sync(0xffffffffu, q, o);
    }
    if (lane==0){ S.red[v*4+widx]=s; S.red[8+v*4+widx]=q; }
    __syncthreads();
    float ts = S.red[v*4]+S.red[v*4+1]+S.red[v*4+2]+S.red[v*4+3];
    float tq = S.red[8+v*4]+S.red[8+v*4+1]+S.red[8+v*4+2]+S.red[8+v*4+3];
    float mu = ts*(1.0f/HH);
    float rstd = rsqrtf(tq*(1.0f/HH)-mu*mu+1e-5f);
    g_xn[(size_t)(bl0+v)*HH + f] = (x-mu)*rstd*g1[f] + be1[f];
}

// ============================================================
// Edge message kernel
// ============================================================
__global__ __launch_bounds__(256,3) void k_edge(
    const float* __restrict__ hE, const int* __restrict__ Eidx,
    const float* __restrict__ b2, const float* __restrict__ b3,
    const float* __restrict__ g3, const float* __restrict__ be3,
    float* __restrict__ out_hE)
{
    extern __shared__ char smem_raw[];
    MsgSmem2& S = *reinterpret_cast<MsgSmem2*>(smem_raw);
    int bl0 = blockIdx.x * NODES;
    int b   = bl0 / LL;
    int t   = threadIdx.x;

    load_node_params(S, bl0, t, g_hV, Eidx, (const float*)0);
    __syncthreads();
    build_mi2(S, bl0, b, t, g_hV, hE);
    __syncthreads();
    run_msg_gemms(S, g_W11pb, g_W12pb, b2, g_W13pb, b3, t);

    const float* msgF = reinterpret_cast<const float*>(S.A0);
    int w = t>>5, lane = t&31;
    #pragma unroll
    for (int i=0;i<8;i++){
        int gr = w*8+i;
        size_t e = (size_t)bl0*KK + gr;
        float4 hv_ = reinterpret_cast<const float4*>(hE + e*HH)[lane];
        float4 mv  = reinterpret_cast<const float4*>(msgF + (size_t)gr*LDF)[lane];
        float x0 = mv.x+hv_.x, x1 = mv.y+hv_.y, x2 = mv.z+hv_.z, x3 = mv.w+hv_.w;
        float s = x0+x1+x2+x3;
        float q = x0*x0+x1*x1+x2*x2+x3*x3;
        #pragma unroll
        for (int o=16;o>0;o>>=1){
            s += __shfl_xor_sync(0xffffffffu, s, o);
            q += __shfl_xor_sync(0xffffffffu, q, o);
        }
        float mu = s*(1.0f/HH);
        float rstd = rsqrtf(q*(1.0f/HH)-mu*mu+1e-5f);
        int f0 = lane*4;
        float4 gg = *reinterpret_cast<const float4*>(g3 + f0);
        float4 bb = *reinterpret_cast<const float4*>(be3 + f0);
        float4 o4;
        o4.x = (x0-mu)*rstd*gg.x + bb.x;
        o4.y = (x1-mu)*rstd*gg.y + bb.y;
        o4.z = (x2-mu)*rstd*gg.z + bb.z;
        o4.w = (x3-mu)*rstd*gg.w + bb.w;
        *reinterpret_cast<float4*>(out_hE + e*HH + f0) = o4;
    }
}

// ============================================================
// tf32 FFN
// ============================================================
__global__ void k_ffn1(const float* __restrict__ bdin)
{
    __shared__ float sA[HH*LDT];
    int rb = blockIdx.x, cb = blockIdx.y;
    int t = threadIdx.x;
    int lane=t&31, warp=t>>5;

    int m = t>>2; int k0 = (t&3)*32;
    const float* src = g_xn + ((size_t)(rb*32+m))*HH + k0;
    #pragma unroll
    for (int i=0;i<8;i++){
        float4 v = *reinterpret_cast<const float4*>(src + i*4);
        sA[(k0+i*4+0)*LDT+m]=tf32r(v.x);
        sA[(k0+i*4+1)*LDT+m]=tf32r(v.y);
        sA[(k0+i*4+2)*LDT+m]=tf32r(v.z);
        sA[(k0+i*4+3)*LDT+m]=tf32r(v.w);
    }
    __syncthreads();

    float c[2][4][4];
    mma_core<16>(g_Wdinp, 64, cb*16 + warp*4, sA, c, lane);

    int qid=lane>>2, tig=lane&3;
    #pragma unroll
    for (int j=0;j<4;j++){
        int n = (cb*16+warp*4+j)*8 + tig*2;
        float b0=bdin[n], b1=bdin[n+1];
        #pragma unroll
        for (int mt=0;mt<2;mt++){
            int r = rb*32 + mt*16 + qid;
            g_ff[(size_t)r*512 + n]       = gelu_f(c[mt][j][0]+b0);
            g_ff[(size_t)r*512 + n+1]     = gelu_f(c[mt][j][1]+b1);
            g_ff[(size_t)(r+8)*512 + n]   = gelu_f(c[mt][j][2]+b0);
            g_ff[(size_t)(r+8)*512 + n+1] = gelu_f(c[mt][j][3]+b1);
        }
    }
}

struct FfnSmem {
    float sA[4*HH*LDT];
    float mu[32], rstd[32];
};

__global__ void k_ffn2(const float* __restrict__ bdout,
                       const float* __restrict__ g2, const float* __restrict__ be2,
                       const float* __restrict__ maskV,
                       float* __restrict__ out_hV)
{
    extern __shared__ char smem_raw[];
    FfnSmem& S = *reinterpret_cast<FfnSmem*>(smem_raw);
    int rb = blockIdx.x;
    int t = threadIdx.x;
    int lane=t&31, warp=t>>5;

    int m = t>>2; int k0 = (t&3)*128;
    const float* src = g_ff + ((size_t)(rb*32+m))*512 + k0;
    #pragma unroll
    for (int i=0;i<32;i++){
        float4 v = *reinterpret_cast<const float4*>(src + i*4);
        S.sA[(k0+i*4+0)*LDT+m]=tf32r(v.x);
        S.sA[(k0+i*4+1)*LDT+m]=tf32r(v.y);
        S.sA[(k0+i*4+2)*LDT+m]=tf32r(v.z);
        S.sA[(k0+i*4+3)*LDT+m]=tf32r(v.w);
    }
    __syncthreads();

    float c[2][4][4];
    mma_core<64>(g_Wdoutp, 16, warp*4, S.sA, c, lane);
    __syncthreads();

    int qid=lane>>2, tig=lane&3;
    #pragma unroll
    for (int j=0;j<4;j++){
        int n = (warp*4+j)*8 + tig*2;
        float b0=bdout[n], b1=bdout[n+1];
        #pragma unroll
        for (int mt=0;mt<2;mt++){
            int r = mt*16 + qid;
            size_t node0 = (size_t)(rb*32 + r);
            size_t node1 = node0 + 8;
            S.sA[n*LDT + r]       = c[mt][j][0]+b0 + g_xn[node0*HH + n];
            S.sA[(n+1)*LDT + r]   = c[mt][j][1]+b1 + g_xn[node0*HH + n+1];
            S.sA[n*LDT + r+8]     = c[mt][j][2]+b0 + g_xn[node1*HH + n];
            S.sA[(n+1)*LDT + r+8] = c[mt][j][3]+b1 + g_xn[node1*HH + n+1];
        }
    }
    __syncthreads();

    if (t < 32){
        float s=0.f, q=0.f;
        #pragma unroll 4
        for (int cf=0;cf<HH;cf++){ float v=S.sA[cf*LDT+t]; s+=v; q+=v*v; }
        float mu = s*(1.f/HH);
        S.mu[t]=mu;
        S.rstd[t]=rsqrtf(q*(1.f/HH)-mu*mu+1e-5f);
    }
    __syncthreads();

    float gg=g2[t], bb=be2[t];
    for (int r=0;r<32;r++){
        size_t node = (size_t)(rb*32+r);
        float y = (S.sA[t*LDT+r]-S.mu[r])*S.rstd[r]*gg+bb;
        y *= maskV[node];
        g_hV[node*HH+t]=y;
        out_hV[node*HH+t]=y;
    }
}

// ============================================================
extern "C" void kernel_launch(void* const* d_in, const int* in_sizes, int n_in,
                              void* d_out, int out_size)
{
    const float* hV    =(const float*)d_in[0];
    const float* hE    =(const float*)d_in[1];
    const int*   Eidx  =(const int*)  d_in[2];
    const float* X     =(const float*)d_in[3];
    const float* maskV =(const float*)d_in[4];
    const float* maskA =(const float*)d_in[5];
    const float* Wp_node=(const float*)d_in[6];  const float* bp_node=(const float*)d_in[7];
    const float* Wp_edge=(const float*)d_in[8];  const float* bp_edge=(const float*)d_in[9];
    const float* W1 =(const float*)d_in[10]; const float* b1 =(const float*)d_in[11];
    const float* W2 =(const float*)d_in[12]; const float* b2 =(const float*)d_in[13];
    const float* W3 =(const float*)d_in[14]; const float* b3 =(const float*)d_in[15];
    const float* W11=(const float*)d_in[16]; const float* b11=(const float*)d_in[17];
    const float* W12=(const float*)d_in[18]; const float* b12=(const float*)d_in[19];
    const float* W13=(const float*)d_in[20]; const float* b13=(const float*)d_in[21];
    const float* Wdin =(const float*)d_in[22]; const float* bdin =(const float*)d_in[23];
    const float* Wdout=(const float*)d_in[24]; const float* bdout=(const float*)d_in[25];
    const float* g1=(const float*)d_in[26]; const float* be1=(const float*)d_in[27];
    const float* g2=(const float*)d_in[28]; const float* be2=(const float*)d_in[29];
    const float* g3=(const float*)d_in[30]; const float* be3=(const float*)d_in[31];

    float* out_hV = (float*)d_out;
    float* out_hE = out_hV + (size_t)NB*HH;

    int smem_msg = (int)sizeof(MsgSmem2);
    int smem_ffn = (int)sizeof(FfnSmem);
    cudaFuncSetAttribute(k_node, cudaFuncAttributeMaxDynamicSharedMemorySize, smem_msg);
    cudaFuncSetAttribute(k_edge, cudaFuncAttributeMaxDynamicSharedMemorySize, smem_msg);
    cudaFuncSetAttribute(k_ffn2, cudaFuncAttributeMaxDynamicSharedMemorySize, smem_ffn);

    uint32_t *p1,*p2,*p3,*p11,*p12,*p13;
    float *pdin,*pdout,*phv,*pw1h,*pw11h,*pu;
    cudaGetSymbolAddress((void**)&p1,   g_W1pb);
    cudaGetSymbolAddress((void**)&p2,   g_W2pb);
    cudaGetSymbolAddress((void**)&p3,   g_W3pb);
    cudaGetSymbolAddress((void**)&p11,  g_W11pb);
    cudaGetSymbolAddress((void**)&p12,  g_W12pb);
    cudaGetSymbolAddress((void**)&p13,  g_W13pb);
    cudaGetSymbolAddress((void**)&pdin, g_Wdinp);
    cudaGetSymbolAddress((void**)&pdout,g_Wdoutp);
    cudaGetSymbolAddress((void**)&phv,  g_hV);
    cudaGetSymbolAddress((void**)&pw1h, g_W1hp);
    cudaGetSymbolAddress((void**)&pw11h,g_W11hp);
    cudaGetSymbolAddress((void**)&pu,   g_u);

    k_packb<<<dim3(29,16,6),32>>>(W1,W2,W3,W11,W12,W13,p1,p2,p3,p11,p12,p13);
    dim3 pb(32,16);
    k_pack<<<dim3(16,4),pb>>>(Wdin,  pdin, 512);
    k_pack<<<dim3(64,1),pb>>>(Wdout, pdout,128);
    k_pack<<<dim3(16,1),pb>>>(W1,  pw1h, 128);
    k_pack<<<dim3(16,1),pb>>>(W11, pw11h,128);

    k_frames<<<NB/128,128>>>(X);
    k_projpg<<<NB/8,dim3(24,8)>>>(hV, Wp_node, bp_node);
    k_head<<<NB/32,128>>>(hV, pw1h, b1, pu);
    k_node<<<NB/NODES,256,smem_msg>>>(hV,hE,Eidx,maskA,b2,b3,g1,be1);
    k_ffn1<<<dim3(128,4),128>>>(bdin);
    k_ffn2<<<128,128,smem_ffn>>>(bdout,g2,be2,maskV,out_hV);
    k_projpg<<<NB/8,dim3(24,8)>>>(phv, Wp_edge, bp_edge);
    k_head<<<NB/32,128>>>(phv, pw11h, b11, pu);
    k_edge<<<NB/NODES,256,smem_msg>>>(hE,Eidx,b12,b13,g3,be3,out_hE);
}

// round 8
// speedup vs baseline: 9.3579x; 1.0972x over previous
#include <cuda_runtime.h>
#include <cuda_bf16.h>
#include <math.h>
#include <stdint.h>

#define BB 2
#define LL 2048
#define KK 32
#define HH 128
#define PP 8
#define MSG 456
#define LDT 40        /* tf32 FFN tiles */
#define NB (BB*LL)    /* 4096 nodes */

#define NODES 2       /* nodes per message CTA (2 independent halves) */
#define MROWS (NODES*KK)   /* 64 */
#define LDK 344       /* bf16 elems per mi row (688B stride, conflict-free) */
#define LDH 136       /* bf16 elems per h row (272B stride) */
#define LDF 132       /* fp32 msg row */
#define HALFREG (32*LDK)   /* bf16 elems per half's A0 region */

// -------- scratch --------
__device__ float g_R [NB*9];
__device__ float g_t [NB*3];
__device__ float g_pl[NB*24];
__device__ float g_pg[NB*24];
__device__ float g_hV[NB*HH];
__device__ float g_xn[NB*HH];
__device__ float g_u [NB*HH];
__device__ float g_ff[(size_t)NB*4*HH];

// tf32 packed weights
__device__ float g_Wdinp [16*64*64];
__device__ float g_Wdoutp[64*16*64];
__device__ float g_W1hp  [16*16*64];
__device__ float g_W11hp [16*16*64];

// bf16 packed message weights
__device__ uint32_t g_W1pb [29*16*64];
__device__ uint32_t g_W2pb [ 8*16*64];
__device__ uint32_t g_W3pb [ 8*16*64];
__device__ uint32_t g_W11pb[29*16*64];
__device__ uint32_t g_W12pb[ 8*16*64];
__device__ uint32_t g_W13pb[ 8*16*64];

__device__ __forceinline__ float gelu_f(float x){
    return 0.5f*x*(1.0f+erff(x*0.70710678118654752440f));
}
__device__ __forceinline__ float tf32r(float x){
    uint32_t u; asm("cvt.rna.tf32.f32 %0, %1;" : "=r"(u) : "f"(x));
    return __uint_as_float(u);
}
__device__ __forceinline__ uint32_t bf16x2(float lo, float hi){
    __nv_bfloat162 h = __floats2bfloat162_rn(lo, hi);
    return *reinterpret_cast<uint32_t*>(&h);
}
__device__ __forceinline__ void bar_half(int half){
    asm volatile("bar.sync %0, 128;" :: "r"(1+half) : "memory");
}
__device__ __forceinline__ void mma8(float* c, const uint32_t* a, uint32_t b0, uint32_t b1){
    asm volatile("mma.sync.aligned.m16n8k8.row.col.f32.tf32.tf32.f32 "
        "{%0,%1,%2,%3},{%4,%5,%6,%7},{%8,%9},{%0,%1,%2,%3};"
        : "+f"(c[0]),"+f"(c[1]),"+f"(c[2]),"+f"(c[3])
        : "r"(a[0]),"r"(a[1]),"r"(a[2]),"r"(a[3]),"r"(b0),"r"(b1));
}
__device__ __forceinline__ void mma16816(float* c, const uint32_t* a, const uint32_t* b){
    asm volatile("mma.sync.aligned.m16n8k16.row.col.f32.bf16.bf16.f32 "
        "{%0,%1,%2,%3},{%4,%5,%6,%7},{%8,%9},{%0,%1,%2,%3};"
        : "+f"(c[0]),"+f"(c[1]),"+f"(c[2]),"+f"(c[3])
        : "r"(a[0]),"r"(a[1]),"r"(a[2]),"r"(a[3]),"r"(b[0]),"r"(b[1]));
}
__device__ __forceinline__ void ldsm4(uint32_t* r, uint32_t addr){
    asm volatile("ldmatrix.sync.aligned.m8n8.x4.shared.b16 {%0,%1,%2,%3}, [%4];"
        : "=r"(r[0]),"=r"(r[1]),"=r"(r[2]),"=r"(r[3]) : "r"(addr));
}

// ============================================================
// tf32 weight pack
// ============================================================
__global__ void k_pack(const float* __restrict__ W, float* __restrict__ out, int N)
{
    int ntiles = N >> 3;
    int kc   = blockIdx.x;
    int j    = blockIdx.y*16 + threadIdx.y;
    int lane = threadIdx.x;
    int row  = kc*8 + (lane&3);
    int col  = j*8 + (lane>>2);
    float b0 = W[row*N + col];
    float b1 = W[(row+4)*N + col];
    float* o = out + (((size_t)kc*ntiles + j)*32 + lane)*2;
    o[0] = tf32r(b0); o[1] = tf32r(b1);
}

// ============================================================
// bf16 weight pack. grid(29,16,6) block 32.
// ============================================================
__global__ void k_packb(const float* __restrict__ W1,const float* __restrict__ W2,
                        const float* __restrict__ W3,const float* __restrict__ W11,
                        const float* __restrict__ W12,const float* __restrict__ W13,
                        uint32_t* o1,uint32_t* o2,uint32_t* o3,
                        uint32_t* o11,uint32_t* o12,uint32_t* o13)
{
    int z = blockIdx.z;
    const float* src; uint32_t* dst; int Ktot;
    switch(z){
        case 0: src=W1;  dst=o1;  Ktot=MSG; break;
        case 1: src=W2;  dst=o2;  Ktot=HH;  break;
        case 2: src=W3;  dst=o3;  Ktot=HH;  break;
        case 3: src=W11; dst=o11; Ktot=MSG; break;
        case 4: src=W12; dst=o12; Ktot=HH;  break;
        default:src=W13; dst=o13; Ktot=HH;  break;
    }
    int kc = blockIdx.x;
    if (kc >= (Ktot+15)/16) return;
    int j = blockIdx.y, lane = threadIdx.x;
    int n = j*8 + (lane>>2);
    #pragma unroll
    for (int r=0;r<2;r++){
        int k = kc*16 + (lane&3)*2 + 8*r;
        float v0 = (k   < Ktot)? src[(size_t)k*HH + n]     : 0.f;
        float v1 = (k+1 < Ktot)? src[(size_t)(k+1)*HH + n] : 0.f;
        dst[(((size_t)kc*16 + j)*32 + lane)*2 + r] = bf16x2(v0, v1);
    }
}

// ============================================================
// Frames: 1 thread per node
// ============================================================
__global__ void k_frames(const float* __restrict__ X)
{
    int node = blockIdx.x*128 + threadIdx.x;
    if (node >= NB) return;
    const float* Xp = X + (size_t)node*12;
    float Nx=Xp[0],Ny=Xp[1],Nz=Xp[2];
    float Ax=Xp[3],Ay=Xp[4],Az=Xp[5];
    float Cx=Xp[6],Cy=Xp[7],Cz=Xp[8];
    float e0x=Ax-Nx, e0y=Ay-Ny, e0z=Az-Nz;
    float inv = 1.0f/sqrtf(e0x*e0x+e0y*e0y+e0z*e0z + 1e-8f);
    e0x*=inv; e0y*=inv; e0z*=inv;
    float e1x=Cx-Ax, e1y=Cy-Ay, e1z=Cz-Az;
    float d = e0x*e1x+e0y*e1y+e0z*e1z;
    e1x-=e0x*d; e1y-=e0y*d; e1z-=e0z*d;
    inv = 1.0f/sqrtf(e1x*e1x+e1y*e1y+e1z*e1z + 1e-8f);
    e1x*=inv; e1y*=inv; e1z*=inv;
    float e2x=e0y*e1z-e0z*e1y;
    float e2y=e0z*e1x-e0x*e1z;
    float e2z=e0x*e1y-e0y*e1x;
    float* R = g_R + node*9;
    R[0]=e0x; R[1]=e1x; R[2]=e2x;
    R[3]=e0y; R[4]=e1y; R[5]=e2y;
    R[6]=e0z; R[7]=e1z; R[8]=e2z;
    g_t[node*3+0]=Ax; g_t[node*3+1]=Ay; g_t[node*3+2]=Az;
}

// ============================================================
// Fused p_local projection + p_global. block (24,8), grid NB/8.
// ============================================================
__global__ void k_projpg(const float* __restrict__ hv,
                         const float* __restrict__ Wp,
                         const float* __restrict__ bp)
{
    __shared__ float spl[8][24];
    int node = blockIdx.x*8 + threadIdx.y;
    int j = threadIdx.x;
    const float* h = hv + (size_t)node*HH;
    float acc = bp[j];
    #pragma unroll 8
    for (int f=0; f<HH; f++) acc += h[f]*Wp[f*24+j];
    g_pl[(size_t)node*24 + j] = acc;
    spl[threadIdx.y][j] = acc;
    __syncthreads();
    int p = j/3, i = j%3;
    const float* R = g_R + node*9;
    const float* pl = &spl[threadIdx.y][p*3];
    g_pg[(size_t)node*24 + j] =
        g_t[node*3+i] + R[i*3+0]*pl[0] + R[i*3+1]*pl[1] + R[i*3+2]*pl[2];
}

// ============================================================
// tf32 MMA core (FFN + head precompute)
// ============================================================
template<int NKC>
__device__ __forceinline__ void mma_core(const float* __restrict__ Bpack, int ntiles, int jbase,
                                         const float* sA, float c[2][4][4], int lane)
{
    int qid = lane>>2, tig = lane&3;
    #pragma unroll
    for (int mt=0;mt<2;mt++)
        #pragma unroll
        for (int j=0;j<4;j++)
            #pragma unroll
            for (int i=0;i<4;i++) c[mt][j][i]=0.f;
    const float* bbase = Bpack + (size_t)jbase*64 + lane*2;
    #pragma unroll 4
    for (int kc=0; kc<NKC; kc++){
        const float* a0p = sA + (kc*8+tig)*LDT;
        const float* a1p = a0p + 4*LDT;
        uint32_t a[2][4];
        a[0][0]=__float_as_uint(a0p[qid]);
        a[0][1]=__float_as_uint(a0p[qid+8]);
        a[0][2]=__float_as_uint(a1p[qid]);
        a[0][3]=__float_as_uint(a1p[qid+8]);
        a[1][0]=__float_as_uint(a0p[qid+16]);
        a[1][1]=__float_as_uint(a0p[qid+24]);
        a[1][2]=__float_as_uint(a1p[qid+16]);
        a[1][3]=__float_as_uint(a1p[qid+24]);
        const float* bp = bbase + (size_t)kc*ntiles*64;
        #pragma unroll
        for (int j=0;j<4;j++){
            float2 bv = *reinterpret_cast<const float2*>(bp + (size_t)j*64);
            uint32_t b0=__float_as_uint(bv.x), b1=__float_as_uint(bv.y);
            mma8(c[0][j], a[0], b0, b1);
            mma8(c[1][j], a[1], b0, b1);
        }
    }
}

// ============================================================
// Head precompute: out[node][128] = src[node] @ Whead + bias
// ============================================================
__global__ void k_head(const float* __restrict__ src,
                       const float* __restrict__ Bpack,
                       const float* __restrict__ bias,
                       float* __restrict__ out)
{
    __shared__ float sA[HH*LDT];
    int rb = blockIdx.x;
    int t = threadIdx.x;
    int lane=t&31, warp=t>>5;

    int m = t>>2; int k0 = (t&3)*32;
    const float* s = src + ((size_t)(rb*32+m))*HH + k0;
    #pragma unroll
    for (int i=0;i<8;i++){
        float4 v = *reinterpret_cast<const float4*>(s + i*4);
        sA[(k0+i*4+0)*LDT+m]=tf32r(v.x);
        sA[(k0+i*4+1)*LDT+m]=tf32r(v.y);
        sA[(k0+i*4+2)*LDT+m]=tf32r(v.z);
        sA[(k0+i*4+3)*LDT+m]=tf32r(v.w);
    }
    __syncthreads();

    float c[2][4][4];
    mma_core<16>(Bpack, 16, warp*4, sA, c, lane);

    int qid=lane>>2, tig=lane&3;
    #pragma unroll
    for (int j=0;j<4;j++){
        int n = (warp*4+j)*8 + tig*2;
        float b0=bias[n], b1=bias[n+1];
        #pragma unroll
        for (int mt=0;mt<2;mt++){
            int r = rb*32 + mt*16 + qid;
            out[(size_t)r*HH + n]       = c[mt][j][0]+b0;
            out[(size_t)r*HH + n+1]     = c[mt][j][1]+b1;
            out[(size_t)(r+8)*HH + n]   = c[mt][j][2]+b0;
            out[(size_t)(r+8)*HH + n+1] = c[mt][j][3]+b1;
        }
    }
}

// ============================================================
// Message-kernel shared memory (2 independent halves, M=32 each)
// Each half owns A0 region [half*HALFREG, +HALFREG) for mi -> h2 -> msgF,
// and A1 rows [half*32, +32) for h1. No cross-half sharing.
// ============================================================
struct __align__(16) MsgSmem2 {
    __nv_bfloat16 A0[MROWS*LDK];
    __nv_bfloat16 A1[MROWS*LDH];
    float hv[NODES*HH];
    float uu[NODES*HH];
    float Rr[NODES*9], tvv[NODES*3], pll[NODES*24], pgg[NODES*24];
    float mask[MROWS];
    int   nbidx[MROWS];
    float red[16];
};

// ============================================================
// bf16 MMA core: warp computes C[32 x 32] slice. mq selects A row block.
// ============================================================
template<int NKC>
__device__ __forceinline__ void mma_bf16(const uint32_t* __restrict__ Bp, int nq,
                                         uint32_t aAddr, int ldkB, int mq, int lane,
                                         float c[2][4][4])
{
    #pragma unroll
    for (int mt=0;mt<2;mt++)
        #pragma unroll
        for (int j=0;j<4;j++)
            #pragma unroll
            for (int i=0;i<4;i++) c[mt][j][i]=0.f;

    uint32_t arow = aAddr + (uint32_t)((mq*32 + (lane&15))*ldkB) + ((lane>>4)&1)*16;
    for (int kc=0; kc<NKC; kc++){
        uint32_t a[2][4];
        #pragma unroll
        for (int mt=0;mt<2;mt++) ldsm4(a[mt], arow + mt*16*ldkB + kc*32);
        const uint32_t* bp = Bp + ((size_t)(kc*16 + nq*4)*32 + lane)*2;
        uint32_t b[4][2];
        #pragma unroll
        for (int j=0;j<4;j++){
            uint2 u = *reinterpret_cast<const uint2*>(bp + j*64);
            b[j][0]=u.x; b[j][1]=u.y;
        }
        #pragma unroll
        for (int mt=0;mt<2;mt++)
            #pragma unroll
            for (int j=0;j<4;j++) mma16816(c[mt][j], a[mt], b[j]);
    }
}

// epilogues: r0 = mq*32 + local rows (mq=0 for per-half-offset buffers)
__device__ __forceinline__ void epi_gelu_u(float c[2][4][4], const float* __restrict__ uv,
                                           __nv_bfloat16* dst, int lane, int mq, int nq)
{
    int qid=lane>>2, tig=lane&3;
    #pragma unroll
    for (int mt=0;mt<2;mt++){
        int r0 = mq*32 + mt*16 + qid;
        #pragma unroll
        for (int j=0;j<4;j++){
            int n0 = nq*32 + j*8 + tig*2;
            float b0=uv[n0], b1=uv[n0+1];
            *reinterpret_cast<uint32_t*>(dst + (size_t)r0*LDH + n0) =
                bf16x2(gelu_f(c[mt][j][0]+b0), gelu_f(c[mt][j][1]+b1));
            *reinterpret_cast<uint32_t*>(dst + (size_t)(r0+8)*LDH + n0) =
                bf16x2(gelu_f(c[mt][j][2]+b0), gelu_f(c[mt][j][3]+b1));
        }
    }
}

__device__ __forceinline__ void epi_gelu_bf16(float c[2][4][4], const float* __restrict__ bias,
                                              __nv_bfloat16* dst, int lane, int mq, int nq)
{
    int qid=lane>>2, tig=lane&3;
    #pragma unroll
    for (int mt=0;mt<2;mt++){
        int r0 = mq*32 + mt*16 + qid;
        #pragma unroll
        for (int j=0;j<4;j++){
            int n0 = nq*32 + j*8 + tig*2;
            float b0=bias[n0], b1=bias[n0+1];
            *reinterpret_cast<uint32_t*>(dst + (size_t)r0*LDH + n0) =
                bf16x2(gelu_f(c[mt][j][0]+b0), gelu_f(c[mt][j][1]+b1));
            *reinterpret_cast<uint32_t*>(dst + (size_t)(r0+8)*LDH + n0) =
                bf16x2(gelu_f(c[mt][j][2]+b0), gelu_f(c[mt][j][3]+b1));
        }
    }
}

__device__ __forceinline__ void epi_float(float c[2][4][4], const float* __restrict__ bias,
                                          float* msgF, int lane, int nq)
{
    int qid=lane>>2, tig=lane&3;
    #pragma unroll
    for (int mt=0;mt<2;mt++){
        int r0 = mt*16 + qid;
        #pragma unroll
        for (int j=0;j<4;j++){
            int n0 = nq*32 + j*8 + tig*2;
            float b0=bias[n0], b1=bias[n0+1];
            msgF[(size_t)r0*LDF + n0]       = c[mt][j][0]+b0;
            msgF[(size_t)r0*LDF + n0+1]     = c[mt][j][1]+b1;
            msgF[(size_t)(r0+8)*LDF + n0]   = c[mt][j][2]+b0;
            msgF[(size_t)(r0+8)*LDF + n0+1] = c[mt][j][3]+b1;
        }
    }
}

// Per-half param load. ht in [0,128).
__device__ __forceinline__ void load_node_params(MsgSmem2& S, int bl0, int half, int ht,
                                                 const float* __restrict__ hVsrc,
                                                 const int* __restrict__ Eidx,
                                                 const float* __restrict__ maskA)
{
    int node = bl0 + half;
    S.hv[half*HH+ht] = hVsrc[(size_t)node*HH + ht];
    S.uu[half*HH+ht] = g_u[(size_t)node*HH + ht];
    if (ht < KK){
        S.nbidx[half*KK+ht] = Eidx[(size_t)node*KK + ht];
        S.mask[half*KK+ht]  = maskA ? maskA[(size_t)node*KK + ht] : 1.0f;
    }
    if (ht < 9)  S.Rr[half*9+ht]  = g_R[node*9 + ht];
    if (ht < 3)  S.tvv[half*3+ht] = g_t[node*3 + ht];
    if (ht < 24){ S.pll[half*24+ht] = g_pl[node*24 + ht]; S.pgg[half*24+ht] = g_pg[node*24 + ht]; }
}

// Per-half build. Warp hw (0..3) of half builds rows half*32+hw*8..+8.
// Geometry: all 128 threads of half, 2 points each.
__device__ __forceinline__ void build_mi2(MsgSmem2& S, int bl0, int b, int half, int hw,
                                          int lane, int ht,
                                          const float* __restrict__ hVsrc,
                                          const float* __restrict__ hE)
{
    #pragma unroll
    for (int i=0;i<8;i++){
        int gr = half*32 + hw*8 + i;
        size_t e = (size_t)(bl0+half)*KK + (hw*8+i);
        int nb = S.nbidx[gr];
        const float4* he4 = reinterpret_cast<const float4*>(hE + e*HH);
        const float4* nb4 = reinterpret_cast<const float4*>(hVsrc + ((size_t)b*LL + nb)*HH);
        __nv_bfloat16* row = S.A0 + (size_t)gr*LDK;
        float4 x;
        x = he4[lane];
        *reinterpret_cast<uint2*>(row + lane*4)      = make_uint2(bf16x2(x.x,x.y), bf16x2(x.z,x.w));
        x = nb4[lane];
        *reinterpret_cast<uint2*>(row + HH + lane*4) = make_uint2(bf16x2(x.x,x.y), bf16x2(x.z,x.w));
        if (lane < 8) reinterpret_cast<uint32_t*>(row + 328)[lane] = 0u;  // pad 328..343
    }
    // geometry: row r = ht>>2 (0..31), points (ht&3)*2, +1
    {
        int r = ht>>2;
        int gr = half*32 + r;
        int p0 = (ht&3)*2;
        const float* R  = S.Rr  + half*9;
        const float* tv = S.tvv + half*3;
        const float* pl = S.pll + half*24;
        const float* pg = S.pgg + half*24;
        int nb = S.nbidx[gr];
        const float* npg = g_pg + ((size_t)b*LL + nb)*24;
        __nv_bfloat16* q = S.A0 + (size_t)gr*LDK + 2*HH;
        #pragma unroll
        for (int p=p0;p<p0+2;p++){
            float plx=pl[p*3], ply=pl[p*3+1], plz=pl[p*3+2];
            q[p*3+0]=__float2bfloat16_rn(plx);
            q[p*3+1]=__float2bfloat16_rn(ply);
            q[p*3+2]=__float2bfloat16_rn(plz);
            q[24+p] =__float2bfloat16_rn(sqrtf(plx*plx+ply*ply+plz*plz+1e-8f));
            float dx=npg[p*3+0]-tv[0], dy=npg[p*3+1]-tv[1], dz=npg[p*3+2]-tv[2];
            float nlx = R[0]*dx + R[3]*dy + R[6]*dz;
            float nly = R[1]*dx + R[4]*dy + R[7]*dz;
            float nlz = R[2]*dx + R[5]*dy + R[8]*dz;
            q[32+p*3+0]=__float2bfloat16_rn(nlx);
            q[32+p*3+1]=__float2bfloat16_rn(nly);
            q[32+p*3+2]=__float2bfloat16_rn(nlz);
            q[56+p]=__float2bfloat16_rn(sqrtf(nlx*nlx+nly*nly+nlz*nlz+1e-8f));
            float gx=pg[p*3+0]-npg[p*3+0];
            float gy=pg[p*3+1]-npg[p*3+1];
            float gz=pg[p*3+2]-npg[p*3+2];
            q[64+p]=__float2bfloat16_rn(sqrtf(gx*gx+gy*gy+gz*gz+1e-8f));
        }
    }
}

// Three chained GEMMs per half with half-scoped barriers.
// Leaves fp32 message at (float*)(S.A0 + half*HALFREG), local rows [0,32).
__device__ __forceinline__ void run_msg_gemms(MsgSmem2& S,
    const uint32_t* __restrict__ B1,
    const uint32_t* __restrict__ B2, const float* __restrict__ b2,
    const uint32_t* __restrict__ B3, const float* __restrict__ b3,
    int half, int hw, int lane)
{
    uint32_t a0  = (uint32_t)__cvta_generic_to_shared(S.A0);
    uint32_t a0h = a0 + (uint32_t)(half*HALFREG*2);     // half's A0 region (bytes)
    uint32_t a1  = (uint32_t)__cvta_generic_to_shared(S.A1);
    __nv_bfloat16* h2base = S.A0 + (size_t)half*HALFREG;
    float* msgF = reinterpret_cast<float*>(h2base);
    float c[2][4][4];

    // GEMM1: mi (global rows via mq=half) -> h1 (A1 global rows)
    mma_bf16<21>(B1 + (size_t)8*16*64, hw, a0, LDK*2, half, lane, c);
    epi_gelu_u(c, S.uu + half*HH, S.A1, lane, half, hw);
    bar_half(half);

    // GEMM2: h1 (A1 global rows) -> h2 (own A0 region, local rows)
    mma_bf16<8>(B2, hw, a1, LDH*2, half, lane, c);
    epi_gelu_bf16(c, b2, h2base, lane, 0, hw);
    bar_half(half);

    // GEMM3: h2 (own region, local rows) -> msgF (own region, fp32)
    mma_bf16<8>(B3, hw, a0h, LDH*2, 0, lane, c);
    bar_half(half);                       // all h2 reads done before fp32 overwrite
    epi_float(c, b3, msgF, lane, hw);
    bar_half(half);
}

// ============================================================
// Node message kernel
// ============================================================
__global__ __launch_bounds__(256,3) void k_node(
    const float* __restrict__ hV, const float* __restrict__ hE,
    const int* __restrict__ Eidx, const float* __restrict__ maskA,
    const float* __restrict__ b2, const float* __restrict__ b3,
    const float* __restrict__ g1, const float* __restrict__ be1)
{
    extern __shared__ char smem_raw[];
    MsgSmem2& S = *reinterpret_cast<MsgSmem2*>(smem_raw);
    int bl0 = blockIdx.x * NODES;
    int b   = bl0 / LL;
    int t   = threadIdx.x;
    int w = t>>5, lane = t&31;
    int half = w & 1, hw = w >> 1;
    int ht = hw*32 + lane;

    load_node_params(S, bl0, half, ht, hV, Eidx, maskA);
    bar_half(half);
    build_mi2(S, bl0, b, half, hw, lane, ht, hV, hE);
    bar_half(half);
    run_msg_gemms(S, g_W1pb, g_W2pb, b2, g_W3pb, b3, half, hw, lane);

    const float* msgF = reinterpret_cast<const float*>(S.A0 + (size_t)half*HALFREG);
    int f = ht;
    float acc = 0.f;
    #pragma unroll
    for (int r=0;r<32;r++) acc += S.mask[half*32+r] * msgF[(size_t)r*LDF + f];
    float x = S.hv[half*HH + f] + acc*(1.0f/KK);
    float s=x, q=x*x;
    #pragma unroll
    for (int o=16;o>0;o>>=1){
        s += __shfl_down_sync(0xffffffffu, s, o);
        q += __shfl_down_sync(0xffffffffu, q, o);
    }
    if (lane==0){ S.red[half*4+hw]=s; S.red[8+half*4+hw]=q; }
    bar_half(half);
    float ts = S.red[half*4]+S.red[half*4+1]+S.red[half*4+2]+S.red[half*4+3];
    float tq = S.red[8+half*4]+S.red[8+half*4+1]+S.red[8+half*4+2]+S.red[8+half*4+3];
    float mu = ts*(1.0f/HH);
    float rstd = rsqrtf(tq*(1.0f/HH)-mu*mu+1e-5f);
    g_xn[(size_t)(bl0+half)*HH + f] = (x-mu)*rstd*g1[f] + be1[f];
}

// ============================================================
// Edge message kernel
// ============================================================
__global__ __launch_bounds__(256,3) void k_edge(
    const float* __restrict__ hE, const int* __restrict__ Eidx,
    const float* __restrict__ b2, const float* __restrict__ b3,
    const float* __restrict__ g3, const float* __restrict__ be3,
    float* __restrict__ out_hE)
{
    extern __shared__ char smem_raw[];
    MsgSmem2& S = *reinterpret_cast<MsgSmem2*>(smem_raw);
    int bl0 = blockIdx.x * NODES;
    int b   = bl0 / LL;
    int t   = threadIdx.x;
    int w = t>>5, lane = t&31;
    int half = w & 1, hw = w >> 1;
    int ht = hw*32 + lane;

    load_node_params(S, bl0, half, ht, g_hV, Eidx, (const float*)0);
    bar_half(half);
    build_mi2(S, bl0, b, half, hw, lane, ht, g_hV, hE);
    bar_half(half);
    run_msg_gemms(S, g_W11pb, g_W12pb, b2, g_W13pb, b3, half, hw, lane);

    const float* msgF = reinterpret_cast<const float*>(S.A0 + (size_t)half*HALFREG);
    #pragma unroll
    for (int i=0;i<8;i++){
        int grl = hw*8+i;
        size_t e = (size_t)(bl0+half)*KK + grl;
        float4 hv_ = reinterpret_cast<const float4*>(hE + e*HH)[lane];
        float4 mv  = reinterpret_cast<const float4*>(msgF + (size_t)grl*LDF)[lane];
        float x0 = mv.x+hv_.x, x1 = mv.y+hv_.y, x2 = mv.z+hv_.z, x3 = mv.w+hv_.w;
        float s = x0+x1+x2+x3;
        float q = x0*x0+x1*x1+x2*x2+x3*x3;
        #pragma unroll
        for (int o=16;o>0;o>>=1){
            s += __shfl_xor_sync(0xffffffffu, s, o);
            q += __shfl_xor_sync(0xffffffffu, q, o);
        }
        float mu = s*(1.0f/HH);
        float rstd = rsqrtf(q*(1.0f/HH)-mu*mu+1e-5f);
        int f0 = lane*4;
        float4 gg = *reinterpret_cast<const float4*>(g3 + f0);
        float4 bb = *reinterpret_cast<const float4*>(be3 + f0);
        float4 o4;
        o4.x = (x0-mu)*rstd*gg.x + bb.x;
        o4.y = (x1-mu)*rstd*gg.y + bb.y;
        o4.z = (x2-mu)*rstd*gg.z + bb.z;
        o4.w = (x3-mu)*rstd*gg.w + bb.w;
        *reinterpret_cast<float4*>(out_hE + e*HH + f0) = o4;
    }
}

// ============================================================
// tf32 FFN
// ============================================================
__global__ void k_ffn1(const float* __restrict__ bdin)
{
    __shared__ float sA[HH*LDT];
    int rb = blockIdx.x, cb = blockIdx.y;
    int t = threadIdx.x;
    int lane=t&31, warp=t>>5;

    int m = t>>2; int k0 = (t&3)*32;
    const float* src = g_xn + ((size_t)(rb*32+m))*HH + k0;
    #pragma unroll
    for (int i=0;i<8;i++){
        float4 v = *reinterpret_cast<const float4*>(src + i*4);
        sA[(k0+i*4+0)*LDT+m]=tf32r(v.x);
        sA[(k0+i*4+1)*LDT+m]=tf32r(v.y);
        sA[(k0+i*4+2)*LDT+m]=tf32r(v.z);
        sA[(k0+i*4+3)*LDT+m]=tf32r(v.w);
    }
    __syncthreads();

    float c[2][4][4];
    mma_core<16>(g_Wdinp, 64, cb*16 + warp*4, sA, c, lane);

    int qid=lane>>2, tig=lane&3;
    #pragma unroll
    for (int j=0;j<4;j++){
        int n = (cb*16+warp*4+j)*8 + tig*2;
        float b0=bdin[n], b1=bdin[n+1];
        #pragma unroll
        for (int mt=0;mt<2;mt++){
            int r = rb*32 + mt*16 + qid;
            g_ff[(size_t)r*512 + n]       = gelu_f(c[mt][j][0]+b0);
            g_ff[(size_t)r*512 + n+1]     = gelu_f(c[mt][j][1]+b1);
            g_ff[(size_t)(r+8)*512 + n]   = gelu_f(c[mt][j][2]+b0);
            g_ff[(size_t)(r+8)*512 + n+1] = gelu_f(c[mt][j][3]+b1);
        }
    }
}

struct FfnSmem {
    float sA[4*HH*LDT];
    float mu[32], rstd[32];
};

__global__ void k_ffn2(const float* __restrict__ bdout,
                       const float* __restrict__ g2, const float* __restrict__ be2,
                       const float* __restrict__ maskV,
                       float* __restrict__ out_hV)
{
    extern __shared__ char smem_raw[];
    FfnSmem& S = *reinterpret_cast<FfnSmem*>(smem_raw);
    int rb = blockIdx.x;
    int t = threadIdx.x;
    int lane=t&31, warp=t>>5;

    int m = t>>2; int k0 = (t&3)*128;
    const float* src = g_ff + ((size_t)(rb*32+m))*512 + k0;
    #pragma unroll
    for (int i=0;i<32;i++){
        float4 v = *reinterpret_cast<const float4*>(src + i*4);
        S.sA[(k0+i*4+0)*LDT+m]=tf32r(v.x);
        S.sA[(k0+i*4+1)*LDT+m]=tf32r(v.y);
        S.sA[(k0+i*4+2)*LDT+m]=tf32r(v.z);
        S.sA[(k0+i*4+3)*LDT+m]=tf32r(v.w);
    }
    __syncthreads();

    float c[2][4][4];
    mma_core<64>(g_Wdoutp, 16, warp*4, S.sA, c, lane);
    __syncthreads();

    int qid=lane>>2, tig=lane&3;
    #pragma unroll
    for (int j=0;j<4;j++){
        int n = (warp*4+j)*8 + tig*2;
        float b0=bdout[n], b1=bdout[n+1];
        #pragma unroll
        for (int mt=0;mt<2;mt++){
            int r = mt*16 + qid;
            size_t node0 = (size_t)(rb*32 + r);
            size_t node1 = node0 + 8;
            S.sA[n*LDT + r]       = c[mt][j][0]+b0 + g_xn[node0*HH + n];
            S.sA[(n+1)*LDT + r]   = c[mt][j][1]+b1 + g_xn[node0*HH + n+1];
            S.sA[n*LDT + r+8]     = c[mt][j][2]+b0 + g_xn[node1*HH + n];
            S.sA[(n+1)*LDT + r+8] = c[mt][j][3]+b1 + g_xn[node1*HH + n+1];
        }
    }
    __syncthreads();

    if (t < 32){
        float s=0.f, q=0.f;
        #pragma unroll 4
        for (int cf=0;cf<HH;cf++){ float v=S.sA[cf*LDT+t]; s+=v; q+=v*v; }
        float mu = s*(1.f/HH);
        S.mu[t]=mu;
        S.rstd[t]=rsqrtf(q*(1.f/HH)-mu*mu+1e-5f);
    }
    __syncthreads();

    float gg=g2[t], bb=be2[t];
    for (int r=0;r<32;r++){
        size_t node = (size_t)(rb*32+r);
        float y = (S.sA[t*LDT+r]-S.mu[r])*S.rstd[r]*gg+bb;
        y *= maskV[node];
        g_hV[node*HH+t]=y;
        out_hV[node*HH+t]=y;
    }
}

// ============================================================
extern "C" void kernel_launch(void* const* d_in, const int* in_sizes, int n_in,
                              void* d_out, int out_size)
{
    const float* hV    =(const float*)d_in[0];
    const float* hE    =(const float*)d_in[1];
    const int*   Eidx  =(const int*)  d_in[2];
    const float* X     =(const float*)d_in[3];
    const float* maskV =(const float*)d_in[4];
    const float* maskA =(const float*)d_in[5];
    const float* Wp_node=(const float*)d_in[6];  const float* bp_node=(const float*)d_in[7];
    const float* Wp_edge=(const float*)d_in[8];  const float* bp_edge=(const float*)d_in[9];
    const float* W1 =(const float*)d_in[10]; const float* b1 =(const float*)d_in[11];
    const float* W2 =(const float*)d_in[12]; const float* b2 =(const float*)d_in[13];
    const float* W3 =(const float*)d_in[14]; const float* b3 =(const float*)d_in[15];
    const float* W11=(const float*)d_in[16]; const float* b11=(const float*)d_in[17];
    const float* W12=(const float*)d_in[18]; const float* b12=(const float*)d_in[19];
    const float* W13=(const float*)d_in[20]; const float* b13=(const float*)d_in[21];
    const float* Wdin =(const float*)d_in[22]; const float* bdin =(const float*)d_in[23];
    const float* Wdout=(const float*)d_in[24]; const float* bdout=(const float*)d_in[25];
    const float* g1=(const float*)d_in[26]; const float* be1=(const float*)d_in[27];
    const float* g2=(const float*)d_in[28]; const float* be2=(const float*)d_in[29];
    const float* g3=(const float*)d_in[30]; const float* be3=(const float*)d_in[31];

    float* out_hV = (float*)d_out;
    float* out_hE = out_hV + (size_t)NB*HH;

    int smem_msg = (int)sizeof(MsgSmem2);
    int smem_ffn = (int)sizeof(FfnSmem);
    cudaFuncSetAttribute(k_node, cudaFuncAttributeMaxDynamicSharedMemorySize, smem_msg);
    cudaFuncSetAttribute(k_edge, cudaFuncAttributeMaxDynamicSharedMemorySize, smem_msg);
    cudaFuncSetAttribute(k_ffn2, cudaFuncAttributeMaxDynamicSharedMemorySize, smem_ffn);

    uint32_t *p1,*p2,*p3,*p11,*p12,*p13;
    float *pdin,*pdout,*phv,*pw1h,*pw11h,*pu;
    cudaGetSymbolAddress((void**)&p1,   g_W1pb);
    cudaGetSymbolAddress((void**)&p2,   g_W2pb);
    cudaGetSymbolAddress((void**)&p3,   g_W3pb);
    cudaGetSymbolAddress((void**)&p11,  g_W11pb);
    cudaGetSymbolAddress((void**)&p12,  g_W12pb);
    cudaGetSymbolAddress((void**)&p13,  g_W13pb);
    cudaGetSymbolAddress((void**)&pdin, g_Wdinp);
    cudaGetSymbolAddress((void**)&pdout,g_Wdoutp);
    cudaGetSymbolAddress((void**)&phv,  g_hV);
    cudaGetSymbolAddress((void**)&pw1h, g_W1hp);
    cudaGetSymbolAddress((void**)&pw11h,g_W11hp);
    cudaGetSymbolAddress((void**)&pu,   g_u);

    k_packb<<<dim3(29,16,6),32>>>(W1,W2,W3,W11,W12,W13,p1,p2,p3,p11,p12,p13);
    dim3 pb(32,16);
    k_pack<<<dim3(16,4),pb>>>(Wdin,  pdin, 512);
    k_pack<<<dim3(64,1),pb>>>(Wdout, pdout,128);
    k_pack<<<dim3(16,1),pb>>>(W1,  pw1h, 128);
    k_pack<<<dim3(16,1),pb>>>(W11, pw11h,128);

    k_frames<<<NB/128,128>>>(X);
    k_projpg<<<NB/8,dim3(24,8)>>>(hV, Wp_node, bp_node);
    k_head<<<NB/32,128>>>(hV, pw1h, b1, pu);
    k_node<<<NB/NODES,256,smem_msg>>>(hV,hE,Eidx,maskA,b2,b3,g1,be1);
    k_ffn1<<<dim3(128,4),128>>>(bdin);
    k_ffn2<<<128,128,smem_ffn>>>(bdout,g2,be2,maskV,out_hV);
    k_projpg<<<NB/8,dim3(24,8)>>>(phv, Wp_edge, bp_edge);
    k_head<<<NB/32,128>>>(phv, pw11h, b11, pu);
    k_edge<<<NB/NODES,256,smem_msg>>>(hE,Eidx,b12,b13,g3,be3,out_hE);
}